// round 9
// baseline (speedup 1.0000x reference)
#include <cuda_runtime.h>
#include <cuda_bf16.h>
#include <stdint.h>
#include <math.h>

// ---------------------------------------------------------------------------
// 2-bit quantized CNN forward.
//  conv1: fp32 conv via packed fma.rn.f32x2
//  conv2/conv3: channel-split across TWO concurrent kernels (two streams):
//    conv_mma: mma.sync.m16n8k32.s8 (tensor pipe), oc [0,40) of each 64-group
//    conv_dp:  dp4a (fma/alu pipe),               oc [40,64) of each group
//  Exact integer math: conv = (sum code*wint) * (alpha_prev/3 * s_w).
// ---------------------------------------------------------------------------

__device__ unsigned g_smax[4];                 // maxabs bits: w1, wc, w2, w3
__device__ float    g_qw1[32 * 3 * 9];
__device__ float    g_qwc[10 * 128];
__device__ int      g_wf2[9 * 64 * 8];         // mma B-frags [tap][oc][p]
__device__ int      g_wf3[9 * 2 * 128 * 8];    // [tap][chunk][oc][p]
__device__ uint4    g_dw2[8 * 9 * 6];          // dp4a w [k][tap][oc4] (oc40..63)
__device__ uint4    g_dw3[2 * 16 * 9 * 6];     // [z][k][tap][oc4]
__device__ uint8_t  g_c1[32L * 112 * 112 * 32];
__device__ uint8_t  g_c2[32L * 56 * 56 * 64];
__device__ uint8_t  g_c3[32L * 28 * 28 * 128];

// ---- helpers ---------------------------------------------------------------
__device__ __forceinline__ uint32_t smem_u32(const void* p) {
    uint32_t a;
    asm("{ .reg .u64 t; cvta.to.shared.u64 t, %1; cvt.u32.u64 %0, t; }"
        : "=r"(a) : "l"(p));
    return a;
}
__device__ __forceinline__ void ldsm4(uint32_t addr, int& a0, int& a1,
                                      int& a2, int& a3) {
    asm volatile("ldmatrix.sync.aligned.m8n8.x4.shared.b16 {%0,%1,%2,%3},[%4];"
                 : "=r"(a0), "=r"(a1), "=r"(a2), "=r"(a3) : "r"(addr));
}
__device__ __forceinline__ void mma_s8(int* d, int a0, int a1, int a2, int a3,
                                       int b0, int b1) {
    asm("mma.sync.aligned.m16n8k32.row.col.s32.s8.s8.s32 "
        "{%0,%1,%2,%3},{%4,%5,%6,%7},{%8,%9},{%0,%1,%2,%3};"
        : "+r"(d[0]), "+r"(d[1]), "+r"(d[2]), "+r"(d[3])
        : "r"(a0), "r"(a1), "r"(a2), "r"(a3), "r"(b0), "r"(b1));
}
#define PACK_F32X2(out, lo, hi) \
    asm("mov.b64 %0, {%1, %2};" : "=l"(out) : "r"(lo), "r"(hi))
#define UNPACK_F32X2(lo, hi, in) \
    asm("mov.b64 {%0, %1}, %2;" : "=f"(lo), "=f"(hi) : "l"(in))
#define FMA_F32X2(acc, a, b) \
    asm("fma.rn.f32x2 %0, %1, %2, %0;" : "+l"(acc) : "l"(a), "l"(b))

__device__ __forceinline__ float get_scale(int t) {
    return fmaxf(__uint_as_float(g_smax[t]), 1e-8f);
}

// ---- prologue 1: max|w| -----------------------------------------------------
__global__ void maxabs_kernel(const float* __restrict__ w1,
                              const float* __restrict__ wc,
                              const float* __restrict__ w2,
                              const float* __restrict__ w3) {
    __shared__ float red[8];
    const int blk = blockIdx.x;
    int t, base, cnt;
    const float* p;
    if (blk == 0)      { t = 0; p = w1; base = 0; cnt = 864; }
    else if (blk == 1) { t = 1; p = wc; base = 0; cnt = 1280; }
    else if (blk < 6)  { t = 2; p = w2; base = (blk - 2) * 4608; cnt = 4608; }
    else               { t = 3; p = w3; base = (blk - 6) * 4608; cnt = 4608; }
    float m = 0.f;
    for (int i = threadIdx.x; i < cnt; i += 256)
        m = fmaxf(m, fabsf(p[base + i]));
    #pragma unroll
    for (int o = 16; o; o >>= 1)
        m = fmaxf(m, __shfl_xor_sync(0xffffffffu, m, o));
    if ((threadIdx.x & 31) == 0) red[threadIdx.x >> 5] = m;
    __syncthreads();
    if (threadIdx.x == 0) {
        float v = red[0];
        #pragma unroll
        for (int i = 1; i < 8; i++) v = fmaxf(v, red[i]);
        atomicMax(&g_smax[t], __float_as_uint(v));  // |w|>=0, bit-monotone
    }
}

// ---- prologue 2: quantize + pack --------------------------------------------
__global__ void pack_kernel(const float* __restrict__ w1,
                            const float* __restrict__ wc,
                            const float* __restrict__ w2,
                            const float* __restrict__ w3) {
    const int blk = blockIdx.x;
    if (blk == 0) {
        const float s = get_scale(0);
        for (int i = threadIdx.x; i < 864; i += 256)
            g_qw1[i] = rintf(w1[i] / s) * s;
    } else if (blk == 1) {
        const float s = get_scale(1);
        for (int i = threadIdx.x; i < 1280; i += 256)
            g_qwc[i] = rintf(wc[i] / s) * s;
    } else if (blk == 2) {
        // mma frags conv2: word p: icw = (p>>1) + (p&1)*4
        const float inv_s = 1.f / get_scale(2);
        for (int i = threadIdx.x; i < 9 * 64 * 8; i += 256) {
            const int tap = i / 512, r = i % 512, oc = r >> 3, p = r & 7;
            const int icw = (p >> 1) + ((p & 1) << 2);
            uint32_t word = 0;
            #pragma unroll
            for (int l = 0; l < 4; l++) {
                const int ic = icw * 4 + l;
                const int c = (int)rintf(w2[(oc * 32 + ic) * 9 + tap] * inv_s);
                word |= ((uint32_t)(uint8_t)(int8_t)c) << (8 * l);
            }
            g_wf2[i] = (int)word;
        }
    } else if (blk == 3) {
        const float inv_s = 1.f / get_scale(3);
        for (int i = threadIdx.x; i < 9 * 2 * 128 * 8; i += 256) {
            const int tap = i / 2048, r = i % 2048;
            const int chunk = r >> 10, r2 = r & 1023, oc = r2 >> 3, p = r2 & 7;
            const int icw = (p >> 1) + ((p & 1) << 2);
            uint32_t word = 0;
            #pragma unroll
            for (int l = 0; l < 4; l++) {
                const int ic = chunk * 32 + (icw * 4) + l;
                const int c = (int)rintf(w3[(oc * 64 + ic) * 9 + tap] * inv_s);
                word |= ((uint32_t)(uint8_t)(int8_t)c) << (8 * l);
            }
            g_wf3[i] = (int)word;
        }
    } else if (blk == 4) {
        // dp4a conv2 weights: oc 40..63, [k][tap][d] u32 words
        const float inv_s = 1.f / get_scale(2);
        uint32_t* dst = (uint32_t*)g_dw2;
        for (int i = threadIdx.x; i < 8 * 9 * 24; i += 256) {
            const int k = i / 216, t = (i % 216) / 24, d = i % 24;
            const int oc = 40 + d;
            uint32_t word = 0;
            #pragma unroll
            for (int l = 0; l < 4; l++) {
                const int ic = k * 4 + l;
                const int c = (int)rintf(w2[(oc * 32 + ic) * 9 + t] * inv_s);
                word |= ((uint32_t)(uint8_t)(int8_t)c) << (8 * l);
            }
            dst[i] = word;
        }
    } else {
        // dp4a conv3 weights: z in {0,1}, oc z*64+40..+63
        const float inv_s = 1.f / get_scale(3);
        uint32_t* dst = (uint32_t*)g_dw3;
        for (int i = threadIdx.x; i < 2 * 16 * 9 * 24; i += 256) {
            const int z = i / 3456, r = i % 3456;
            const int k = r / 216, t = (r % 216) / 24, d = r % 24;
            const int oc = z * 64 + 40 + d;
            uint32_t word = 0;
            #pragma unroll
            for (int l = 0; l < 4; l++) {
                const int ic = k * 4 + l;
                const int c = (int)rintf(w3[(oc * 64 + ic) * 9 + t] * inv_s);
                word |= ((uint32_t)(uint8_t)(int8_t)c) << (8 * l);
            }
            dst[i] = word;
        }
    }
}

// ---- block 1: fp32 conv3x3(pad1) via fma.f32x2 + quant_act + maxpool2 -------
__global__ __launch_bounds__(128) void conv1_kernel(
    const float* __restrict__ x, const float* __restrict__ alpha_p,
    uint8_t* __restrict__ out) {
    constexpr int H = 224, W = 224, PH = 112, PW = 112, OC = 32, OCB = 8;
    __shared__ float sx[3][18][34];
    __shared__ unsigned long long swp[OCB][3][9];   // (w,w) duplicated pairs

    const int tid = threadIdx.x;
    const int tx = tid & 15, ty = tid >> 4;
    const int tile_x = blockIdx.x;
    const int tile_y = blockIdx.y % 14;
    const int b      = blockIdx.y / 14;
    const int oc0    = blockIdx.z * OCB;

    const int px0 = tile_x * 16, py0 = tile_y * 8;
    const int ix0 = 2 * px0 - 1, iy0 = 2 * py0 - 1;

    const float* xb = x + (long)b * 3 * H * W;
    for (int i = tid; i < 3 * 18 * 34; i += 128) {
        const int ic = i / 612, rr = (i % 612) / 34, cc = i % 34;
        const int gy = iy0 + rr, gx = ix0 + cc;
        float v = 0.f;
        if (gy >= 0 && gy < H && gx >= 0 && gx < W)
            v = xb[(long)ic * H * W + gy * W + gx];
        sx[ic][rr][cc] = v;
    }
    if (tid < OCB * 27) {
        const int j = tid / 27, r27 = tid % 27;
        const float w = g_qw1[((oc0 + j) * 3 + r27 / 9) * 9 + r27 % 9];
        unsigned long long pw;
        PACK_F32X2(pw, __float_as_uint(w), __float_as_uint(w));
        swp[j][r27 / 9][r27 % 9] = pw;
    }
    __syncthreads();

    unsigned long long accA[OCB], accB[OCB];
    #pragma unroll
    for (int j = 0; j < OCB; j++) { accA[j] = 0ull; accB[j] = 0ull; }

    #pragma unroll
    for (int ic = 0; ic < 3; ic++) {
        float win[4][4];
        #pragma unroll
        for (int r = 0; r < 4; r++)
            #pragma unroll
            for (int c = 0; c < 4; c++)
                win[r][c] = sx[ic][2 * ty + r][2 * tx + c];
        unsigned long long pk[4][3];
        #pragma unroll
        for (int r = 0; r < 4; r++)
            #pragma unroll
            for (int c = 0; c < 3; c++)
                PACK_F32X2(pk[r][c], __float_as_uint(win[r][c]),
                           __float_as_uint(win[r][c + 1]));
        #pragma unroll
        for (int j = 0; j < OCB; j++) {
            #pragma unroll
            for (int ky = 0; ky < 3; ky++)
                #pragma unroll
                for (int kx = 0; kx < 3; kx++) {
                    FMA_F32X2(accA[j], pk[ky][kx], swp[j][ic][ky * 3 + kx]);
                    FMA_F32X2(accB[j], pk[ky + 1][kx], swp[j][ic][ky * 3 + kx]);
                }
        }
    }

    const float alpha = __ldg(alpha_p);
    const float inv_scale = 3.f / alpha;
    const int px = px0 + tx, py = py0 + ty;
    uint32_t lo = 0, hi = 0;
    #pragma unroll
    for (int j = 0; j < OCB; j++) {
        float p0, p1, p2, p3;
        UNPACK_F32X2(p0, p1, accA[j]);
        UNPACK_F32X2(p2, p3, accB[j]);
        const float m = fmaxf(fmaxf(p0, p1), fmaxf(p2, p3));
        const float y = fminf(fmaxf(m, 0.f), alpha);
        const uint32_t code = (uint32_t)(int)rintf(y * inv_scale);
        if (j < 4) lo |= code << (8 * j);
        else       hi |= code << (8 * (j - 4));
    }
    *(uint2*)&out[(((long)b * PH + py) * PW + px) * OC + oc0] = make_uint2(lo, hi);
}

// ---- conv2/3 part A: pure-mma conv + quant_act + maxpool2 -------------------
// Writes oc [z*64, z*64+NOC).  Proven R3/R5 kernel.
template <int H, int IC, int OC, int NOC, int TW, int TH, int WARPS, int PSTRIDE>
__global__ void conv_mma(const uint8_t* __restrict__ xin,
                         const int* __restrict__ wf,
                         const float* __restrict__ aprev_p,
                         const float* __restrict__ acur_p,
                         int wtensor,
                         uint8_t* __restrict__ out) {
    constexpr int CH  = IC / 32;
    constexpr int TIW = TW + 2, TIH = TH + 2;
    constexpr int OCG = NOC / 8;
    constexpr int VPP = IC / 16;
    constexpr int WTX = TW / 8, WTY = TH / 2, NWT = WTX * WTY;
    constexpr int PHW = H / 2;

    extern __shared__ __align__(16) uint8_t dsm[];
    uint8_t* stile = dsm;
    int* swf = (int*)(dsm + TIH * TIW * PSTRIDE);

    const int tid = threadIdx.x;
    const int tilesY = H / TH;
    const int by = blockIdx.y % tilesY;
    const int b  = blockIdx.y / tilesY;
    const int cx0 = blockIdx.x * TW, cy0 = by * TH;
    const int oc0 = blockIdx.z * 64;

    for (int i = tid; i < 9 * CH * NOC * 8; i += blockDim.x) {
        const int p = i & 7, j = (i >> 3) % NOC, tc = (i >> 3) / NOC;
        swf[i] = wf[((tc * OC) + oc0 + j) * 8 + p];
    }
    for (int i = tid; i < TIH * TIW * VPP; i += blockDim.x) {
        const int v = i % VPP, pix = i / VPP;
        const int gx = cx0 - 1 + pix % TIW;
        const int gy = cy0 - 1 + pix / TIW;
        uint4 val = make_uint4(0, 0, 0, 0);
        if (gx >= 0 && gx < H && gy >= 0 && gy < H)
            val = *(const uint4*)(xin + (((long)b * H + gy) * H + gx) * IC + v * 16);
        *(uint4*)(stile + pix * PSTRIDE + v * 16) = val;
    }
    __syncthreads();

    const int warp = tid >> 5, lane = tid & 31;
    const uint32_t sbase = smem_u32(stile);
    const float combined = (__ldg(aprev_p) * (1.f / 3.f)) * get_scale(wtensor);
    const float alpha = __ldg(acur_p);
    const float inv_scale = 3.f / alpha;
    const int r = lane >> 2;

    for (int wt = warp; wt < NWT; wt += WARPS) {
        const int tx = wt % WTX, ty = wt / WTX;
        const int piy = ty * 2 + ((lane >> 3) & 1);
        const int pix = tx * 8 + (lane & 7);
        const uint32_t abase = sbase + (piy * TIW + pix) * PSTRIDE
                             + ((lane >> 4) << 4);
        int acc[OCG][4];
        #pragma unroll
        for (int g = 0; g < OCG; g++)
            #pragma unroll
            for (int q = 0; q < 4; q++) acc[g][q] = 0;

        #pragma unroll
        for (int t = 0; t < 9; t++) {
            const int dy = t / 3, dx = t % 3;
            #pragma unroll
            for (int c = 0; c < CH; c++) {
                int a0, a1, a2, a3;
                ldsm4(abase + (dy * TIW + dx) * PSTRIDE + c * 32, a0, a1, a2, a3);
                #pragma unroll
                for (int g = 0; g < OCG; g++) {
                    const uint2 bb = *(const uint2*)
                        &swf[(((t * CH + c) * NOC) + g * 8 + (lane >> 2)) * 8
                             + 2 * (lane & 3)];
                    mma_s8(acc[g], a0, a1, a2, a3, (int)bb.x, (int)bb.y);
                }
            }
        }
        #pragma unroll
        for (int g = 0; g < OCG; g++) {
            const int v0 = max(acc[g][0], acc[g][2]);
            const int v1 = max(acc[g][1], acc[g][3]);
            const int o0 = max(v0, __shfl_xor_sync(0xffffffffu, v0, 4));
            const int o1 = max(v1, __shfl_xor_sync(0xffffffffu, v1, 4));
            if (!(r & 1)) {
                const int ppx = (cx0 >> 1) + tx * 4 + (r >> 1);
                const int ppy = (cy0 >> 1) + ty;
                const float f0 = fminf(fmaxf((float)o0 * combined, 0.f), alpha);
                const float f1 = fminf(fmaxf((float)o1 * combined, 0.f), alpha);
                const uint32_t c0 = (uint32_t)(int)rintf(f0 * inv_scale);
                const uint32_t c1 = (uint32_t)(int)rintf(f1 * inv_scale);
                const int oc = oc0 + g * 8 + (lane & 3) * 2;
                *(uint16_t*)(out + (((long)b * PHW + ppy) * PHW + ppx) * OC + oc)
                    = (uint16_t)(c0 | (c1 << 8));
            }
        }
    }
}

// ---- conv2/3 part B: pure-dp4a conv + quant_act + maxpool2 ------------------
// 128 threads, lane = (conv col, pooled row).  Writes oc [z*64+40, z*64+64).
template <int H, int IC, int OC, int TW, int TH, int PSTRIDE>
__global__ __launch_bounds__(128) void conv_dp(
    const uint8_t* __restrict__ xin, const uint4* __restrict__ dw,
    const float* __restrict__ aprev_p, const float* __restrict__ acur_p,
    int wtensor, uint8_t* __restrict__ out) {
    constexpr int DPOC = 24, DQ = 6;
    constexpr int IC4  = IC / 4;
    constexpr int IC16 = IC / 16;
    constexpr int TIW  = TW + 2, TIH = TH + 2;
    constexpr int VPP  = IC / 16;
    constexpr int PHW  = H / 2;
    constexpr int DLANES = TW * (TH / 2);
    static_assert(DLANES <= 128, "lane budget");

    extern __shared__ __align__(16) uint8_t dsm[];
    uint8_t* stile = dsm;                                   // TIH*TIW*PSTRIDE
    uint4*   sdw   = (uint4*)(dsm + TIH * TIW * PSTRIDE);   // IC4*9*DQ uint4

    const int tid = threadIdx.x;
    const int tilesY = H / TH;
    const int by = blockIdx.y % tilesY;
    const int b  = blockIdx.y / tilesY;
    const int cx0 = blockIdx.x * TW, cy0 = by * TH;
    const int oc0 = blockIdx.z * 64 + 40;

    {
        const uint4* dwz = dw + (long)blockIdx.z * (IC4 * 9 * DQ);
        for (int i = tid; i < IC4 * 9 * DQ; i += 128) sdw[i] = dwz[i];
    }
    for (int i = tid; i < TIH * TIW * VPP; i += 128) {
        const int v = i % VPP, pix = i / VPP;
        const int gx = cx0 - 1 + pix % TIW;
        const int gy = cy0 - 1 + pix / TIW;
        uint4 val = make_uint4(0, 0, 0, 0);
        if (gx >= 0 && gx < H && gy >= 0 && gy < H)
            val = *(const uint4*)(xin + (((long)b * H + gy) * H + gx) * IC + v * 16);
        *(uint4*)(stile + pix * PSTRIDE + v * 16) = val;
    }
    __syncthreads();

    const int cx = tid % TW, cyp = tid / TW;
    const bool active = tid < DLANES;
    const int dcyp = min(cyp, TH / 2 - 1);

    const float combined = (__ldg(aprev_p) * (1.f / 3.f)) * get_scale(wtensor);
    const float alpha = __ldg(acur_p);
    const float inv_scale = 3.f / alpha;

    int acc[DPOC][2];
    #pragma unroll
    for (int j = 0; j < DPOC; j++) { acc[j][0] = 0; acc[j][1] = 0; }

    #pragma unroll 1
    for (int g4 = 0; g4 < IC16; g4++) {
        const uint8_t* tb = stile + ((2 * dcyp) * TIW + cx) * PSTRIDE + g4 * 16;
        #pragma unroll
        for (int cc = 0; cc < 3; cc++) {
            uint4 col[4];
            #pragma unroll
            for (int rr = 0; rr < 4; rr++)
                col[rr] = *(const uint4*)(tb + (rr * TIW + cc) * PSTRIDE);
            #pragma unroll
            for (int dy = 0; dy < 3; dy++) {
                const int t = dy * 3 + cc;
                #pragma unroll
                for (int kk = 0; kk < 4; kk++) {
                    const uint32_t a0 = ((const uint32_t*)&col[dy])[kk];
                    const uint32_t a1 = ((const uint32_t*)&col[dy + 1])[kk];
                    const int k = g4 * 4 + kk;
                    #pragma unroll
                    for (int q = 0; q < DQ; q++) {
                        const uint4 w = sdw[(k * 9 + t) * DQ + q];
                        acc[q*4+0][0] = __dp4a((int)a0, (int)w.x, acc[q*4+0][0]);
                        acc[q*4+0][1] = __dp4a((int)a1, (int)w.x, acc[q*4+0][1]);
                        acc[q*4+1][0] = __dp4a((int)a0, (int)w.y, acc[q*4+1][0]);
                        acc[q*4+1][1] = __dp4a((int)a1, (int)w.y, acc[q*4+1][1]);
                        acc[q*4+2][0] = __dp4a((int)a0, (int)w.z, acc[q*4+2][0]);
                        acc[q*4+2][1] = __dp4a((int)a1, (int)w.z, acc[q*4+2][1]);
                        acc[q*4+3][0] = __dp4a((int)a0, (int)w.w, acc[q*4+3][0]);
                        acc[q*4+3][1] = __dp4a((int)a1, (int)w.w, acc[q*4+3][1]);
                    }
                }
            }
        }
    }

    uint32_t pw[DQ];
    #pragma unroll
    for (int q = 0; q < DQ; q++) pw[q] = 0;
    #pragma unroll
    for (int j = 0; j < DPOC; j++) {
        int v = max(acc[j][0], acc[j][1]);               // vertical pool
        v = max(v, __shfl_xor_sync(0xffffffffu, v, 1));  // horizontal pool
        const float f = fminf(fmaxf((float)v * combined, 0.f), alpha);
        const uint32_t code = (uint32_t)(int)rintf(f * inv_scale);
        pw[j >> 2] |= code << (8 * (j & 3));
    }
    if (active && !(cx & 1)) {
        const int ppx = (cx0 >> 1) + (cx >> 1);
        const int ppy = (cy0 >> 1) + cyp;
        uint8_t* o = out + (((long)b * PHW + ppy) * PHW + ppx) * OC + oc0;
        ((uint2*)o)[0] = make_uint2(pw[0], pw[1]);
        ((uint2*)o)[1] = make_uint2(pw[2], pw[3]);
        ((uint2*)o)[2] = make_uint2(pw[4], pw[5]);
    }
}

// ---- global max over 28x28 + 1x1 quantized conv classifier ------------------
__global__ void gmax_fc_kernel(const uint8_t* __restrict__ h3,
                               const float* __restrict__ a3_p,
                               float* __restrict__ out) {
    __shared__ uint32_t sm[4][32];
    __shared__ float gm[128];
    const int b = blockIdx.x;
    const int tid = threadIdx.x;
    const int w = tid >> 5, c4 = tid & 31;
    const uint32_t* p = (const uint32_t*)(h3 + (long)b * 784 * 128);
    uint32_t m = 0;
    for (int pix = w; pix < 784; pix += 4)
        m = __vmaxu4(m, p[(long)pix * 32 + c4]);
    sm[w][c4] = m;
    __syncthreads();
    if (tid < 32) {
        const uint32_t v = __vmaxu4(__vmaxu4(sm[0][tid], sm[1][tid]),
                                    __vmaxu4(sm[2][tid], sm[3][tid]));
        const float sc = __ldg(a3_p) * (1.f / 3.f);
        gm[tid * 4 + 0] = (float)(v & 0xff) * sc;
        gm[tid * 4 + 1] = (float)((v >> 8) & 0xff) * sc;
        gm[tid * 4 + 2] = (float)((v >> 16) & 0xff) * sc;
        gm[tid * 4 + 3] = (float)(v >> 24) * sc;
    }
    __syncthreads();
    if (tid < 10) {
        float s = 0.f;
        #pragma unroll 8
        for (int k = 0; k < 128; k++)
            s = fmaf(gm[k], g_qwc[tid * 128 + k], s);
        out[b * 10 + tid] = s;
    }
}

// ---------------------------------------------------------------------------
extern "C" void kernel_launch(void* const* d_in, const int* in_sizes, int n_in,
                              void* d_out, int out_size) {
    const float* x  = (const float*)d_in[0];
    const float* w1 = (const float*)d_in[1];
    const float* w2 = (const float*)d_in[2];
    const float* w3 = (const float*)d_in[3];
    const float* wc = (const float*)d_in[4];
    const float* a1 = (const float*)d_in[5];
    const float* a2 = (const float*)d_in[6];
    const float* a3 = (const float*)d_in[7];

    int *wf2, *wf3;
    uint4 *dw2, *dw3;
    uint8_t *c1, *c2, *c3;
    cudaGetSymbolAddress((void**)&wf2, g_wf2);
    cudaGetSymbolAddress((void**)&wf3, g_wf3);
    cudaGetSymbolAddress((void**)&dw2, g_dw2);
    cudaGetSymbolAddress((void**)&dw3, g_dw3);
    cudaGetSymbolAddress((void**)&c1, g_c1);
    cudaGetSymbolAddress((void**)&c2, g_c2);
    cudaGetSymbolAddress((void**)&c3, g_c3);

    // mma kernels: 40 of each 64-channel group
    auto km2 = conv_mma<112, 32, 64, 40, 16, 16, 8, 48>;
    constexpr int SMM2 = 18 * 18 * 48 + 9 * 1 * 40 * 8 * 4;   // 27072
    auto km3 = conv_mma<56, 64, 128, 40, 56, 8, 7, 80>;
    constexpr int SMM3 = 58 * 10 * 80 + 9 * 2 * 40 * 8 * 4;   // 69440
    // dp kernels: channels 40..63 of each group
    auto kd2 = conv_dp<112, 32, 64, 16, 16, 48>;
    constexpr int SMD2 = 18 * 18 * 48 + 8 * 9 * 6 * 16;       // 22464
    auto kd3 = conv_dp<56, 64, 128, 28, 8, 80>;
    constexpr int SMD3 = 30 * 10 * 80 + 16 * 9 * 6 * 16;      // 37824
    cudaFuncSetAttribute(km2, cudaFuncAttributeMaxDynamicSharedMemorySize, SMM2);
    cudaFuncSetAttribute(km3, cudaFuncAttributeMaxDynamicSharedMemorySize, SMM3);
    cudaFuncSetAttribute(kd2, cudaFuncAttributeMaxDynamicSharedMemorySize, SMD2);
    cudaFuncSetAttribute(kd3, cudaFuncAttributeMaxDynamicSharedMemorySize, SMD3);

    // side stream + fork/join events (created on first, uncaptured call)
    static cudaStream_t s1 = nullptr;
    static cudaEvent_t evA = nullptr, evB = nullptr, evC = nullptr, evD = nullptr;
    if (s1 == nullptr) {
        cudaStreamCreateWithFlags(&s1, cudaStreamNonBlocking);
        cudaEventCreateWithFlags(&evA, cudaEventDisableTiming);
        cudaEventCreateWithFlags(&evB, cudaEventDisableTiming);
        cudaEventCreateWithFlags(&evC, cudaEventDisableTiming);
        cudaEventCreateWithFlags(&evD, cudaEventDisableTiming);
    }

    maxabs_kernel<<<22, 256>>>(w1, wc, w2, w3);
    pack_kernel<<<6, 256>>>(w1, wc, w2, w3);

    // block 1: [32,3,224,224] -> codes [32,112,112,32]
    conv1_kernel<<<dim3(7, 14 * 32, 4), 128>>>(x, a1, c1);

    // ---- conv2: mma (s0) || dp (s1) ----
    cudaEventRecord(evA, 0);
    cudaStreamWaitEvent(s1, evA, 0);
    kd2<<<dim3(7, 7 * 32, 1), 128, SMD2, s1>>>(c1, dw2, a1, a2, 2, c2);
    km2<<<dim3(7, 7 * 32, 1), 256, SMM2>>>(c1, wf2, a1, a2, 2, c2);
    cudaEventRecord(evB, s1);
    cudaStreamWaitEvent(0, evB, 0);

    // ---- conv3: mma (s0) || dp (s1) ----
    cudaEventRecord(evC, 0);
    cudaStreamWaitEvent(s1, evC, 0);
    kd3<<<dim3(2, 7 * 32, 2), 128, SMD3, s1>>>(c2, dw3, a2, a3, 3, c3);
    km3<<<dim3(1, 7 * 32, 2), 224, SMM3>>>(c2, wf3, a2, a3, 3, c3);
    cudaEventRecord(evD, s1);
    cudaStreamWaitEvent(0, evD, 0);

    // global max + classifier
    gmax_fc_kernel<<<32, 128>>>(c3, a3, (float*)d_out);
}

// round 10
// speedup vs baseline: 1.2399x; 1.2399x over previous
#include <cuda_runtime.h>
#include <cuda_bf16.h>
#include <stdint.h>
#include <math.h>

// ---------------------------------------------------------------------------
// 2-bit quantized CNN forward.
//  conv1: fp32 conv via packed fma.rn.f32x2
//  conv2/conv3: fused hybrid int8 conv, 32 channels per CTA:
//    warps 0-3: mma.sync.m16n8k32.s8 (tensor pipe), 16 channels
//    warps 4-7: dp4a (fma pipe), 16 channels
//  Exact integer math: conv = (sum code*wint) * (alpha_prev/3 * s_w).
// ---------------------------------------------------------------------------

__device__ unsigned g_smax[4];                 // maxabs bits: w1, wc, w2, w3
__device__ float    g_qw1[32 * 3 * 9];
__device__ float    g_qwc[10 * 128];
__device__ int      g_wf2[9 * 64 * 8];         // mma B-frags [tap][oc][p]
__device__ int      g_wf3[9 * 2 * 128 * 8];    // [tap][chunk][oc][p]
__device__ uint4    g_dw2[2 * 8 * 9 * 4];      // dp4a w [z][k][tap][q]
__device__ uint4    g_dw3[4 * 16 * 9 * 4];     // [z][k][tap][q]
__device__ uint8_t  g_c1[32L * 112 * 112 * 32];
__device__ uint8_t  g_c2[32L * 56 * 56 * 64];
__device__ uint8_t  g_c3[32L * 28 * 28 * 128];

// ---- helpers ---------------------------------------------------------------
__device__ __forceinline__ uint32_t smem_u32(const void* p) {
    uint32_t a;
    asm("{ .reg .u64 t; cvta.to.shared.u64 t, %1; cvt.u32.u64 %0, t; }"
        : "=r"(a) : "l"(p));
    return a;
}
__device__ __forceinline__ void ldsm4(uint32_t addr, int& a0, int& a1,
                                      int& a2, int& a3) {
    asm volatile("ldmatrix.sync.aligned.m8n8.x4.shared.b16 {%0,%1,%2,%3},[%4];"
                 : "=r"(a0), "=r"(a1), "=r"(a2), "=r"(a3) : "r"(addr));
}
__device__ __forceinline__ void mma_s8(int* d, int a0, int a1, int a2, int a3,
                                       int b0, int b1) {
    asm("mma.sync.aligned.m16n8k32.row.col.s32.s8.s8.s32 "
        "{%0,%1,%2,%3},{%4,%5,%6,%7},{%8,%9},{%0,%1,%2,%3};"
        : "+r"(d[0]), "+r"(d[1]), "+r"(d[2]), "+r"(d[3])
        : "r"(a0), "r"(a1), "r"(a2), "r"(a3), "r"(b0), "r"(b1));
}
#define PACK_F32X2(out, lo, hi) \
    asm("mov.b64 %0, {%1, %2};" : "=l"(out) : "r"(lo), "r"(hi))
#define UNPACK_F32X2(lo, hi, in) \
    asm("mov.b64 {%0, %1}, %2;" : "=f"(lo), "=f"(hi) : "l"(in))
#define FMA_F32X2(acc, a, b) \
    asm("fma.rn.f32x2 %0, %1, %2, %0;" : "+l"(acc) : "l"(a), "l"(b))

__device__ __forceinline__ float get_scale(int t) {
    return fmaxf(__uint_as_float(g_smax[t]), 1e-8f);
}

// ---- prologue 1: max|w| -----------------------------------------------------
__global__ void maxabs_kernel(const float* __restrict__ w1,
                              const float* __restrict__ wc,
                              const float* __restrict__ w2,
                              const float* __restrict__ w3) {
    __shared__ float red[8];
    const int blk = blockIdx.x;
    int t, base, cnt;
    const float* p;
    if (blk == 0)      { t = 0; p = w1; base = 0; cnt = 864; }
    else if (blk == 1) { t = 1; p = wc; base = 0; cnt = 1280; }
    else if (blk < 6)  { t = 2; p = w2; base = (blk - 2) * 4608; cnt = 4608; }
    else               { t = 3; p = w3; base = (blk - 6) * 4608; cnt = 4608; }
    float m = 0.f;
    for (int i = threadIdx.x; i < cnt; i += 256)
        m = fmaxf(m, fabsf(p[base + i]));
    #pragma unroll
    for (int o = 16; o; o >>= 1)
        m = fmaxf(m, __shfl_xor_sync(0xffffffffu, m, o));
    if ((threadIdx.x & 31) == 0) red[threadIdx.x >> 5] = m;
    __syncthreads();
    if (threadIdx.x == 0) {
        float v = red[0];
        #pragma unroll
        for (int i = 1; i < 8; i++) v = fmaxf(v, red[i]);
        atomicMax(&g_smax[t], __float_as_uint(v));  // |w|>=0, bit-monotone
    }
}

// ---- prologue 2: quantize + pack --------------------------------------------
// dp4a tables: z = 32-channel group; dp covers oc z*32+16 .. z*32+31.
__global__ void pack_kernel(const float* __restrict__ w1,
                            const float* __restrict__ wc,
                            const float* __restrict__ w2,
                            const float* __restrict__ w3) {
    const int blk = blockIdx.x;
    if (blk == 0) {
        const float s = get_scale(0);
        for (int i = threadIdx.x; i < 864; i += 256)
            g_qw1[i] = rintf(w1[i] / s) * s;
    } else if (blk == 1) {
        const float s = get_scale(1);
        for (int i = threadIdx.x; i < 1280; i += 256)
            g_qwc[i] = rintf(wc[i] / s) * s;
    } else if (blk == 2) {
        // mma frags conv2: word p: icw = (p>>1) + (p&1)*4
        const float inv_s = 1.f / get_scale(2);
        for (int i = threadIdx.x; i < 9 * 64 * 8; i += 256) {
            const int tap = i / 512, r = i % 512, oc = r >> 3, p = r & 7;
            const int icw = (p >> 1) + ((p & 1) << 2);
            uint32_t word = 0;
            #pragma unroll
            for (int l = 0; l < 4; l++) {
                const int ic = icw * 4 + l;
                const int c = (int)rintf(w2[(oc * 32 + ic) * 9 + tap] * inv_s);
                word |= ((uint32_t)(uint8_t)(int8_t)c) << (8 * l);
            }
            g_wf2[i] = (int)word;
        }
    } else if (blk == 3) {
        const float inv_s = 1.f / get_scale(3);
        for (int i = threadIdx.x; i < 9 * 2 * 128 * 8; i += 256) {
            const int tap = i / 2048, r = i % 2048;
            const int chunk = r >> 10, r2 = r & 1023, oc = r2 >> 3, p = r2 & 7;
            const int icw = (p >> 1) + ((p & 1) << 2);
            uint32_t word = 0;
            #pragma unroll
            for (int l = 0; l < 4; l++) {
                const int ic = chunk * 32 + (icw * 4) + l;
                const int c = (int)rintf(w3[(oc * 64 + ic) * 9 + tap] * inv_s);
                word |= ((uint32_t)(uint8_t)(int8_t)c) << (8 * l);
            }
            g_wf3[i] = (int)word;
        }
    } else if (blk == 4) {
        // dp4a conv2: [z][k][tap][q] uint4; oc = z*32+16+q*4+chl, ic = k*4+l
        const float inv_s = 1.f / get_scale(2);
        uint32_t* dst = (uint32_t*)g_dw2;
        for (int i = threadIdx.x; i < 2 * 8 * 9 * 16; i += 256) {
            const int z = i / 1152, r = i % 1152;
            const int k = r / 144, r2 = r % 144;
            const int t = r2 / 16, q = (r2 % 16) >> 2, chl = i & 3;
            const int oc = z * 32 + 16 + q * 4 + chl;
            uint32_t word = 0;
            #pragma unroll
            for (int l = 0; l < 4; l++) {
                const int ic = k * 4 + l;
                const int c = (int)rintf(w2[(oc * 32 + ic) * 9 + t] * inv_s);
                word |= ((uint32_t)(uint8_t)(int8_t)c) << (8 * l);
            }
            dst[i] = word;
        }
    } else {
        // dp4a conv3: z in {0..3}
        const float inv_s = 1.f / get_scale(3);
        uint32_t* dst = (uint32_t*)g_dw3;
        for (int i = threadIdx.x; i < 4 * 16 * 9 * 16; i += 256) {
            const int z = i / 2304, r = i % 2304;
            const int k = r / 144, r2 = r % 144;
            const int t = r2 / 16, q = (r2 % 16) >> 2, chl = i & 3;
            const int oc = z * 32 + 16 + q * 4 + chl;
            uint32_t word = 0;
            #pragma unroll
            for (int l = 0; l < 4; l++) {
                const int ic = k * 4 + l;
                const int c = (int)rintf(w3[(oc * 64 + ic) * 9 + t] * inv_s);
                word |= ((uint32_t)(uint8_t)(int8_t)c) << (8 * l);
            }
            dst[i] = word;
        }
    }
}

// ---- block 1: fp32 conv3x3(pad1) via fma.f32x2 + quant_act + maxpool2 -------
__global__ __launch_bounds__(128) void conv1_kernel(
    const float* __restrict__ x, const float* __restrict__ alpha_p,
    uint8_t* __restrict__ out) {
    constexpr int H = 224, W = 224, PH = 112, PW = 112, OC = 32, OCB = 8;
    __shared__ float sx[3][18][34];
    __shared__ unsigned long long swp[OCB][3][9];   // (w,w) duplicated pairs

    const int tid = threadIdx.x;
    const int tx = tid & 15, ty = tid >> 4;
    const int tile_x = blockIdx.x;
    const int tile_y = blockIdx.y % 14;
    const int b      = blockIdx.y / 14;
    const int oc0    = blockIdx.z * OCB;

    const int px0 = tile_x * 16, py0 = tile_y * 8;
    const int ix0 = 2 * px0 - 1, iy0 = 2 * py0 - 1;

    const float* xb = x + (long)b * 3 * H * W;
    for (int i = tid; i < 3 * 18 * 34; i += 128) {
        const int ic = i / 612, rr = (i % 612) / 34, cc = i % 34;
        const int gy = iy0 + rr, gx = ix0 + cc;
        float v = 0.f;
        if (gy >= 0 && gy < H && gx >= 0 && gx < W)
            v = xb[(long)ic * H * W + gy * W + gx];
        sx[ic][rr][cc] = v;
    }
    if (tid < OCB * 27) {
        const int j = tid / 27, r27 = tid % 27;
        const float w = g_qw1[((oc0 + j) * 3 + r27 / 9) * 9 + r27 % 9];
        unsigned long long pw;
        PACK_F32X2(pw, __float_as_uint(w), __float_as_uint(w));
        swp[j][r27 / 9][r27 % 9] = pw;
    }
    __syncthreads();

    unsigned long long accA[OCB], accB[OCB];
    #pragma unroll
    for (int j = 0; j < OCB; j++) { accA[j] = 0ull; accB[j] = 0ull; }

    #pragma unroll
    for (int ic = 0; ic < 3; ic++) {
        float win[4][4];
        #pragma unroll
        for (int r = 0; r < 4; r++)
            #pragma unroll
            for (int c = 0; c < 4; c++)
                win[r][c] = sx[ic][2 * ty + r][2 * tx + c];
        unsigned long long pk[4][3];
        #pragma unroll
        for (int r = 0; r < 4; r++)
            #pragma unroll
            for (int c = 0; c < 3; c++)
                PACK_F32X2(pk[r][c], __float_as_uint(win[r][c]),
                           __float_as_uint(win[r][c + 1]));
        #pragma unroll
        for (int j = 0; j < OCB; j++) {
            #pragma unroll
            for (int ky = 0; ky < 3; ky++)
                #pragma unroll
                for (int kx = 0; kx < 3; kx++) {
                    FMA_F32X2(accA[j], pk[ky][kx], swp[j][ic][ky * 3 + kx]);
                    FMA_F32X2(accB[j], pk[ky + 1][kx], swp[j][ic][ky * 3 + kx]);
                }
        }
    }

    const float alpha = __ldg(alpha_p);
    const float inv_scale = 3.f / alpha;
    const int px = px0 + tx, py = py0 + ty;
    uint32_t lo = 0, hi = 0;
    #pragma unroll
    for (int j = 0; j < OCB; j++) {
        float p0, p1, p2, p3;
        UNPACK_F32X2(p0, p1, accA[j]);
        UNPACK_F32X2(p2, p3, accB[j]);
        const float m = fmaxf(fmaxf(p0, p1), fmaxf(p2, p3));
        const float y = fminf(fmaxf(m, 0.f), alpha);
        const uint32_t code = (uint32_t)(int)rintf(y * inv_scale);
        if (j < 4) lo |= code << (8 * j);
        else       hi |= code << (8 * (j - 4));
    }
    *(uint2*)&out[(((long)b * PH + py) * PW + px) * OC + oc0] = make_uint2(lo, hi);
}

// ---- blocks 2/3: fused hybrid, 32 channels/CTA (16 mma + 16 dp4a) -----------
template <int H, int IC, int OC, int NOC, int MMAOC, int TW, int TH, int PSTRIDE>
__global__ __launch_bounds__(256, 3) void conv_hyb(
    const uint8_t* __restrict__ xin, const int* __restrict__ wf,
    const uint4* __restrict__ dw,
    const float* __restrict__ aprev_p, const float* __restrict__ acur_p,
    int wtensor, uint8_t* __restrict__ out) {
    constexpr int DPOC = NOC - MMAOC;          // 16
    constexpr int DQ   = DPOC / 4;             // 4
    constexpr int CH   = IC / 32;
    constexpr int IC4  = IC / 4;
    constexpr int IC16 = IC / 16;
    constexpr int TIW  = TW + 2, TIH = TH + 2;
    constexpr int OCG  = MMAOC / 8;            // 2
    constexpr int VPP  = IC / 16;
    constexpr int WTX  = TW / 8, WTY = TH / 2, NWT = WTX * WTY;
    constexpr int PHW  = H / 2;
    constexpr int DLANES = TW * (TH / 2);
    static_assert(DLANES <= 128, "dp lane budget");

    extern __shared__ __align__(16) uint8_t dsm[];
    uint8_t* stile = dsm;                                   // TIH*TIW*PSTRIDE
    uint4*   sdw   = (uint4*)(dsm + TIH * TIW * PSTRIDE);   // IC4*9*DQ uint4
    int*     swf   = (int*)(dsm + TIH * TIW * PSTRIDE + IC4 * 9 * DQ * 16);

    const int tid = threadIdx.x;
    const int tilesY = H / TH;
    const int by = blockIdx.y % tilesY;
    const int b  = blockIdx.y / tilesY;
    const int cx0 = blockIdx.x * TW, cy0 = by * TH;
    const int oc0 = blockIdx.z * NOC;

    // mma B-frags for this CTA's 16 mma channels
    for (int i = tid; i < 9 * CH * MMAOC * 8; i += 256) {
        const int p = i & 7, j = (i >> 3) % MMAOC, tc = (i >> 3) / MMAOC;
        swf[i] = wf[((tc * OC) + oc0 + j) * 8 + p];
    }
    // dp4a weights for this CTA's 16 dp channels
    {
        const uint4* dwz = dw + (long)blockIdx.z * (IC4 * 9 * DQ);
        for (int i = tid; i < IC4 * 9 * DQ; i += 256) sdw[i] = dwz[i];
    }
    // input tile
    for (int i = tid; i < TIH * TIW * VPP; i += 256) {
        const int v = i % VPP, pix = i / VPP;
        const int gx = cx0 - 1 + pix % TIW;
        const int gy = cy0 - 1 + pix / TIW;
        uint4 val = make_uint4(0, 0, 0, 0);
        if (gx >= 0 && gx < H && gy >= 0 && gy < H)
            val = *(const uint4*)(xin + (((long)b * H + gy) * H + gx) * IC + v * 16);
        *(uint4*)(stile + pix * PSTRIDE + v * 16) = val;
    }
    __syncthreads();

    const int warp = tid >> 5, lane = tid & 31;
    const float combined = (__ldg(aprev_p) * (1.f / 3.f)) * get_scale(wtensor);
    const float alpha = __ldg(acur_p);
    const float inv_scale = 3.f / alpha;

    if (warp < 4) {
        // ---------------- mma path (tensor pipe) ----------------
        const uint32_t sbase = smem_u32(stile);
        const int r = lane >> 2;
        for (int wt = warp; wt < NWT; wt += 4) {
            const int tx = wt % WTX, ty = wt / WTX;
            const int piy = ty * 2 + ((lane >> 3) & 1);
            const int pix = tx * 8 + (lane & 7);
            const uint32_t abase = sbase + (piy * TIW + pix) * PSTRIDE
                                 + ((lane >> 4) << 4);
            int acc[OCG][4];
            #pragma unroll
            for (int g = 0; g < OCG; g++)
                #pragma unroll
                for (int q = 0; q < 4; q++) acc[g][q] = 0;

            #pragma unroll
            for (int t = 0; t < 9; t++) {
                const int dy = t / 3, dx = t % 3;
                #pragma unroll
                for (int c = 0; c < CH; c++) {
                    int a0, a1, a2, a3;
                    ldsm4(abase + (dy * TIW + dx) * PSTRIDE + c * 32,
                          a0, a1, a2, a3);
                    #pragma unroll
                    for (int g = 0; g < OCG; g++) {
                        const uint2 bb = *(const uint2*)
                            &swf[(((t * CH + c) * MMAOC) + g * 8 + (lane >> 2)) * 8
                                 + 2 * (lane & 3)];
                        mma_s8(acc[g], a0, a1, a2, a3, (int)bb.x, (int)bb.y);
                    }
                }
            }
            #pragma unroll
            for (int g = 0; g < OCG; g++) {
                const int v0 = max(acc[g][0], acc[g][2]);
                const int v1 = max(acc[g][1], acc[g][3]);
                const int o0 = max(v0, __shfl_xor_sync(0xffffffffu, v0, 4));
                const int o1 = max(v1, __shfl_xor_sync(0xffffffffu, v1, 4));
                if (!(r & 1)) {
                    const int ppx = (cx0 >> 1) + tx * 4 + (r >> 1);
                    const int ppy = (cy0 >> 1) + ty;
                    const float f0 = fminf(fmaxf((float)o0 * combined, 0.f), alpha);
                    const float f1 = fminf(fmaxf((float)o1 * combined, 0.f), alpha);
                    const uint32_t c0 = (uint32_t)(int)rintf(f0 * inv_scale);
                    const uint32_t c1 = (uint32_t)(int)rintf(f1 * inv_scale);
                    const int oc = oc0 + g * 8 + (lane & 3) * 2;
                    *(uint16_t*)(out + (((long)b * PHW + ppy) * PHW + ppx) * OC + oc)
                        = (uint16_t)(c0 | (c1 << 8));
                }
            }
        }
    } else {
        // -------- dp4a path (fma pipe), column-streamed LDS.128 --------
        const int dt = tid - 128;              // 0..127
        const int cx = dt % TW, cyp = dt / TW;
        const bool active = dt < DLANES;
        const int dcyp = min(cyp, TH / 2 - 1);

        int acc[DPOC][2];
        #pragma unroll
        for (int j = 0; j < DPOC; j++) { acc[j][0] = 0; acc[j][1] = 0; }

        #pragma unroll 1
        for (int g4 = 0; g4 < IC16; g4++) {
            const uint8_t* tb = stile + ((2 * dcyp) * TIW + cx) * PSTRIDE
                              + g4 * 16;
            #pragma unroll
            for (int cc = 0; cc < 3; cc++) {
                uint4 col[4];
                #pragma unroll
                for (int rr = 0; rr < 4; rr++)
                    col[rr] = *(const uint4*)(tb + (rr * TIW + cc) * PSTRIDE);
                #pragma unroll
                for (int dy = 0; dy < 3; dy++) {
                    const int t = dy * 3 + cc;
                    #pragma unroll
                    for (int kk = 0; kk < 4; kk++) {
                        const uint32_t a0 = ((const uint32_t*)&col[dy])[kk];
                        const uint32_t a1 = ((const uint32_t*)&col[dy + 1])[kk];
                        const int k = g4 * 4 + kk;
                        #pragma unroll
                        for (int q = 0; q < DQ; q++) {
                            const uint4 w = sdw[(k * 9 + t) * DQ + q];
                            acc[q*4+0][0] = __dp4a((int)a0, (int)w.x, acc[q*4+0][0]);
                            acc[q*4+0][1] = __dp4a((int)a1, (int)w.x, acc[q*4+0][1]);
                            acc[q*4+1][0] = __dp4a((int)a0, (int)w.y, acc[q*4+1][0]);
                            acc[q*4+1][1] = __dp4a((int)a1, (int)w.y, acc[q*4+1][1]);
                            acc[q*4+2][0] = __dp4a((int)a0, (int)w.z, acc[q*4+2][0]);
                            acc[q*4+2][1] = __dp4a((int)a1, (int)w.z, acc[q*4+2][1]);
                            acc[q*4+3][0] = __dp4a((int)a0, (int)w.w, acc[q*4+3][0]);
                            acc[q*4+3][1] = __dp4a((int)a1, (int)w.w, acc[q*4+3][1]);
                        }
                    }
                }
            }
        }

        uint32_t pw[DQ];
        #pragma unroll
        for (int q = 0; q < DQ; q++) pw[q] = 0;
        #pragma unroll
        for (int j = 0; j < DPOC; j++) {
            int v = max(acc[j][0], acc[j][1]);               // vertical pool
            v = max(v, __shfl_xor_sync(0xffffffffu, v, 1));  // horizontal pool
            const float f = fminf(fmaxf((float)v * combined, 0.f), alpha);
            const uint32_t code = (uint32_t)(int)rintf(f * inv_scale);
            pw[j >> 2] |= code << (8 * (j & 3));
        }
        if (active && !(cx & 1)) {
            const int ppx = (cx0 >> 1) + (cx >> 1);
            const int ppy = (cy0 >> 1) + cyp;
            uint8_t* o = out + (((long)b * PHW + ppy) * PHW + ppx) * OC
                       + oc0 + MMAOC;
            *(uint4*)o = make_uint4(pw[0], pw[1], pw[2], pw[3]);
        }
    }
}

// ---- global max over 28x28 + 1x1 quantized conv classifier ------------------
__global__ void gmax_fc_kernel(const uint8_t* __restrict__ h3,
                               const float* __restrict__ a3_p,
                               float* __restrict__ out) {
    __shared__ uint32_t sm[4][32];
    __shared__ float gm[128];
    const int b = blockIdx.x;
    const int tid = threadIdx.x;
    const int w = tid >> 5, c4 = tid & 31;
    const uint32_t* p = (const uint32_t*)(h3 + (long)b * 784 * 128);
    uint32_t m = 0;
    for (int pix = w; pix < 784; pix += 4)
        m = __vmaxu4(m, p[(long)pix * 32 + c4]);
    sm[w][c4] = m;
    __syncthreads();
    if (tid < 32) {
        const uint32_t v = __vmaxu4(__vmaxu4(sm[0][tid], sm[1][tid]),
                                    __vmaxu4(sm[2][tid], sm[3][tid]));
        const float sc = __ldg(a3_p) * (1.f / 3.f);
        gm[tid * 4 + 0] = (float)(v & 0xff) * sc;
        gm[tid * 4 + 1] = (float)((v >> 8) & 0xff) * sc;
        gm[tid * 4 + 2] = (float)((v >> 16) & 0xff) * sc;
        gm[tid * 4 + 3] = (float)(v >> 24) * sc;
    }
    __syncthreads();
    if (tid < 10) {
        float s = 0.f;
        #pragma unroll 8
        for (int k = 0; k < 128; k++)
            s = fmaf(gm[k], g_qwc[tid * 128 + k], s);
        out[b * 10 + tid] = s;
    }
}

// ---------------------------------------------------------------------------
extern "C" void kernel_launch(void* const* d_in, const int* in_sizes, int n_in,
                              void* d_out, int out_size) {
    const float* x  = (const float*)d_in[0];
    const float* w1 = (const float*)d_in[1];
    const float* w2 = (const float*)d_in[2];
    const float* w3 = (const float*)d_in[3];
    const float* wc = (const float*)d_in[4];
    const float* a1 = (const float*)d_in[5];
    const float* a2 = (const float*)d_in[6];
    const float* a3 = (const float*)d_in[7];

    int *wf2, *wf3;
    uint4 *dw2, *dw3;
    uint8_t *c1, *c2, *c3;
    cudaGetSymbolAddress((void**)&wf2, g_wf2);
    cudaGetSymbolAddress((void**)&wf3, g_wf3);
    cudaGetSymbolAddress((void**)&dw2, g_dw2);
    cudaGetSymbolAddress((void**)&dw3, g_dw3);
    cudaGetSymbolAddress((void**)&c1, g_c1);
    cudaGetSymbolAddress((void**)&c2, g_c2);
    cudaGetSymbolAddress((void**)&c3, g_c3);

    // conv2: 32 channels/CTA (16 mma + 16 dp), tile 16x16, z=2
    auto k2 = conv_hyb<112, 32, 64, 32, 16, 16, 16, 48>;
    constexpr int SM2 = 18 * 18 * 48 + 8 * 9 * 4 * 16 + 9 * 1 * 16 * 8 * 4;
    // conv3: 32 channels/CTA, tile 8x28, z=4
    auto k3 = conv_hyb<56, 64, 128, 32, 16, 8, 28, 80>;
    constexpr int SM3 = 30 * 10 * 80 + 16 * 9 * 4 * 16 + 9 * 2 * 16 * 8 * 4;
    cudaFuncSetAttribute(k2, cudaFuncAttributeMaxDynamicSharedMemorySize, SM2);
    cudaFuncSetAttribute(k3, cudaFuncAttributeMaxDynamicSharedMemorySize, SM3);

    maxabs_kernel<<<22, 256>>>(w1, wc, w2, w3);
    pack_kernel<<<6, 256>>>(w1, wc, w2, w3);

    // block 1: [32,3,224,224] -> codes [32,112,112,32]
    conv1_kernel<<<dim3(7, 14 * 32, 4), 128>>>(x, a1, c1);
    // block 2: -> codes [32,56,56,64]
    k2<<<dim3(7, 7 * 32, 2), 256, SM2>>>(c1, wf2, dw2, a1, a2, 2, c2);
    // block 3: -> codes [32,28,28,128]
    k3<<<dim3(7, 2 * 32, 4), 256, SM3>>>(c2, wf3, dw3, a2, a3, 3, c3);

    // global max + classifier
    gmax_fc_kernel<<<32, 128>>>(c3, a3, (float*)d_out);
}

// round 11
// speedup vs baseline: 1.2842x; 1.0357x over previous
#include <cuda_runtime.h>
#include <cuda_bf16.h>
#include <stdint.h>
#include <math.h>

// ---------------------------------------------------------------------------
// 2-bit quantized CNN forward.
//  conv1: fp32 conv via packed fma.rn.f32x2
//  conv2/conv3: fused hybrid int8 conv, 32 channels per CTA:
//    warps 0-3: mma.sync.m16n8k32.s8 (tensor pipe), 16 channels
//    warps 4-7: dp4a (fma pipe), 16 channels, rolling 2-row window
//  __launch_bounds__(256,4): 64 regs -> 4 CTAs/SM (full RF).
//  Exact integer math: conv = (sum code*wint) * (alpha_prev/3 * s_w).
// ---------------------------------------------------------------------------

__device__ unsigned g_smax[4];                 // maxabs bits: w1, wc, w2, w3
__device__ float    g_qw1[32 * 3 * 9];
__device__ float    g_qwc[10 * 128];
__device__ int      g_wf2[9 * 64 * 8];         // mma B-frags [tap][oc][p]
__device__ int      g_wf3[9 * 2 * 128 * 8];    // [tap][chunk][oc][p]
__device__ uint4    g_dw2[2 * 8 * 9 * 4];      // dp4a w [z][k][tap][q]
__device__ uint4    g_dw3[4 * 16 * 9 * 4];     // [z][k][tap][q]
__device__ uint8_t  g_c1[32L * 112 * 112 * 32];
__device__ uint8_t  g_c2[32L * 56 * 56 * 64];
__device__ uint8_t  g_c3[32L * 28 * 28 * 128];

// ---- helpers ---------------------------------------------------------------
__device__ __forceinline__ uint32_t smem_u32(const void* p) {
    uint32_t a;
    asm("{ .reg .u64 t; cvta.to.shared.u64 t, %1; cvt.u32.u64 %0, t; }"
        : "=r"(a) : "l"(p));
    return a;
}
__device__ __forceinline__ void ldsm4(uint32_t addr, int& a0, int& a1,
                                      int& a2, int& a3) {
    asm volatile("ldmatrix.sync.aligned.m8n8.x4.shared.b16 {%0,%1,%2,%3},[%4];"
                 : "=r"(a0), "=r"(a1), "=r"(a2), "=r"(a3) : "r"(addr));
}
__device__ __forceinline__ void mma_s8(int* d, int a0, int a1, int a2, int a3,
                                       int b0, int b1) {
    asm("mma.sync.aligned.m16n8k32.row.col.s32.s8.s8.s32 "
        "{%0,%1,%2,%3},{%4,%5,%6,%7},{%8,%9},{%0,%1,%2,%3};"
        : "+r"(d[0]), "+r"(d[1]), "+r"(d[2]), "+r"(d[3])
        : "r"(a0), "r"(a1), "r"(a2), "r"(a3), "r"(b0), "r"(b1));
}
#define PACK_F32X2(out, lo, hi) \
    asm("mov.b64 %0, {%1, %2};" : "=l"(out) : "r"(lo), "r"(hi))
#define UNPACK_F32X2(lo, hi, in) \
    asm("mov.b64 {%0, %1}, %2;" : "=f"(lo), "=f"(hi) : "l"(in))
#define FMA_F32X2(acc, a, b) \
    asm("fma.rn.f32x2 %0, %1, %2, %0;" : "+l"(acc) : "l"(a), "l"(b))

__device__ __forceinline__ float get_scale(int t) {
    return fmaxf(__uint_as_float(g_smax[t]), 1e-8f);
}

// ---- prologue 1: max|w| -----------------------------------------------------
__global__ void maxabs_kernel(const float* __restrict__ w1,
                              const float* __restrict__ wc,
                              const float* __restrict__ w2,
                              const float* __restrict__ w3) {
    __shared__ float red[8];
    const int blk = blockIdx.x;
    int t, base, cnt;
    const float* p;
    if (blk == 0)      { t = 0; p = w1; base = 0; cnt = 864; }
    else if (blk == 1) { t = 1; p = wc; base = 0; cnt = 1280; }
    else if (blk < 6)  { t = 2; p = w2; base = (blk - 2) * 4608; cnt = 4608; }
    else               { t = 3; p = w3; base = (blk - 6) * 4608; cnt = 4608; }
    float m = 0.f;
    for (int i = threadIdx.x; i < cnt; i += 256)
        m = fmaxf(m, fabsf(p[base + i]));
    #pragma unroll
    for (int o = 16; o; o >>= 1)
        m = fmaxf(m, __shfl_xor_sync(0xffffffffu, m, o));
    if ((threadIdx.x & 31) == 0) red[threadIdx.x >> 5] = m;
    __syncthreads();
    if (threadIdx.x == 0) {
        float v = red[0];
        #pragma unroll
        for (int i = 1; i < 8; i++) v = fmaxf(v, red[i]);
        atomicMax(&g_smax[t], __float_as_uint(v));  // |w|>=0, bit-monotone
    }
}

// ---- prologue 2: quantize + pack --------------------------------------------
// dp4a tables: z = 32-channel group; dp covers oc z*32+16 .. z*32+31.
__global__ void pack_kernel(const float* __restrict__ w1,
                            const float* __restrict__ wc,
                            const float* __restrict__ w2,
                            const float* __restrict__ w3) {
    const int blk = blockIdx.x;
    if (blk == 0) {
        const float s = get_scale(0);
        for (int i = threadIdx.x; i < 864; i += 256)
            g_qw1[i] = rintf(w1[i] / s) * s;
    } else if (blk == 1) {
        const float s = get_scale(1);
        for (int i = threadIdx.x; i < 1280; i += 256)
            g_qwc[i] = rintf(wc[i] / s) * s;
    } else if (blk == 2) {
        // mma frags conv2: word p: icw = (p>>1) + (p&1)*4
        const float inv_s = 1.f / get_scale(2);
        for (int i = threadIdx.x; i < 9 * 64 * 8; i += 256) {
            const int tap = i / 512, r = i % 512, oc = r >> 3, p = r & 7;
            const int icw = (p >> 1) + ((p & 1) << 2);
            uint32_t word = 0;
            #pragma unroll
            for (int l = 0; l < 4; l++) {
                const int ic = icw * 4 + l;
                const int c = (int)rintf(w2[(oc * 32 + ic) * 9 + tap] * inv_s);
                word |= ((uint32_t)(uint8_t)(int8_t)c) << (8 * l);
            }
            g_wf2[i] = (int)word;
        }
    } else if (blk == 3) {
        const float inv_s = 1.f / get_scale(3);
        for (int i = threadIdx.x; i < 9 * 2 * 128 * 8; i += 256) {
            const int tap = i / 2048, r = i % 2048;
            const int chunk = r >> 10, r2 = r & 1023, oc = r2 >> 3, p = r2 & 7;
            const int icw = (p >> 1) + ((p & 1) << 2);
            uint32_t word = 0;
            #pragma unroll
            for (int l = 0; l < 4; l++) {
                const int ic = chunk * 32 + (icw * 4) + l;
                const int c = (int)rintf(w3[(oc * 64 + ic) * 9 + tap] * inv_s);
                word |= ((uint32_t)(uint8_t)(int8_t)c) << (8 * l);
            }
            g_wf3[i] = (int)word;
        }
    } else if (blk == 4) {
        // dp4a conv2: [z][k][tap][q] uint4; oc = z*32+16+q*4+chl, ic = k*4+l
        const float inv_s = 1.f / get_scale(2);
        uint32_t* dst = (uint32_t*)g_dw2;
        for (int i = threadIdx.x; i < 2 * 8 * 9 * 16; i += 256) {
            const int z = i / 1152, r = i % 1152;
            const int k = r / 144, r2 = r % 144;
            const int t = r2 / 16, q = (r2 % 16) >> 2, chl = i & 3;
            const int oc = z * 32 + 16 + q * 4 + chl;
            uint32_t word = 0;
            #pragma unroll
            for (int l = 0; l < 4; l++) {
                const int ic = k * 4 + l;
                const int c = (int)rintf(w2[(oc * 32 + ic) * 9 + t] * inv_s);
                word |= ((uint32_t)(uint8_t)(int8_t)c) << (8 * l);
            }
            dst[i] = word;
        }
    } else {
        // dp4a conv3: z in {0..3}
        const float inv_s = 1.f / get_scale(3);
        uint32_t* dst = (uint32_t*)g_dw3;
        for (int i = threadIdx.x; i < 4 * 16 * 9 * 16; i += 256) {
            const int z = i / 2304, r = i % 2304;
            const int k = r / 144, r2 = r % 144;
            const int t = r2 / 16, q = (r2 % 16) >> 2, chl = i & 3;
            const int oc = z * 32 + 16 + q * 4 + chl;
            uint32_t word = 0;
            #pragma unroll
            for (int l = 0; l < 4; l++) {
                const int ic = k * 4 + l;
                const int c = (int)rintf(w3[(oc * 64 + ic) * 9 + t] * inv_s);
                word |= ((uint32_t)(uint8_t)(int8_t)c) << (8 * l);
            }
            dst[i] = word;
        }
    }
}

// ---- block 1: fp32 conv3x3(pad1) via fma.f32x2 + quant_act + maxpool2 -------
__global__ __launch_bounds__(128) void conv1_kernel(
    const float* __restrict__ x, const float* __restrict__ alpha_p,
    uint8_t* __restrict__ out) {
    constexpr int H = 224, W = 224, PH = 112, PW = 112, OC = 32, OCB = 8;
    __shared__ float sx[3][18][34];
    __shared__ unsigned long long swp[OCB][3][9];   // (w,w) duplicated pairs

    const int tid = threadIdx.x;
    const int tx = tid & 15, ty = tid >> 4;
    const int tile_x = blockIdx.x;
    const int tile_y = blockIdx.y % 14;
    const int b      = blockIdx.y / 14;
    const int oc0    = blockIdx.z * OCB;

    const int px0 = tile_x * 16, py0 = tile_y * 8;
    const int ix0 = 2 * px0 - 1, iy0 = 2 * py0 - 1;

    const float* xb = x + (long)b * 3 * H * W;
    for (int i = tid; i < 3 * 18 * 34; i += 128) {
        const int ic = i / 612, rr = (i % 612) / 34, cc = i % 34;
        const int gy = iy0 + rr, gx = ix0 + cc;
        float v = 0.f;
        if (gy >= 0 && gy < H && gx >= 0 && gx < W)
            v = xb[(long)ic * H * W + gy * W + gx];
        sx[ic][rr][cc] = v;
    }
    if (tid < OCB * 27) {
        const int j = tid / 27, r27 = tid % 27;
        const float w = g_qw1[((oc0 + j) * 3 + r27 / 9) * 9 + r27 % 9];
        unsigned long long pw;
        PACK_F32X2(pw, __float_as_uint(w), __float_as_uint(w));
        swp[j][r27 / 9][r27 % 9] = pw;
    }
    __syncthreads();

    unsigned long long accA[OCB], accB[OCB];
    #pragma unroll
    for (int j = 0; j < OCB; j++) { accA[j] = 0ull; accB[j] = 0ull; }

    #pragma unroll
    for (int ic = 0; ic < 3; ic++) {
        float win[4][4];
        #pragma unroll
        for (int r = 0; r < 4; r++)
            #pragma unroll
            for (int c = 0; c < 4; c++)
                win[r][c] = sx[ic][2 * ty + r][2 * tx + c];
        unsigned long long pk[4][3];
        #pragma unroll
        for (int r = 0; r < 4; r++)
            #pragma unroll
            for (int c = 0; c < 3; c++)
                PACK_F32X2(pk[r][c], __float_as_uint(win[r][c]),
                           __float_as_uint(win[r][c + 1]));
        #pragma unroll
        for (int j = 0; j < OCB; j++) {
            #pragma unroll
            for (int ky = 0; ky < 3; ky++)
                #pragma unroll
                for (int kx = 0; kx < 3; kx++) {
                    FMA_F32X2(accA[j], pk[ky][kx], swp[j][ic][ky * 3 + kx]);
                    FMA_F32X2(accB[j], pk[ky + 1][kx], swp[j][ic][ky * 3 + kx]);
                }
        }
    }

    const float alpha = __ldg(alpha_p);
    const float inv_scale = 3.f / alpha;
    const int px = px0 + tx, py = py0 + ty;
    uint32_t lo = 0, hi = 0;
    #pragma unroll
    for (int j = 0; j < OCB; j++) {
        float p0, p1, p2, p3;
        UNPACK_F32X2(p0, p1, accA[j]);
        UNPACK_F32X2(p2, p3, accB[j]);
        const float m = fmaxf(fmaxf(p0, p1), fmaxf(p2, p3));
        const float y = fminf(fmaxf(m, 0.f), alpha);
        const uint32_t code = (uint32_t)(int)rintf(y * inv_scale);
        if (j < 4) lo |= code << (8 * j);
        else       hi |= code << (8 * (j - 4));
    }
    *(uint2*)&out[(((long)b * PH + py) * PW + px) * OC + oc0] = make_uint2(lo, hi);
}

// ---- blocks 2/3: fused hybrid, 32 channels/CTA (16 mma + 16 dp4a) -----------
// launch_bounds(256,4): target 64 regs -> 4 CTAs/SM.
template <int H, int IC, int OC, int NOC, int MMAOC, int TW, int TH, int PSTRIDE>
__global__ __launch_bounds__(256, 4) void conv_hyb(
    const uint8_t* __restrict__ xin, const int* __restrict__ wf,
    const uint4* __restrict__ dw,
    const float* __restrict__ aprev_p, const float* __restrict__ acur_p,
    int wtensor, uint8_t* __restrict__ out) {
    constexpr int DPOC = NOC - MMAOC;          // 16
    constexpr int DQ   = DPOC / 4;             // 4
    constexpr int CH   = IC / 32;
    constexpr int IC4  = IC / 4;
    constexpr int IC16 = IC / 16;
    constexpr int TIW  = TW + 2, TIH = TH + 2;
    constexpr int OCG  = MMAOC / 8;            // 2
    constexpr int VPP  = IC / 16;
    constexpr int WTX  = TW / 8, WTY = TH / 2, NWT = WTX * WTY;
    constexpr int PHW  = H / 2;
    constexpr int DLANES = TW * (TH / 2);
    static_assert(DLANES <= 128, "dp lane budget");

    extern __shared__ __align__(16) uint8_t dsm[];
    uint8_t* stile = dsm;                                   // TIH*TIW*PSTRIDE
    uint4*   sdw   = (uint4*)(dsm + TIH * TIW * PSTRIDE);   // IC4*9*DQ uint4
    int*     swf   = (int*)(dsm + TIH * TIW * PSTRIDE + IC4 * 9 * DQ * 16);

    const int tid = threadIdx.x;
    const int tilesY = H / TH;
    const int by = blockIdx.y % tilesY;
    const int b  = blockIdx.y / tilesY;
    const int cx0 = blockIdx.x * TW, cy0 = by * TH;
    const int oc0 = blockIdx.z * NOC;

    // mma B-frags for this CTA's 16 mma channels
    for (int i = tid; i < 9 * CH * MMAOC * 8; i += 256) {
        const int p = i & 7, j = (i >> 3) % MMAOC, tc = (i >> 3) / MMAOC;
        swf[i] = wf[((tc * OC) + oc0 + j) * 8 + p];
    }
    // dp4a weights for this CTA's 16 dp channels
    {
        const uint4* dwz = dw + (long)blockIdx.z * (IC4 * 9 * DQ);
        for (int i = tid; i < IC4 * 9 * DQ; i += 256) sdw[i] = dwz[i];
    }
    // input tile
    for (int i = tid; i < TIH * TIW * VPP; i += 256) {
        const int v = i % VPP, pix = i / VPP;
        const int gx = cx0 - 1 + pix % TIW;
        const int gy = cy0 - 1 + pix / TIW;
        uint4 val = make_uint4(0, 0, 0, 0);
        if (gx >= 0 && gx < H && gy >= 0 && gy < H)
            val = *(const uint4*)(xin + (((long)b * H + gy) * H + gx) * IC + v * 16);
        *(uint4*)(stile + pix * PSTRIDE + v * 16) = val;
    }
    __syncthreads();

    const int warp = tid >> 5, lane = tid & 31;
    const float combined = (__ldg(aprev_p) * (1.f / 3.f)) * get_scale(wtensor);
    const float alpha = __ldg(acur_p);
    const float inv_scale = 3.f / alpha;

    if (warp < 4) {
        // ---------------- mma path (tensor pipe) ----------------
        const uint32_t sbase = smem_u32(stile);
        const int r = lane >> 2;
        for (int wt = warp; wt < NWT; wt += 4) {
            const int tx = wt % WTX, ty = wt / WTX;
            const int piy = ty * 2 + ((lane >> 3) & 1);
            const int pix = tx * 8 + (lane & 7);
            const uint32_t abase = sbase + (piy * TIW + pix) * PSTRIDE
                                 + ((lane >> 4) << 4);
            int acc[OCG][4];
            #pragma unroll
            for (int g = 0; g < OCG; g++)
                #pragma unroll
                for (int q = 0; q < 4; q++) acc[g][q] = 0;

            #pragma unroll
            for (int t = 0; t < 9; t++) {
                const int dy = t / 3, dx = t % 3;
                #pragma unroll
                for (int c = 0; c < CH; c++) {
                    int a0, a1, a2, a3;
                    ldsm4(abase + (dy * TIW + dx) * PSTRIDE + c * 32,
                          a0, a1, a2, a3);
                    #pragma unroll
                    for (int g = 0; g < OCG; g++) {
                        const uint2 bb = *(const uint2*)
                            &swf[(((t * CH + c) * MMAOC) + g * 8 + (lane >> 2)) * 8
                                 + 2 * (lane & 3)];
                        mma_s8(acc[g], a0, a1, a2, a3, (int)bb.x, (int)bb.y);
                    }
                }
            }
            #pragma unroll
            for (int g = 0; g < OCG; g++) {
                const int v0 = max(acc[g][0], acc[g][2]);
                const int v1 = max(acc[g][1], acc[g][3]);
                const int o0 = max(v0, __shfl_xor_sync(0xffffffffu, v0, 4));
                const int o1 = max(v1, __shfl_xor_sync(0xffffffffu, v1, 4));
                if (!(r & 1)) {
                    const int ppx = (cx0 >> 1) + tx * 4 + (r >> 1);
                    const int ppy = (cy0 >> 1) + ty;
                    const float f0 = fminf(fmaxf((float)o0 * combined, 0.f), alpha);
                    const float f1 = fminf(fmaxf((float)o1 * combined, 0.f), alpha);
                    const uint32_t c0 = (uint32_t)(int)rintf(f0 * inv_scale);
                    const uint32_t c1 = (uint32_t)(int)rintf(f1 * inv_scale);
                    const int oc = oc0 + g * 8 + (lane & 3) * 2;
                    *(uint16_t*)(out + (((long)b * PHW + ppy) * PHW + ppx) * OC + oc)
                        = (uint16_t)(c0 | (c1 << 8));
                }
            }
        }
    } else {
        // ---- dp4a path (fma pipe), rolling 2-row window, LDS.128 ----
        const int dt = tid - 128;              // 0..127
        const int cx = dt % TW, cyp = dt / TW;
        const bool active = dt < DLANES;
        const int dcyp = min(cyp, TH / 2 - 1);

        int acc[DPOC][2];
        #pragma unroll
        for (int j = 0; j < DPOC; j++) { acc[j][0] = 0; acc[j][1] = 0; }

        #pragma unroll 1
        for (int g4 = 0; g4 < IC16; g4++) {
            const uint8_t* tb = stile + ((2 * dcyp) * TIW + cx) * PSTRIDE
                              + g4 * 16;
            #pragma unroll
            for (int cc = 0; cc < 3; cc++) {
                const uint8_t* cp = tb + cc * PSTRIDE;
                uint4 r0 = *(const uint4*)(cp);
                uint4 r1 = *(const uint4*)(cp + TIW * PSTRIDE);
                #pragma unroll
                for (int dy = 0; dy < 3; dy++) {
                    const int t = dy * 3 + cc;
                    #pragma unroll
                    for (int kk = 0; kk < 4; kk++) {
                        const uint32_t a0 = ((const uint32_t*)&r0)[kk];
                        const uint32_t a1 = ((const uint32_t*)&r1)[kk];
                        const int k = g4 * 4 + kk;
                        #pragma unroll
                        for (int q = 0; q < DQ; q++) {
                            const uint4 w = sdw[(k * 9 + t) * DQ + q];
                            acc[q*4+0][0] = __dp4a((int)a0, (int)w.x, acc[q*4+0][0]);
                            acc[q*4+0][1] = __dp4a((int)a1, (int)w.x, acc[q*4+0][1]);
                            acc[q*4+1][0] = __dp4a((int)a0, (int)w.y, acc[q*4+1][0]);
                            acc[q*4+1][1] = __dp4a((int)a1, (int)w.y, acc[q*4+1][1]);
                            acc[q*4+2][0] = __dp4a((int)a0, (int)w.z, acc[q*4+2][0]);
                            acc[q*4+2][1] = __dp4a((int)a1, (int)w.z, acc[q*4+2][1]);
                            acc[q*4+3][0] = __dp4a((int)a0, (int)w.w, acc[q*4+3][0]);
                            acc[q*4+3][1] = __dp4a((int)a1, (int)w.w, acc[q*4+3][1]);
                        }
                    }
                    if (dy < 2) {
                        r0 = r1;
                        r1 = *(const uint4*)(cp + (dy + 2) * TIW * PSTRIDE);
                    }
                }
            }
        }

        uint32_t pw[DQ];
        #pragma unroll
        for (int q = 0; q < DQ; q++) pw[q] = 0;
        #pragma unroll
        for (int j = 0; j < DPOC; j++) {
            int v = max(acc[j][0], acc[j][1]);               // vertical pool
            v = max(v, __shfl_xor_sync(0xffffffffu, v, 1));  // horizontal pool
            const float f = fminf(fmaxf((float)v * combined, 0.f), alpha);
            const uint32_t code = (uint32_t)(int)rintf(f * inv_scale);
            pw[j >> 2] |= code << (8 * (j & 3));
        }
        if (active && !(cx & 1)) {
            const int ppx = (cx0 >> 1) + (cx >> 1);
            const int ppy = (cy0 >> 1) + cyp;
            uint8_t* o = out + (((long)b * PHW + ppy) * PHW + ppx) * OC
                       + oc0 + MMAOC;
            *(uint4*)o = make_uint4(pw[0], pw[1], pw[2], pw[3]);
        }
    }
}

// ---- global max over 28x28 + 1x1 quantized conv classifier ------------------
__global__ void gmax_fc_kernel(const uint8_t* __restrict__ h3,
                               const float* __restrict__ a3_p,
                               float* __restrict__ out) {
    __shared__ uint32_t sm[4][32];
    __shared__ float gm[128];
    const int b = blockIdx.x;
    const int tid = threadIdx.x;
    const int w = tid >> 5, c4 = tid & 31;
    const uint32_t* p = (const uint32_t*)(h3 + (long)b * 784 * 128);
    uint32_t m = 0;
    for (int pix = w; pix < 784; pix += 4)
        m = __vmaxu4(m, p[(long)pix * 32 + c4]);
    sm[w][c4] = m;
    __syncthreads();
    if (tid < 32) {
        const uint32_t v = __vmaxu4(__vmaxu4(sm[0][tid], sm[1][tid]),
                                    __vmaxu4(sm[2][tid], sm[3][tid]));
        const float sc = __ldg(a3_p) * (1.f / 3.f);
        gm[tid * 4 + 0] = (float)(v & 0xff) * sc;
        gm[tid * 4 + 1] = (float)((v >> 8) & 0xff) * sc;
        gm[tid * 4 + 2] = (float)((v >> 16) & 0xff) * sc;
        gm[tid * 4 + 3] = (float)(v >> 24) * sc;
    }
    __syncthreads();
    if (tid < 10) {
        float s = 0.f;
        #pragma unroll 8
        for (int k = 0; k < 128; k++)
            s = fmaf(gm[k], g_qwc[tid * 128 + k], s);
        out[b * 10 + tid] = s;
    }
}

// ---------------------------------------------------------------------------
extern "C" void kernel_launch(void* const* d_in, const int* in_sizes, int n_in,
                              void* d_out, int out_size) {
    const float* x  = (const float*)d_in[0];
    const float* w1 = (const float*)d_in[1];
    const float* w2 = (const float*)d_in[2];
    const float* w3 = (const float*)d_in[3];
    const float* wc = (const float*)d_in[4];
    const float* a1 = (const float*)d_in[5];
    const float* a2 = (const float*)d_in[6];
    const float* a3 = (const float*)d_in[7];

    int *wf2, *wf3;
    uint4 *dw2, *dw3;
    uint8_t *c1, *c2, *c3;
    cudaGetSymbolAddress((void**)&wf2, g_wf2);
    cudaGetSymbolAddress((void**)&wf3, g_wf3);
    cudaGetSymbolAddress((void**)&dw2, g_dw2);
    cudaGetSymbolAddress((void**)&dw3, g_dw3);
    cudaGetSymbolAddress((void**)&c1, g_c1);
    cudaGetSymbolAddress((void**)&c2, g_c2);
    cudaGetSymbolAddress((void**)&c3, g_c3);

    // conv2: 32 channels/CTA (16 mma + 16 dp), tile 16x16, z=2
    auto k2 = conv_hyb<112, 32, 64, 32, 16, 16, 16, 48>;
    constexpr int SM2 = 18 * 18 * 48 + 8 * 9 * 4 * 16 + 9 * 1 * 16 * 8 * 4;
    // conv3: 32 channels/CTA, tile 8x28, z=4
    auto k3 = conv_hyb<56, 64, 128, 32, 16, 8, 28, 80>;
    constexpr int SM3 = 30 * 10 * 80 + 16 * 9 * 4 * 16 + 9 * 2 * 16 * 8 * 4;
    cudaFuncSetAttribute(k2, cudaFuncAttributeMaxDynamicSharedMemorySize, SM2);
    cudaFuncSetAttribute(k3, cudaFuncAttributeMaxDynamicSharedMemorySize, SM3);

    maxabs_kernel<<<22, 256>>>(w1, wc, w2, w3);
    pack_kernel<<<6, 256>>>(w1, wc, w2, w3);

    // block 1: [32,3,224,224] -> codes [32,112,112,32]
    conv1_kernel<<<dim3(7, 14 * 32, 4), 128>>>(x, a1, c1);
    // block 2: -> codes [32,56,56,64]
    k2<<<dim3(7, 7 * 32, 2), 256, SM2>>>(c1, wf2, dw2, a1, a2, 2, c2);
    // block 3: -> codes [32,28,28,128]
    k3<<<dim3(7, 2 * 32, 4), 256, SM3>>>(c2, wf3, dw3, a2, a3, 3, c3);

    // global max + classifier
    gmax_fc_kernel<<<32, 128>>>(c3, a3, (float*)d_out);
}

// round 12
// speedup vs baseline: 1.2869x; 1.0021x over previous
#include <cuda_runtime.h>
#include <cuda_bf16.h>
#include <stdint.h>
#include <math.h>

// ---------------------------------------------------------------------------
// 2-bit quantized CNN forward.
//  conv1: fp32 conv via packed fma.rn.f32x2 (16 oc/CTA, tile loaded twice)
//  conv2/conv3: fused hybrid int8 conv, 32 channels per CTA:
//    warps 0-3: mma.sync.m16n8k32.s8 (tensor pipe), 16 channels
//    warps 4-7: dp4a (fma pipe), 16 channels, rolling 2-row window
//  Exact integer math: conv = (sum code*wint) * (alpha_prev/3 * s_w).
// ---------------------------------------------------------------------------

__device__ unsigned g_smax[4];                 // scale bits: [2]=w2, [3]=w3
__device__ float    g_qw1[32 * 3 * 9];
__device__ float    g_qwc[10 * 128];
__device__ int      g_wf2[9 * 64 * 8];         // mma B-frags [tap][oc][p]
__device__ int      g_wf3[9 * 2 * 128 * 8];    // [tap][chunk][oc][p]
__device__ uint4    g_dw2[2 * 8 * 9 * 4];      // dp4a w [z][k][tap][q]
__device__ uint4    g_dw3[4 * 16 * 9 * 4];     // [z][k][tap][q]
__device__ uint32_t g_gpart[32 * 4 * 32];      // gmax stage1 partials
__device__ uint8_t  g_c1[32L * 112 * 112 * 32];
__device__ uint8_t  g_c2[32L * 56 * 56 * 64];
__device__ uint8_t  g_c3[32L * 28 * 28 * 128];

// ---- helpers ---------------------------------------------------------------
__device__ __forceinline__ uint32_t smem_u32(const void* p) {
    uint32_t a;
    asm("{ .reg .u64 t; cvta.to.shared.u64 t, %1; cvt.u32.u64 %0, t; }"
        : "=r"(a) : "l"(p));
    return a;
}
__device__ __forceinline__ void ldsm4(uint32_t addr, int& a0, int& a1,
                                      int& a2, int& a3) {
    asm volatile("ldmatrix.sync.aligned.m8n8.x4.shared.b16 {%0,%1,%2,%3},[%4];"
                 : "=r"(a0), "=r"(a1), "=r"(a2), "=r"(a3) : "r"(addr));
}
__device__ __forceinline__ void mma_s8(int* d, int a0, int a1, int a2, int a3,
                                       int b0, int b1) {
    asm("mma.sync.aligned.m16n8k32.row.col.s32.s8.s8.s32 "
        "{%0,%1,%2,%3},{%4,%5,%6,%7},{%8,%9},{%0,%1,%2,%3};"
        : "+r"(d[0]), "+r"(d[1]), "+r"(d[2]), "+r"(d[3])
        : "r"(a0), "r"(a1), "r"(a2), "r"(a3), "r"(b0), "r"(b1));
}
#define PACK_F32X2(out, lo, hi) \
    asm("mov.b64 %0, {%1, %2};" : "=l"(out) : "r"(lo), "r"(hi))
#define UNPACK_F32X2(lo, hi, in) \
    asm("mov.b64 {%0, %1}, %2;" : "=f"(lo), "=f"(hi) : "l"(in))
#define FMA_F32X2(acc, a, b) \
    asm("fma.rn.f32x2 %0, %1, %2, %0;" : "+l"(acc) : "l"(a), "l"(b))

__device__ __forceinline__ float get_scale(int t) {
    return fmaxf(__uint_as_float(g_smax[t]), 1e-8f);
}

// block-wide (256 thr) max|w| reduction
__device__ __forceinline__ float blk_maxabs(const float* __restrict__ w, int n) {
    __shared__ float red[8];
    float m = 0.f;
    for (int i = threadIdx.x; i < n; i += 256)
        m = fmaxf(m, fabsf(w[i]));
    #pragma unroll
    for (int o = 16; o; o >>= 1)
        m = fmaxf(m, __shfl_xor_sync(0xffffffffu, m, o));
    if ((threadIdx.x & 31) == 0) red[threadIdx.x >> 5] = m;
    __syncthreads();
    float v = red[0];
    #pragma unroll
    for (int i = 1; i < 8; i++) v = fmaxf(v, red[i]);
    return fmaxf(v, 1e-8f);
}

// ---- prologue: per-block inline max|w| + quantize + pack --------------------
// dp4a tables: z = 32-channel group; dp covers oc z*32+16 .. z*32+31.
__global__ void pack_kernel(const float* __restrict__ w1,
                            const float* __restrict__ wc,
                            const float* __restrict__ w2,
                            const float* __restrict__ w3) {
    const int blk = blockIdx.x;
    if (blk == 0) {
        const float s = blk_maxabs(w1, 864);
        for (int i = threadIdx.x; i < 864; i += 256)
            g_qw1[i] = rintf(w1[i] / s) * s;
    } else if (blk == 1) {
        const float s = blk_maxabs(wc, 1280);
        for (int i = threadIdx.x; i < 1280; i += 256)
            g_qwc[i] = rintf(wc[i] / s) * s;
    } else if (blk == 2) {
        // mma frags conv2: word p: icw = (p>>1) + (p&1)*4
        const float s = blk_maxabs(w2, 64 * 32 * 9);
        if (threadIdx.x == 0) g_smax[2] = __float_as_uint(s);
        const float inv_s = 1.f / s;
        for (int i = threadIdx.x; i < 9 * 64 * 8; i += 256) {
            const int tap = i / 512, r = i % 512, oc = r >> 3, p = r & 7;
            const int icw = (p >> 1) + ((p & 1) << 2);
            uint32_t word = 0;
            #pragma unroll
            for (int l = 0; l < 4; l++) {
                const int ic = icw * 4 + l;
                const int c = (int)rintf(w2[(oc * 32 + ic) * 9 + tap] * inv_s);
                word |= ((uint32_t)(uint8_t)(int8_t)c) << (8 * l);
            }
            g_wf2[i] = (int)word;
        }
    } else if (blk == 3) {
        const float s = blk_maxabs(w3, 128 * 64 * 9);
        if (threadIdx.x == 0) g_smax[3] = __float_as_uint(s);
        const float inv_s = 1.f / s;
        for (int i = threadIdx.x; i < 9 * 2 * 128 * 8; i += 256) {
            const int tap = i / 2048, r = i % 2048;
            const int chunk = r >> 10, r2 = r & 1023, oc = r2 >> 3, p = r2 & 7;
            const int icw = (p >> 1) + ((p & 1) << 2);
            uint32_t word = 0;
            #pragma unroll
            for (int l = 0; l < 4; l++) {
                const int ic = chunk * 32 + (icw * 4) + l;
                const int c = (int)rintf(w3[(oc * 64 + ic) * 9 + tap] * inv_s);
                word |= ((uint32_t)(uint8_t)(int8_t)c) << (8 * l);
            }
            g_wf3[i] = (int)word;
        }
    } else if (blk == 4) {
        // dp4a conv2: [z][k][tap][q] uint4; oc = z*32+16+q*4+chl, ic = k*4+l
        const float inv_s = 1.f / blk_maxabs(w2, 64 * 32 * 9);
        uint32_t* dst = (uint32_t*)g_dw2;
        for (int i = threadIdx.x; i < 2 * 8 * 9 * 16; i += 256) {
            const int z = i / 1152, r = i % 1152;
            const int k = r / 144, r2 = r % 144;
            const int t = r2 / 16, q = (r2 % 16) >> 2, chl = i & 3;
            const int oc = z * 32 + 16 + q * 4 + chl;
            uint32_t word = 0;
            #pragma unroll
            for (int l = 0; l < 4; l++) {
                const int ic = k * 4 + l;
                const int c = (int)rintf(w2[(oc * 32 + ic) * 9 + t] * inv_s);
                word |= ((uint32_t)(uint8_t)(int8_t)c) << (8 * l);
            }
            dst[i] = word;
        }
    } else {
        // dp4a conv3: z in {0..3}
        const float inv_s = 1.f / blk_maxabs(w3, 128 * 64 * 9);
        uint32_t* dst = (uint32_t*)g_dw3;
        for (int i = threadIdx.x; i < 4 * 16 * 9 * 16; i += 256) {
            const int z = i / 2304, r = i % 2304;
            const int k = r / 144, r2 = r % 144;
            const int t = r2 / 16, q = (r2 % 16) >> 2, chl = i & 3;
            const int oc = z * 32 + 16 + q * 4 + chl;
            uint32_t word = 0;
            #pragma unroll
            for (int l = 0; l < 4; l++) {
                const int ic = k * 4 + l;
                const int c = (int)rintf(w3[(oc * 64 + ic) * 9 + t] * inv_s);
                word |= ((uint32_t)(uint8_t)(int8_t)c) << (8 * l);
            }
            dst[i] = word;
        }
    }
}

// ---- block 1: fp32 conv3x3(pad1) via fma.f32x2 + quant_act + maxpool2 -------
// 16 oc per CTA (tile loaded only twice); pk packed straight from smem.
__global__ __launch_bounds__(128) void conv1_kernel(
    const float* __restrict__ x, const float* __restrict__ alpha_p,
    uint8_t* __restrict__ out) {
    constexpr int H = 224, W = 224, PH = 112, PW = 112, OC = 32, OCB = 16;
    __shared__ float sx[3][18][34];
    __shared__ unsigned long long swp[OCB][3][9];   // (w,w) duplicated pairs

    const int tid = threadIdx.x;
    const int tx = tid & 15, ty = tid >> 4;
    const int tile_x = blockIdx.x;
    const int tile_y = blockIdx.y % 14;
    const int b      = blockIdx.y / 14;
    const int oc0    = blockIdx.z * OCB;

    const int px0 = tile_x * 16, py0 = tile_y * 8;
    const int ix0 = 2 * px0 - 1, iy0 = 2 * py0 - 1;

    const float* xb = x + (long)b * 3 * H * W;
    for (int i = tid; i < 3 * 18 * 34; i += 128) {
        const int ic = i / 612, rr = (i % 612) / 34, cc = i % 34;
        const int gy = iy0 + rr, gx = ix0 + cc;
        float v = 0.f;
        if (gy >= 0 && gy < H && gx >= 0 && gx < W)
            v = xb[(long)ic * H * W + gy * W + gx];
        sx[ic][rr][cc] = v;
    }
    for (int i = tid; i < OCB * 27; i += 128) {
        const int j = i / 27, r27 = i % 27;
        const float w = g_qw1[((oc0 + j) * 3 + r27 / 9) * 9 + r27 % 9];
        unsigned long long pw;
        PACK_F32X2(pw, __float_as_uint(w), __float_as_uint(w));
        swp[j][r27 / 9][r27 % 9] = pw;
    }
    __syncthreads();

    unsigned long long accA[OCB], accB[OCB];
    #pragma unroll
    for (int j = 0; j < OCB; j++) { accA[j] = 0ull; accB[j] = 0ull; }

    #pragma unroll
    for (int ic = 0; ic < 3; ic++) {
        unsigned long long pk[4][3];
        #pragma unroll
        for (int r = 0; r < 4; r++)
            #pragma unroll
            for (int c = 0; c < 3; c++)
                PACK_F32X2(pk[r][c],
                           __float_as_uint(sx[ic][2 * ty + r][2 * tx + c]),
                           __float_as_uint(sx[ic][2 * ty + r][2 * tx + c + 1]));
        #pragma unroll
        for (int j = 0; j < OCB; j++) {
            #pragma unroll
            for (int ky = 0; ky < 3; ky++)
                #pragma unroll
                for (int kx = 0; kx < 3; kx++) {
                    FMA_F32X2(accA[j], pk[ky][kx], swp[j][ic][ky * 3 + kx]);
                    FMA_F32X2(accB[j], pk[ky + 1][kx], swp[j][ic][ky * 3 + kx]);
                }
        }
    }

    const float alpha = __ldg(alpha_p);
    const float inv_scale = 3.f / alpha;
    const int px = px0 + tx, py = py0 + ty;
    uint32_t pw[4] = {0, 0, 0, 0};
    #pragma unroll
    for (int j = 0; j < OCB; j++) {
        float p0, p1, p2, p3;
        UNPACK_F32X2(p0, p1, accA[j]);
        UNPACK_F32X2(p2, p3, accB[j]);
        const float m = fmaxf(fmaxf(p0, p1), fmaxf(p2, p3));
        const float y = fminf(fmaxf(m, 0.f), alpha);
        const uint32_t code = (uint32_t)(int)rintf(y * inv_scale);
        pw[j >> 2] |= code << (8 * (j & 3));
    }
    *(uint4*)&out[(((long)b * PH + py) * PW + px) * OC + oc0]
        = make_uint4(pw[0], pw[1], pw[2], pw[3]);
}

// ---- blocks 2/3: fused hybrid, 32 channels/CTA (16 mma + 16 dp4a) -----------
// launch_bounds(256,4): 64 regs -> 4 CTAs/SM.  (unchanged from R11)
template <int H, int IC, int OC, int NOC, int MMAOC, int TW, int TH, int PSTRIDE>
__global__ __launch_bounds__(256, 4) void conv_hyb(
    const uint8_t* __restrict__ xin, const int* __restrict__ wf,
    const uint4* __restrict__ dw,
    const float* __restrict__ aprev_p, const float* __restrict__ acur_p,
    int wtensor, uint8_t* __restrict__ out) {
    constexpr int DPOC = NOC - MMAOC;          // 16
    constexpr int DQ   = DPOC / 4;             // 4
    constexpr int CH   = IC / 32;
    constexpr int IC4  = IC / 4;
    constexpr int IC16 = IC / 16;
    constexpr int TIW  = TW + 2, TIH = TH + 2;
    constexpr int OCG  = MMAOC / 8;            // 2
    constexpr int VPP  = IC / 16;
    constexpr int WTX  = TW / 8, WTY = TH / 2, NWT = WTX * WTY;
    constexpr int PHW  = H / 2;
    constexpr int DLANES = TW * (TH / 2);
    static_assert(DLANES <= 128, "dp lane budget");

    extern __shared__ __align__(16) uint8_t dsm[];
    uint8_t* stile = dsm;                                   // TIH*TIW*PSTRIDE
    uint4*   sdw   = (uint4*)(dsm + TIH * TIW * PSTRIDE);   // IC4*9*DQ uint4
    int*     swf   = (int*)(dsm + TIH * TIW * PSTRIDE + IC4 * 9 * DQ * 16);

    const int tid = threadIdx.x;
    const int tilesY = H / TH;
    const int by = blockIdx.y % tilesY;
    const int b  = blockIdx.y / tilesY;
    const int cx0 = blockIdx.x * TW, cy0 = by * TH;
    const int oc0 = blockIdx.z * NOC;

    for (int i = tid; i < 9 * CH * MMAOC * 8; i += 256) {
        const int p = i & 7, j = (i >> 3) % MMAOC, tc = (i >> 3) / MMAOC;
        swf[i] = wf[((tc * OC) + oc0 + j) * 8 + p];
    }
    {
        const uint4* dwz = dw + (long)blockIdx.z * (IC4 * 9 * DQ);
        for (int i = tid; i < IC4 * 9 * DQ; i += 256) sdw[i] = dwz[i];
    }
    for (int i = tid; i < TIH * TIW * VPP; i += 256) {
        const int v = i % VPP, pix = i / VPP;
        const int gx = cx0 - 1 + pix % TIW;
        const int gy = cy0 - 1 + pix / TIW;
        uint4 val = make_uint4(0, 0, 0, 0);
        if (gx >= 0 && gx < H && gy >= 0 && gy < H)
            val = *(const uint4*)(xin + (((long)b * H + gy) * H + gx) * IC + v * 16);
        *(uint4*)(stile + pix * PSTRIDE + v * 16) = val;
    }
    __syncthreads();

    const int warp = tid >> 5, lane = tid & 31;
    const float combined = (__ldg(aprev_p) * (1.f / 3.f)) * get_scale(wtensor);
    const float alpha = __ldg(acur_p);
    const float inv_scale = 3.f / alpha;

    if (warp < 4) {
        // ---------------- mma path (tensor pipe) ----------------
        const uint32_t sbase = smem_u32(stile);
        const int r = lane >> 2;
        for (int wt = warp; wt < NWT; wt += 4) {
            const int tx = wt % WTX, ty = wt / WTX;
            const int piy = ty * 2 + ((lane >> 3) & 1);
            const int pix = tx * 8 + (lane & 7);
            const uint32_t abase = sbase + (piy * TIW + pix) * PSTRIDE
                                 + ((lane >> 4) << 4);
            int acc[OCG][4];
            #pragma unroll
            for (int g = 0; g < OCG; g++)
                #pragma unroll
                for (int q = 0; q < 4; q++) acc[g][q] = 0;

            #pragma unroll
            for (int t = 0; t < 9; t++) {
                const int dy = t / 3, dx = t % 3;
                #pragma unroll
                for (int c = 0; c < CH; c++) {
                    int a0, a1, a2, a3;
                    ldsm4(abase + (dy * TIW + dx) * PSTRIDE + c * 32,
                          a0, a1, a2, a3);
                    #pragma unroll
                    for (int g = 0; g < OCG; g++) {
                        const uint2 bb = *(const uint2*)
                            &swf[(((t * CH + c) * MMAOC) + g * 8 + (lane >> 2)) * 8
                                 + 2 * (lane & 3)];
                        mma_s8(acc[g], a0, a1, a2, a3, (int)bb.x, (int)bb.y);
                    }
                }
            }
            #pragma unroll
            for (int g = 0; g < OCG; g++) {
                const int v0 = max(acc[g][0], acc[g][2]);
                const int v1 = max(acc[g][1], acc[g][3]);
                const int o0 = max(v0, __shfl_xor_sync(0xffffffffu, v0, 4));
                const int o1 = max(v1, __shfl_xor_sync(0xffffffffu, v1, 4));
                if (!(r & 1)) {
                    const int ppx = (cx0 >> 1) + tx * 4 + (r >> 1);
                    const int ppy = (cy0 >> 1) + ty;
                    const float f0 = fminf(fmaxf((float)o0 * combined, 0.f), alpha);
                    const float f1 = fminf(fmaxf((float)o1 * combined, 0.f), alpha);
                    const uint32_t c0 = (uint32_t)(int)rintf(f0 * inv_scale);
                    const uint32_t c1 = (uint32_t)(int)rintf(f1 * inv_scale);
                    const int oc = oc0 + g * 8 + (lane & 3) * 2;
                    *(uint16_t*)(out + (((long)b * PHW + ppy) * PHW + ppx) * OC + oc)
                        = (uint16_t)(c0 | (c1 << 8));
                }
            }
        }
    } else {
        // ---- dp4a path (fma pipe), rolling 2-row window, LDS.128 ----
        const int dt = tid - 128;              // 0..127
        const int cx = dt % TW, cyp = dt / TW;
        const bool active = dt < DLANES;
        const int dcyp = min(cyp, TH / 2 - 1);

        int acc[DPOC][2];
        #pragma unroll
        for (int j = 0; j < DPOC; j++) { acc[j][0] = 0; acc[j][1] = 0; }

        #pragma unroll 1
        for (int g4 = 0; g4 < IC16; g4++) {
            const uint8_t* tb = stile + ((2 * dcyp) * TIW + cx) * PSTRIDE
                              + g4 * 16;
            #pragma unroll
            for (int cc = 0; cc < 3; cc++) {
                const uint8_t* cp = tb + cc * PSTRIDE;
                uint4 r0 = *(const uint4*)(cp);
                uint4 r1 = *(const uint4*)(cp + TIW * PSTRIDE);
                #pragma unroll
                for (int dy = 0; dy < 3; dy++) {
                    const int t = dy * 3 + cc;
                    #pragma unroll
                    for (int kk = 0; kk < 4; kk++) {
                        const uint32_t a0 = ((const uint32_t*)&r0)[kk];
                        const uint32_t a1 = ((const uint32_t*)&r1)[kk];
                        const int k = g4 * 4 + kk;
                        #pragma unroll
                        for (int q = 0; q < DQ; q++) {
                            const uint4 w = sdw[(k * 9 + t) * DQ + q];
                            acc[q*4+0][0] = __dp4a((int)a0, (int)w.x, acc[q*4+0][0]);
                            acc[q*4+0][1] = __dp4a((int)a1, (int)w.x, acc[q*4+0][1]);
                            acc[q*4+1][0] = __dp4a((int)a0, (int)w.y, acc[q*4+1][0]);
                            acc[q*4+1][1] = __dp4a((int)a1, (int)w.y, acc[q*4+1][1]);
                            acc[q*4+2][0] = __dp4a((int)a0, (int)w.z, acc[q*4+2][0]);
                            acc[q*4+2][1] = __dp4a((int)a1, (int)w.z, acc[q*4+2][1]);
                            acc[q*4+3][0] = __dp4a((int)a0, (int)w.w, acc[q*4+3][0]);
                            acc[q*4+3][1] = __dp4a((int)a1, (int)w.w, acc[q*4+3][1]);
                        }
                    }
                    if (dy < 2) {
                        r0 = r1;
                        r1 = *(const uint4*)(cp + (dy + 2) * TIW * PSTRIDE);
                    }
                }
            }
        }

        uint32_t pw[DQ];
        #pragma unroll
        for (int q = 0; q < DQ; q++) pw[q] = 0;
        #pragma unroll
        for (int j = 0; j < DPOC; j++) {
            int v = max(acc[j][0], acc[j][1]);               // vertical pool
            v = max(v, __shfl_xor_sync(0xffffffffu, v, 1));  // horizontal pool
            const float f = fminf(fmaxf((float)v * combined, 0.f), alpha);
            const uint32_t code = (uint32_t)(int)rintf(f * inv_scale);
            pw[j >> 2] |= code << (8 * (j & 3));
        }
        if (active && !(cx & 1)) {
            const int ppx = (cx0 >> 1) + (cx >> 1);
            const int ppy = (cy0 >> 1) + cyp;
            uint8_t* o = out + (((long)b * PHW + ppy) * PHW + ppx) * OC
                       + oc0 + MMAOC;
            *(uint4*)o = make_uint4(pw[0], pw[1], pw[2], pw[3]);
        }
    }
}

// ---- global max, stage 1: partial max over 196 pixels -----------------------
__global__ void gmax_stage1(const uint8_t* __restrict__ h3) {
    __shared__ uint32_t sm[4][32];
    const int b = blockIdx.x, s = blockIdx.y;
    const int tid = threadIdx.x;
    const int w = tid >> 5, c4 = tid & 31;
    const uint32_t* p = (const uint32_t*)(h3 + (long)b * 784 * 128);
    uint32_t m = 0;
    for (int pix = s * 196 + w; pix < (s + 1) * 196; pix += 4)
        m = __vmaxu4(m, p[(long)pix * 32 + c4]);
    sm[w][c4] = m;
    __syncthreads();
    if (tid < 32)
        g_gpart[(b * 4 + s) * 32 + tid] =
            __vmaxu4(__vmaxu4(sm[0][tid], sm[1][tid]),
                     __vmaxu4(sm[2][tid], sm[3][tid]));
}

// ---- global max stage 2 + 1x1 quantized conv classifier ---------------------
__global__ void gmax_fc_kernel(const float* __restrict__ a3_p,
                               float* __restrict__ out) {
    __shared__ float gm[128];
    const int b = blockIdx.x;
    const int tid = threadIdx.x;
    if (tid < 32) {
        const uint32_t* gp = &g_gpart[b * 4 * 32];
        const uint32_t v = __vmaxu4(__vmaxu4(gp[tid], gp[32 + tid]),
                                    __vmaxu4(gp[64 + tid], gp[96 + tid]));
        const float sc = __ldg(a3_p) * (1.f / 3.f);
        gm[tid * 4 + 0] = (float)(v & 0xff) * sc;
        gm[tid * 4 + 1] = (float)((v >> 8) & 0xff) * sc;
        gm[tid * 4 + 2] = (float)((v >> 16) & 0xff) * sc;
        gm[tid * 4 + 3] = (float)(v >> 24) * sc;
    }
    __syncthreads();
    if (tid < 10) {
        float s = 0.f;
        #pragma unroll 8
        for (int k = 0; k < 128; k++)
            s = fmaf(gm[k], g_qwc[tid * 128 + k], s);
        out[b * 10 + tid] = s;
    }
}

// ---------------------------------------------------------------------------
extern "C" void kernel_launch(void* const* d_in, const int* in_sizes, int n_in,
                              void* d_out, int out_size) {
    const float* x  = (const float*)d_in[0];
    const float* w1 = (const float*)d_in[1];
    const float* w2 = (const float*)d_in[2];
    const float* w3 = (const float*)d_in[3];
    const float* wc = (const float*)d_in[4];
    const float* a1 = (const float*)d_in[5];
    const float* a2 = (const float*)d_in[6];
    const float* a3 = (const float*)d_in[7];

    int *wf2, *wf3;
    uint4 *dw2, *dw3;
    uint8_t *c1, *c2, *c3;
    cudaGetSymbolAddress((void**)&wf2, g_wf2);
    cudaGetSymbolAddress((void**)&wf3, g_wf3);
    cudaGetSymbolAddress((void**)&dw2, g_dw2);
    cudaGetSymbolAddress((void**)&dw3, g_dw3);
    cudaGetSymbolAddress((void**)&c1, g_c1);
    cudaGetSymbolAddress((void**)&c2, g_c2);
    cudaGetSymbolAddress((void**)&c3, g_c3);

    // conv2: 32 channels/CTA (16 mma + 16 dp), tile 16x16, z=2
    auto k2 = conv_hyb<112, 32, 64, 32, 16, 16, 16, 48>;
    constexpr int SM2 = 18 * 18 * 48 + 8 * 9 * 4 * 16 + 9 * 1 * 16 * 8 * 4;
    // conv3: 32 channels/CTA, tile 8x28, z=4
    auto k3 = conv_hyb<56, 64, 128, 32, 16, 8, 28, 80>;
    constexpr int SM3 = 30 * 10 * 80 + 16 * 9 * 4 * 16 + 9 * 2 * 16 * 8 * 4;
    cudaFuncSetAttribute(k2, cudaFuncAttributeMaxDynamicSharedMemorySize, SM2);
    cudaFuncSetAttribute(k3, cudaFuncAttributeMaxDynamicSharedMemorySize, SM3);

    // prologue: fused maxabs + quantize + pack (6 independent blocks)
    pack_kernel<<<6, 256>>>(w1, wc, w2, w3);

    // block 1: [32,3,224,224] -> codes [32,112,112,32]
    conv1_kernel<<<dim3(7, 14 * 32, 2), 128>>>(x, a1, c1);
    // block 2: -> codes [32,56,56,64]
    k2<<<dim3(7, 7 * 32, 2), 256, SM2>>>(c1, wf2, dw2, a1, a2, 2, c2);
    // block 3: -> codes [32,28,28,128]
    k3<<<dim3(7, 2 * 32, 4), 256, SM3>>>(c2, wf3, dw3, a2, a3, 3, c3);

    // global max + classifier (two-stage)
    gmax_stage1<<<dim3(32, 4), 128>>>(c3);
    gmax_fc_kernel<<<32, 128>>>(a3, (float*)d_out);
}

// round 13
// speedup vs baseline: 1.2898x; 1.0022x over previous
#include <cuda_runtime.h>
#include <cuda_bf16.h>
#include <stdint.h>
#include <math.h>

// ---------------------------------------------------------------------------
// 2-bit quantized CNN forward.
//  conv1: fp32 conv via packed fma.rn.f32x2 (16 oc/CTA)
//  conv2/conv3: fused hybrid int8 conv, 32 channels per CTA:
//    warps 0-3: mma.sync.m16n8k32.s8 (tensor pipe), 16 channels
//    warps 4-7: dp4a (fma pipe), 16 channels, rolling 2-row window
//  Exact integer math: conv = (sum code*wint) * (alpha_prev/3 * s_w).
// ---------------------------------------------------------------------------

__device__ unsigned g_smax[4];                 // maxabs bits: w1, wc, w2, w3
__device__ float    g_qw1[32 * 3 * 9];
__device__ float    g_qwc[10 * 128];
__device__ int      g_wf2[9 * 64 * 8];         // mma B-frags [tap][oc][p]
__device__ int      g_wf3[9 * 2 * 128 * 8];    // [tap][chunk][oc][p]
__device__ uint4    g_dw2[2 * 8 * 9 * 4];      // dp4a w [z][k][tap][q]
__device__ uint4    g_dw3[4 * 16 * 9 * 4];     // [z][k][tap][q]
__device__ uint32_t g_gpart[32 * 4 * 32];      // gmax stage1 partials
__device__ uint8_t  g_c1[32L * 112 * 112 * 32];
__device__ uint8_t  g_c2[32L * 56 * 56 * 64];
__device__ uint8_t  g_c3[32L * 28 * 28 * 128];

// ---- helpers ---------------------------------------------------------------
__device__ __forceinline__ uint32_t smem_u32(const void* p) {
    uint32_t a;
    asm("{ .reg .u64 t; cvta.to.shared.u64 t, %1; cvt.u32.u64 %0, t; }"
        : "=r"(a) : "l"(p));
    return a;
}
__device__ __forceinline__ void ldsm4(uint32_t addr, int& a0, int& a1,
                                      int& a2, int& a3) {
    asm volatile("ldmatrix.sync.aligned.m8n8.x4.shared.b16 {%0,%1,%2,%3},[%4];"
                 : "=r"(a0), "=r"(a1), "=r"(a2), "=r"(a3) : "r"(addr));
}
__device__ __forceinline__ void mma_s8(int* d, int a0, int a1, int a2, int a3,
                                       int b0, int b1) {
    asm("mma.sync.aligned.m16n8k32.row.col.s32.s8.s8.s32 "
        "{%0,%1,%2,%3},{%4,%5,%6,%7},{%8,%9},{%0,%1,%2,%3};"
        : "+r"(d[0]), "+r"(d[1]), "+r"(d[2]), "+r"(d[3])
        : "r"(a0), "r"(a1), "r"(a2), "r"(a3), "r"(b0), "r"(b1));
}
#define PACK_F32X2(out, lo, hi) \
    asm("mov.b64 %0, {%1, %2};" : "=l"(out) : "r"(lo), "r"(hi))
#define UNPACK_F32X2(lo, hi, in) \
    asm("mov.b64 {%0, %1}, %2;" : "=f"(lo), "=f"(hi) : "l"(in))
#define FMA_F32X2(acc, a, b) \
    asm("fma.rn.f32x2 %0, %1, %2, %0;" : "+l"(acc) : "l"(a), "l"(b))

__device__ __forceinline__ float get_scale(int t) {
    return fmaxf(__uint_as_float(g_smax[t]), 1e-8f);
}

// ---- prologue 1: max|w| (parallel, 22 blocks) -------------------------------
__global__ void maxabs_kernel(const float* __restrict__ w1,
                              const float* __restrict__ wc,
                              const float* __restrict__ w2,
                              const float* __restrict__ w3) {
    __shared__ float red[8];
    const int blk = blockIdx.x;
    int t, base, cnt;
    const float* p;
    if (blk == 0)      { t = 0; p = w1; base = 0; cnt = 864; }
    else if (blk == 1) { t = 1; p = wc; base = 0; cnt = 1280; }
    else if (blk < 6)  { t = 2; p = w2; base = (blk - 2) * 4608; cnt = 4608; }
    else               { t = 3; p = w3; base = (blk - 6) * 4608; cnt = 4608; }
    float m = 0.f;
    for (int i = threadIdx.x; i < cnt; i += 256)
        m = fmaxf(m, fabsf(p[base + i]));
    #pragma unroll
    for (int o = 16; o; o >>= 1)
        m = fmaxf(m, __shfl_xor_sync(0xffffffffu, m, o));
    if ((threadIdx.x & 31) == 0) red[threadIdx.x >> 5] = m;
    __syncthreads();
    if (threadIdx.x == 0) {
        float v = red[0];
        #pragma unroll
        for (int i = 1; i < 8; i++) v = fmaxf(v, red[i]);
        atomicMax(&g_smax[t], __float_as_uint(v));  // |w|>=0, bit-monotone
    }
}

// ---- prologue 2: quantize + pack (reads g_smax) -----------------------------
// dp4a tables: z = 32-channel group; dp covers oc z*32+16 .. z*32+31.
__global__ void pack_kernel(const float* __restrict__ w1,
                            const float* __restrict__ wc,
                            const float* __restrict__ w2,
                            const float* __restrict__ w3) {
    const int blk = blockIdx.x;
    if (blk == 0) {
        const float s = get_scale(0);
        for (int i = threadIdx.x; i < 864; i += 256)
            g_qw1[i] = rintf(w1[i] / s) * s;
    } else if (blk == 1) {
        const float s = get_scale(1);
        for (int i = threadIdx.x; i < 1280; i += 256)
            g_qwc[i] = rintf(wc[i] / s) * s;
    } else if (blk == 2) {
        // mma frags conv2: word p: icw = (p>>1) + (p&1)*4
        const float inv_s = 1.f / get_scale(2);
        for (int i = threadIdx.x; i < 9 * 64 * 8; i += 256) {
            const int tap = i / 512, r = i % 512, oc = r >> 3, p = r & 7;
            const int icw = (p >> 1) + ((p & 1) << 2);
            uint32_t word = 0;
            #pragma unroll
            for (int l = 0; l < 4; l++) {
                const int ic = icw * 4 + l;
                const int c = (int)rintf(w2[(oc * 32 + ic) * 9 + tap] * inv_s);
                word |= ((uint32_t)(uint8_t)(int8_t)c) << (8 * l);
            }
            g_wf2[i] = (int)word;
        }
    } else if (blk == 3) {
        const float inv_s = 1.f / get_scale(3);
        for (int i = threadIdx.x; i < 9 * 2 * 128 * 8; i += 256) {
            const int tap = i / 2048, r = i % 2048;
            const int chunk = r >> 10, r2 = r & 1023, oc = r2 >> 3, p = r2 & 7;
            const int icw = (p >> 1) + ((p & 1) << 2);
            uint32_t word = 0;
            #pragma unroll
            for (int l = 0; l < 4; l++) {
                const int ic = chunk * 32 + (icw * 4) + l;
                const int c = (int)rintf(w3[(oc * 64 + ic) * 9 + tap] * inv_s);
                word |= ((uint32_t)(uint8_t)(int8_t)c) << (8 * l);
            }
            g_wf3[i] = (int)word;
        }
    } else if (blk == 4) {
        // dp4a conv2: [z][k][tap][q] uint4; oc = z*32+16+q*4+chl, ic = k*4+l
        const float inv_s = 1.f / get_scale(2);
        uint32_t* dst = (uint32_t*)g_dw2;
        for (int i = threadIdx.x; i < 2 * 8 * 9 * 16; i += 256) {
            const int z = i / 1152, r = i % 1152;
            const int k = r / 144, r2 = r % 144;
            const int t = r2 / 16, q = (r2 % 16) >> 2, chl = i & 3;
            const int oc = z * 32 + 16 + q * 4 + chl;
            uint32_t word = 0;
            #pragma unroll
            for (int l = 0; l < 4; l++) {
                const int ic = k * 4 + l;
                const int c = (int)rintf(w2[(oc * 32 + ic) * 9 + t] * inv_s);
                word |= ((uint32_t)(uint8_t)(int8_t)c) << (8 * l);
            }
            dst[i] = word;
        }
    } else {
        // dp4a conv3: z in {0..3}
        const float inv_s = 1.f / get_scale(3);
        uint32_t* dst = (uint32_t*)g_dw3;
        for (int i = threadIdx.x; i < 4 * 16 * 9 * 16; i += 256) {
            const int z = i / 2304, r = i % 2304;
            const int k = r / 144, r2 = r % 144;
            const int t = r2 / 16, q = (r2 % 16) >> 2, chl = i & 3;
            const int oc = z * 32 + 16 + q * 4 + chl;
            uint32_t word = 0;
            #pragma unroll
            for (int l = 0; l < 4; l++) {
                const int ic = k * 4 + l;
                const int c = (int)rintf(w3[(oc * 64 + ic) * 9 + t] * inv_s);
                word |= ((uint32_t)(uint8_t)(int8_t)c) << (8 * l);
            }
            dst[i] = word;
        }
    }
}

// ---- block 1: fp32 conv3x3(pad1) via fma.f32x2 + quant_act + maxpool2 -------
// 16 oc per CTA (tile loaded only twice); pk packed straight from smem.
__global__ __launch_bounds__(128) void conv1_kernel(
    const float* __restrict__ x, const float* __restrict__ alpha_p,
    uint8_t* __restrict__ out) {
    constexpr int H = 224, W = 224, PH = 112, PW = 112, OC = 32, OCB = 16;
    __shared__ float sx[3][18][34];
    __shared__ unsigned long long swp[OCB][3][9];   // (w,w) duplicated pairs

    const int tid = threadIdx.x;
    const int tx = tid & 15, ty = tid >> 4;
    const int tile_x = blockIdx.x;
    const int tile_y = blockIdx.y % 14;
    const int b      = blockIdx.y / 14;
    const int oc0    = blockIdx.z * OCB;

    const int px0 = tile_x * 16, py0 = tile_y * 8;
    const int ix0 = 2 * px0 - 1, iy0 = 2 * py0 - 1;

    const float* xb = x + (long)b * 3 * H * W;
    for (int i = tid; i < 3 * 18 * 34; i += 128) {
        const int ic = i / 612, rr = (i % 612) / 34, cc = i % 34;
        const int gy = iy0 + rr, gx = ix0 + cc;
        float v = 0.f;
        if (gy >= 0 && gy < H && gx >= 0 && gx < W)
            v = xb[(long)ic * H * W + gy * W + gx];
        sx[ic][rr][cc] = v;
    }
    for (int i = tid; i < OCB * 27; i += 128) {
        const int j = i / 27, r27 = i % 27;
        const float w = g_qw1[((oc0 + j) * 3 + r27 / 9) * 9 + r27 % 9];
        unsigned long long pw;
        PACK_F32X2(pw, __float_as_uint(w), __float_as_uint(w));
        swp[j][r27 / 9][r27 % 9] = pw;
    }
    __syncthreads();

    unsigned long long accA[OCB], accB[OCB];
    #pragma unroll
    for (int j = 0; j < OCB; j++) { accA[j] = 0ull; accB[j] = 0ull; }

    #pragma unroll
    for (int ic = 0; ic < 3; ic++) {
        unsigned long long pk[4][3];
        #pragma unroll
        for (int r = 0; r < 4; r++)
            #pragma unroll
            for (int c = 0; c < 3; c++)
                PACK_F32X2(pk[r][c],
                           __float_as_uint(sx[ic][2 * ty + r][2 * tx + c]),
                           __float_as_uint(sx[ic][2 * ty + r][2 * tx + c + 1]));
        #pragma unroll
        for (int j = 0; j < OCB; j++) {
            #pragma unroll
            for (int ky = 0; ky < 3; ky++)
                #pragma unroll
                for (int kx = 0; kx < 3; kx++) {
                    FMA_F32X2(accA[j], pk[ky][kx], swp[j][ic][ky * 3 + kx]);
                    FMA_F32X2(accB[j], pk[ky + 1][kx], swp[j][ic][ky * 3 + kx]);
                }
        }
    }

    const float alpha = __ldg(alpha_p);
    const float inv_scale = 3.f / alpha;
    const int px = px0 + tx, py = py0 + ty;
    uint32_t pw[4] = {0, 0, 0, 0};
    #pragma unroll
    for (int j = 0; j < OCB; j++) {
        float p0, p1, p2, p3;
        UNPACK_F32X2(p0, p1, accA[j]);
        UNPACK_F32X2(p2, p3, accB[j]);
        const float m = fmaxf(fmaxf(p0, p1), fmaxf(p2, p3));
        const float y = fminf(fmaxf(m, 0.f), alpha);
        const uint32_t code = (uint32_t)(int)rintf(y * inv_scale);
        pw[j >> 2] |= code << (8 * (j & 3));
    }
    *(uint4*)&out[(((long)b * PH + py) * PW + px) * OC + oc0]
        = make_uint4(pw[0], pw[1], pw[2], pw[3]);
}

// ---- blocks 2/3: fused hybrid, 32 channels/CTA (16 mma + 16 dp4a) -----------
// launch_bounds(256,4): 64 regs -> 4 CTAs/SM.
template <int H, int IC, int OC, int NOC, int MMAOC, int TW, int TH, int PSTRIDE>
__global__ __launch_bounds__(256, 4) void conv_hyb(
    const uint8_t* __restrict__ xin, const int* __restrict__ wf,
    const uint4* __restrict__ dw,
    const float* __restrict__ aprev_p, const float* __restrict__ acur_p,
    int wtensor, uint8_t* __restrict__ out) {
    constexpr int DPOC = NOC - MMAOC;          // 16
    constexpr int DQ   = DPOC / 4;             // 4
    constexpr int CH   = IC / 32;
    constexpr int IC4  = IC / 4;
    constexpr int IC16 = IC / 16;
    constexpr int TIW  = TW + 2, TIH = TH + 2;
    constexpr int OCG  = MMAOC / 8;            // 2
    constexpr int VPP  = IC / 16;
    constexpr int WTX  = TW / 8, WTY = TH / 2, NWT = WTX * WTY;
    constexpr int PHW  = H / 2;
    constexpr int DLANES = TW * (TH / 2);
    static_assert(DLANES <= 128, "dp lane budget");

    extern __shared__ __align__(16) uint8_t dsm[];
    uint8_t* stile = dsm;                                   // TIH*TIW*PSTRIDE
    uint4*   sdw   = (uint4*)(dsm + TIH * TIW * PSTRIDE);   // IC4*9*DQ uint4
    int*     swf   = (int*)(dsm + TIH * TIW * PSTRIDE + IC4 * 9 * DQ * 16);

    const int tid = threadIdx.x;
    const int tilesY = H / TH;
    const int by = blockIdx.y % tilesY;
    const int b  = blockIdx.y / tilesY;
    const int cx0 = blockIdx.x * TW, cy0 = by * TH;
    const int oc0 = blockIdx.z * NOC;

    for (int i = tid; i < 9 * CH * MMAOC * 8; i += 256) {
        const int p = i & 7, j = (i >> 3) % MMAOC, tc = (i >> 3) / MMAOC;
        swf[i] = wf[((tc * OC) + oc0 + j) * 8 + p];
    }
    {
        const uint4* dwz = dw + (long)blockIdx.z * (IC4 * 9 * DQ);
        for (int i = tid; i < IC4 * 9 * DQ; i += 256) sdw[i] = dwz[i];
    }
    for (int i = tid; i < TIH * TIW * VPP; i += 256) {
        const int v = i % VPP, pix = i / VPP;
        const int gx = cx0 - 1 + pix % TIW;
        const int gy = cy0 - 1 + pix / TIW;
        uint4 val = make_uint4(0, 0, 0, 0);
        if (gx >= 0 && gx < H && gy >= 0 && gy < H)
            val = *(const uint4*)(xin + (((long)b * H + gy) * H + gx) * IC + v * 16);
        *(uint4*)(stile + pix * PSTRIDE + v * 16) = val;
    }
    __syncthreads();

    const int warp = tid >> 5, lane = tid & 31;
    const float combined = (__ldg(aprev_p) * (1.f / 3.f)) * get_scale(wtensor);
    const float alpha = __ldg(acur_p);
    const float inv_scale = 3.f / alpha;

    if (warp < 4) {
        // ---------------- mma path (tensor pipe) ----------------
        const uint32_t sbase = smem_u32(stile);
        const int r = lane >> 2;
        for (int wt = warp; wt < NWT; wt += 4) {
            const int tx = wt % WTX, ty = wt / WTX;
            const int piy = ty * 2 + ((lane >> 3) & 1);
            const int pix = tx * 8 + (lane & 7);
            const uint32_t abase = sbase + (piy * TIW + pix) * PSTRIDE
                                 + ((lane >> 4) << 4);
            int acc[OCG][4];
            #pragma unroll
            for (int g = 0; g < OCG; g++)
                #pragma unroll
                for (int q = 0; q < 4; q++) acc[g][q] = 0;

            #pragma unroll
            for (int t = 0; t < 9; t++) {
                const int dy = t / 3, dx = t % 3;
                #pragma unroll
                for (int c = 0; c < CH; c++) {
                    int a0, a1, a2, a3;
                    ldsm4(abase + (dy * TIW + dx) * PSTRIDE + c * 32,
                          a0, a1, a2, a3);
                    #pragma unroll
                    for (int g = 0; g < OCG; g++) {
                        const uint2 bb = *(const uint2*)
                            &swf[(((t * CH + c) * MMAOC) + g * 8 + (lane >> 2)) * 8
                                 + 2 * (lane & 3)];
                        mma_s8(acc[g], a0, a1, a2, a3, (int)bb.x, (int)bb.y);
                    }
                }
            }
            #pragma unroll
            for (int g = 0; g < OCG; g++) {
                const int v0 = max(acc[g][0], acc[g][2]);
                const int v1 = max(acc[g][1], acc[g][3]);
                const int o0 = max(v0, __shfl_xor_sync(0xffffffffu, v0, 4));
                const int o1 = max(v1, __shfl_xor_sync(0xffffffffu, v1, 4));
                if (!(r & 1)) {
                    const int ppx = (cx0 >> 1) + tx * 4 + (r >> 1);
                    const int ppy = (cy0 >> 1) + ty;
                    const float f0 = fminf(fmaxf((float)o0 * combined, 0.f), alpha);
                    const float f1 = fminf(fmaxf((float)o1 * combined, 0.f), alpha);
                    const uint32_t c0 = (uint32_t)(int)rintf(f0 * inv_scale);
                    const uint32_t c1 = (uint32_t)(int)rintf(f1 * inv_scale);
                    const int oc = oc0 + g * 8 + (lane & 3) * 2;
                    *(uint16_t*)(out + (((long)b * PHW + ppy) * PHW + ppx) * OC + oc)
                        = (uint16_t)(c0 | (c1 << 8));
                }
            }
        }
    } else {
        // ---- dp4a path (fma pipe), rolling 2-row window, LDS.128 ----
        const int dt = tid - 128;              // 0..127
        const int cx = dt % TW, cyp = dt / TW;
        const bool active = dt < DLANES;
        const int dcyp = min(cyp, TH / 2 - 1);

        int acc[DPOC][2];
        #pragma unroll
        for (int j = 0; j < DPOC; j++) { acc[j][0] = 0; acc[j][1] = 0; }

        #pragma unroll 1
        for (int g4 = 0; g4 < IC16; g4++) {
            const uint8_t* tb = stile + ((2 * dcyp) * TIW + cx) * PSTRIDE
                              + g4 * 16;
            #pragma unroll
            for (int cc = 0; cc < 3; cc++) {
                const uint8_t* cp = tb + cc * PSTRIDE;
                uint4 r0 = *(const uint4*)(cp);
                uint4 r1 = *(const uint4*)(cp + TIW * PSTRIDE);
                #pragma unroll
                for (int dy = 0; dy < 3; dy++) {
                    const int t = dy * 3 + cc;
                    #pragma unroll
                    for (int kk = 0; kk < 4; kk++) {
                        const uint32_t a0 = ((const uint32_t*)&r0)[kk];
                        const uint32_t a1 = ((const uint32_t*)&r1)[kk];
                        const int k = g4 * 4 + kk;
                        #pragma unroll
                        for (int q = 0; q < DQ; q++) {
                            const uint4 w = sdw[(k * 9 + t) * DQ + q];
                            acc[q*4+0][0] = __dp4a((int)a0, (int)w.x, acc[q*4+0][0]);
                            acc[q*4+0][1] = __dp4a((int)a1, (int)w.x, acc[q*4+0][1]);
                            acc[q*4+1][0] = __dp4a((int)a0, (int)w.y, acc[q*4+1][0]);
                            acc[q*4+1][1] = __dp4a((int)a1, (int)w.y, acc[q*4+1][1]);
                            acc[q*4+2][0] = __dp4a((int)a0, (int)w.z, acc[q*4+2][0]);
                            acc[q*4+2][1] = __dp4a((int)a1, (int)w.z, acc[q*4+2][1]);
                            acc[q*4+3][0] = __dp4a((int)a0, (int)w.w, acc[q*4+3][0]);
                            acc[q*4+3][1] = __dp4a((int)a1, (int)w.w, acc[q*4+3][1]);
                        }
                    }
                    if (dy < 2) {
                        r0 = r1;
                        r1 = *(const uint4*)(cp + (dy + 2) * TIW * PSTRIDE);
                    }
                }
            }
        }

        uint32_t pw[DQ];
        #pragma unroll
        for (int q = 0; q < DQ; q++) pw[q] = 0;
        #pragma unroll
        for (int j = 0; j < DPOC; j++) {
            int v = max(acc[j][0], acc[j][1]);               // vertical pool
            v = max(v, __shfl_xor_sync(0xffffffffu, v, 1));  // horizontal pool
            const float f = fminf(fmaxf((float)v * combined, 0.f), alpha);
            const uint32_t code = (uint32_t)(int)rintf(f * inv_scale);
            pw[j >> 2] |= code << (8 * (j & 3));
        }
        if (active && !(cx & 1)) {
            const int ppx = (cx0 >> 1) + (cx >> 1);
            const int ppy = (cy0 >> 1) + cyp;
            uint8_t* o = out + (((long)b * PHW + ppy) * PHW + ppx) * OC
                       + oc0 + MMAOC;
            *(uint4*)o = make_uint4(pw[0], pw[1], pw[2], pw[3]);
        }
    }
}

// ---- global max, stage 1: partial max over 196 pixels -----------------------
__global__ void gmax_stage1(const uint8_t* __restrict__ h3) {
    __shared__ uint32_t sm[4][32];
    const int b = blockIdx.x, s = blockIdx.y;
    const int tid = threadIdx.x;
    const int w = tid >> 5, c4 = tid & 31;
    const uint32_t* p = (const uint32_t*)(h3 + (long)b * 784 * 128);
    uint32_t m = 0;
    for (int pix = s * 196 + w; pix < (s + 1) * 196; pix += 4)
        m = __vmaxu4(m, p[(long)pix * 32 + c4]);
    sm[w][c4] = m;
    __syncthreads();
    if (tid < 32)
        g_gpart[(b * 4 + s) * 32 + tid] =
            __vmaxu4(__vmaxu4(sm[0][tid], sm[1][tid]),
                     __vmaxu4(sm[2][tid], sm[3][tid]));
}

// ---- global max stage 2 + 1x1 quantized conv classifier ---------------------
__global__ void gmax_fc_kernel(const float* __restrict__ a3_p,
                               float* __restrict__ out) {
    __shared__ float gm[128];
    const int b = blockIdx.x;
    const int tid = threadIdx.x;
    if (tid < 32) {
        const uint32_t* gp = &g_gpart[b * 4 * 32];
        const uint32_t v = __vmaxu4(__vmaxu4(gp[tid], gp[32 + tid]),
                                    __vmaxu4(gp[64 + tid], gp[96 + tid]));
        const float sc = __ldg(a3_p) * (1.f / 3.f);
        gm[tid * 4 + 0] = (float)(v & 0xff) * sc;
        gm[tid * 4 + 1] = (float)((v >> 8) & 0xff) * sc;
        gm[tid * 4 + 2] = (float)((v >> 16) & 0xff) * sc;
        gm[tid * 4 + 3] = (float)(v >> 24) * sc;
    }
    __syncthreads();
    if (tid < 10) {
        float s = 0.f;
        #pragma unroll 8
        for (int k = 0; k < 128; k++)
            s = fmaf(gm[k], g_qwc[tid * 128 + k], s);
        out[b * 10 + tid] = s;
    }
}

// ---------------------------------------------------------------------------
extern "C" void kernel_launch(void* const* d_in, const int* in_sizes, int n_in,
                              void* d_out, int out_size) {
    const float* x  = (const float*)d_in[0];
    const float* w1 = (const float*)d_in[1];
    const float* w2 = (const float*)d_in[2];
    const float* w3 = (const float*)d_in[3];
    const float* wc = (const float*)d_in[4];
    const float* a1 = (const float*)d_in[5];
    const float* a2 = (const float*)d_in[6];
    const float* a3 = (const float*)d_in[7];

    int *wf2, *wf3;
    uint4 *dw2, *dw3;
    uint8_t *c1, *c2, *c3;
    cudaGetSymbolAddress((void**)&wf2, g_wf2);
    cudaGetSymbolAddress((void**)&wf3, g_wf3);
    cudaGetSymbolAddress((void**)&dw2, g_dw2);
    cudaGetSymbolAddress((void**)&dw3, g_dw3);
    cudaGetSymbolAddress((void**)&c1, g_c1);
    cudaGetSymbolAddress((void**)&c2, g_c2);
    cudaGetSymbolAddress((void**)&c3, g_c3);

    // conv2: 32 channels/CTA (16 mma + 16 dp), tile 16x16, z=2
    auto k2 = conv_hyb<112, 32, 64, 32, 16, 16, 16, 48>;
    constexpr int SM2 = 18 * 18 * 48 + 8 * 9 * 4 * 16 + 9 * 1 * 16 * 8 * 4;
    // conv3: 32 channels/CTA, tile 8x28, z=4
    auto k3 = conv_hyb<56, 64, 128, 32, 16, 8, 28, 80>;
    constexpr int SM3 = 30 * 10 * 80 + 16 * 9 * 4 * 16 + 9 * 2 * 16 * 8 * 4;
    cudaFuncSetAttribute(k2, cudaFuncAttributeMaxDynamicSharedMemorySize, SM2);
    cudaFuncSetAttribute(k3, cudaFuncAttributeMaxDynamicSharedMemorySize, SM3);

    // prologue: parallel maxabs (22 blocks), then pack (6 blocks)
    maxabs_kernel<<<22, 256>>>(w1, wc, w2, w3);
    pack_kernel<<<6, 256>>>(w1, wc, w2, w3);

    // block 1: [32,3,224,224] -> codes [32,112,112,32]
    conv1_kernel<<<dim3(7, 14 * 32, 2), 128>>>(x, a1, c1);
    // block 2: -> codes [32,56,56,64]
    k2<<<dim3(7, 7 * 32, 2), 256, SM2>>>(c1, wf2, dw2, a1, a2, 2, c2);
    // block 3: -> codes [32,28,28,128]
    k3<<<dim3(7, 2 * 32, 4), 256, SM3>>>(c2, wf3, dw3, a2, a3, 3, c3);

    // global max + classifier (two-stage)
    gmax_stage1<<<dim3(32, 4), 128>>>(c3);
    gmax_fc_kernel<<<32, 128>>>(a3, (float*)d_out);
}

// round 14
// speedup vs baseline: 1.3151x; 1.0196x over previous
#include <cuda_runtime.h>
#include <cuda_bf16.h>
#include <stdint.h>
#include <math.h>

// ---------------------------------------------------------------------------
// 2-bit quantized CNN forward.
//  conv1: fp32 conv via packed fma.rn.f32x2, float2 smem loads (conflict-free)
//  conv2/conv3: fused hybrid int8 conv, 32 channels per CTA:
//    warps 0-3: mma.sync.m16n8k32.s8 (tensor pipe), 16 channels
//    warps 4-7: dp4a (fma pipe), 16 channels, rolling 2-row window
//  Exact integer math: conv = (sum code*wint) * (alpha_prev/3 * s_w).
// ---------------------------------------------------------------------------

__device__ unsigned g_smax[4];                 // maxabs bits: w1, wc, w2, w3
__device__ float    g_qw1[32 * 3 * 9];
__device__ float    g_qwc[10 * 128];
__device__ int      g_wf2[9 * 64 * 8];         // mma B-frags [tap][oc][p]
__device__ int      g_wf3[9 * 2 * 128 * 8];    // [tap][chunk][oc][p]
__device__ uint4    g_dw2[2 * 8 * 9 * 4];      // dp4a w [z][k][tap][q]
__device__ uint4    g_dw3[4 * 16 * 9 * 4];     // [z][k][tap][q]
__device__ uint32_t g_gpart[32 * 4 * 32];      // gmax stage1 partials
__device__ uint8_t  g_c1[32L * 112 * 112 * 32];
__device__ uint8_t  g_c2[32L * 56 * 56 * 64];
__device__ uint8_t  g_c3[32L * 28 * 28 * 128];

// ---- helpers ---------------------------------------------------------------
__device__ __forceinline__ uint32_t smem_u32(const void* p) {
    uint32_t a;
    asm("{ .reg .u64 t; cvta.to.shared.u64 t, %1; cvt.u32.u64 %0, t; }"
        : "=r"(a) : "l"(p));
    return a;
}
__device__ __forceinline__ void ldsm4(uint32_t addr, int& a0, int& a1,
                                      int& a2, int& a3) {
    asm volatile("ldmatrix.sync.aligned.m8n8.x4.shared.b16 {%0,%1,%2,%3},[%4];"
                 : "=r"(a0), "=r"(a1), "=r"(a2), "=r"(a3) : "r"(addr));
}
__device__ __forceinline__ void mma_s8(int* d, int a0, int a1, int a2, int a3,
                                       int b0, int b1) {
    asm("mma.sync.aligned.m16n8k32.row.col.s32.s8.s8.s32 "
        "{%0,%1,%2,%3},{%4,%5,%6,%7},{%8,%9},{%0,%1,%2,%3};"
        : "+r"(d[0]), "+r"(d[1]), "+r"(d[2]), "+r"(d[3])
        : "r"(a0), "r"(a1), "r"(a2), "r"(a3), "r"(b0), "r"(b1));
}
#define PACK_F32X2(out, lo, hi) \
    asm("mov.b64 %0, {%1, %2};" : "=l"(out) : "r"(lo), "r"(hi))
#define UNPACK_F32X2(lo, hi, in) \
    asm("mov.b64 {%0, %1}, %2;" : "=f"(lo), "=f"(hi) : "l"(in))
#define FMA_F32X2(acc, a, b) \
    asm("fma.rn.f32x2 %0, %1, %2, %0;" : "+l"(acc) : "l"(a), "l"(b))

__device__ __forceinline__ float get_scale(int t) {
    return fmaxf(__uint_as_float(g_smax[t]), 1e-8f);
}

// ---- prologue 1: max|w| (parallel, 22 blocks) -------------------------------
__global__ void maxabs_kernel(const float* __restrict__ w1,
                              const float* __restrict__ wc,
                              const float* __restrict__ w2,
                              const float* __restrict__ w3) {
    __shared__ float red[8];
    const int blk = blockIdx.x;
    int t, base, cnt;
    const float* p;
    if (blk == 0)      { t = 0; p = w1; base = 0; cnt = 864; }
    else if (blk == 1) { t = 1; p = wc; base = 0; cnt = 1280; }
    else if (blk < 6)  { t = 2; p = w2; base = (blk - 2) * 4608; cnt = 4608; }
    else               { t = 3; p = w3; base = (blk - 6) * 4608; cnt = 4608; }
    float m = 0.f;
    for (int i = threadIdx.x; i < cnt; i += 256)
        m = fmaxf(m, fabsf(p[base + i]));
    #pragma unroll
    for (int o = 16; o; o >>= 1)
        m = fmaxf(m, __shfl_xor_sync(0xffffffffu, m, o));
    if ((threadIdx.x & 31) == 0) red[threadIdx.x >> 5] = m;
    __syncthreads();
    if (threadIdx.x == 0) {
        float v = red[0];
        #pragma unroll
        for (int i = 1; i < 8; i++) v = fmaxf(v, red[i]);
        atomicMax(&g_smax[t], __float_as_uint(v));  // |w|>=0, bit-monotone
    }
}

// ---- prologue 2: quantize + pack (reads g_smax) -----------------------------
// dp4a tables: z = 32-channel group; dp covers oc z*32+16 .. z*32+31.
__global__ void pack_kernel(const float* __restrict__ w1,
                            const float* __restrict__ wc,
                            const float* __restrict__ w2,
                            const float* __restrict__ w3) {
    const int blk = blockIdx.x;
    if (blk == 0) {
        const float s = get_scale(0);
        for (int i = threadIdx.x; i < 864; i += 256)
            g_qw1[i] = rintf(w1[i] / s) * s;
    } else if (blk == 1) {
        const float s = get_scale(1);
        for (int i = threadIdx.x; i < 1280; i += 256)
            g_qwc[i] = rintf(wc[i] / s) * s;
    } else if (blk == 2) {
        // mma frags conv2: word p: icw = (p>>1) + (p&1)*4
        const float inv_s = 1.f / get_scale(2);
        for (int i = threadIdx.x; i < 9 * 64 * 8; i += 256) {
            const int tap = i / 512, r = i % 512, oc = r >> 3, p = r & 7;
            const int icw = (p >> 1) + ((p & 1) << 2);
            uint32_t word = 0;
            #pragma unroll
            for (int l = 0; l < 4; l++) {
                const int ic = icw * 4 + l;
                const int c = (int)rintf(w2[(oc * 32 + ic) * 9 + tap] * inv_s);
                word |= ((uint32_t)(uint8_t)(int8_t)c) << (8 * l);
            }
            g_wf2[i] = (int)word;
        }
    } else if (blk == 3) {
        const float inv_s = 1.f / get_scale(3);
        for (int i = threadIdx.x; i < 9 * 2 * 128 * 8; i += 256) {
            const int tap = i / 2048, r = i % 2048;
            const int chunk = r >> 10, r2 = r & 1023, oc = r2 >> 3, p = r2 & 7;
            const int icw = (p >> 1) + ((p & 1) << 2);
            uint32_t word = 0;
            #pragma unroll
            for (int l = 0; l < 4; l++) {
                const int ic = chunk * 32 + (icw * 4) + l;
                const int c = (int)rintf(w3[(oc * 64 + ic) * 9 + tap] * inv_s);
                word |= ((uint32_t)(uint8_t)(int8_t)c) << (8 * l);
            }
            g_wf3[i] = (int)word;
        }
    } else if (blk == 4) {
        // dp4a conv2: [z][k][tap][q] uint4; oc = z*32+16+q*4+chl, ic = k*4+l
        const float inv_s = 1.f / get_scale(2);
        uint32_t* dst = (uint32_t*)g_dw2;
        for (int i = threadIdx.x; i < 2 * 8 * 9 * 16; i += 256) {
            const int z = i / 1152, r = i % 1152;
            const int k = r / 144, r2 = r % 144;
            const int t = r2 / 16, q = (r2 % 16) >> 2, chl = i & 3;
            const int oc = z * 32 + 16 + q * 4 + chl;
            uint32_t word = 0;
            #pragma unroll
            for (int l = 0; l < 4; l++) {
                const int ic = k * 4 + l;
                const int c = (int)rintf(w2[(oc * 32 + ic) * 9 + t] * inv_s);
                word |= ((uint32_t)(uint8_t)(int8_t)c) << (8 * l);
            }
            dst[i] = word;
        }
    } else {
        // dp4a conv3: z in {0..3}
        const float inv_s = 1.f / get_scale(3);
        uint32_t* dst = (uint32_t*)g_dw3;
        for (int i = threadIdx.x; i < 4 * 16 * 9 * 16; i += 256) {
            const int z = i / 2304, r = i % 2304;
            const int k = r / 144, r2 = r % 144;
            const int t = r2 / 16, q = (r2 % 16) >> 2, chl = i & 3;
            const int oc = z * 32 + 16 + q * 4 + chl;
            uint32_t word = 0;
            #pragma unroll
            for (int l = 0; l < 4; l++) {
                const int ic = k * 4 + l;
                const int c = (int)rintf(w3[(oc * 64 + ic) * 9 + t] * inv_s);
                word |= ((uint32_t)(uint8_t)(int8_t)c) << (8 * l);
            }
            dst[i] = word;
        }
    }
}

// ---- block 1: fp32 conv3x3(pad1) via fma.f32x2 + quant_act + maxpool2 -------
// 256 threads, 16x16 pooled tile, OCB=8.  Padded smem rows (36 floats):
// each thread's 4-wide window = 2 conflict-free LDS.64; the two float2s ARE
// pk[0]/pk[2], pk[1] = one mov.  Per-position FMA chain order unchanged.
__global__ __launch_bounds__(256, 3) void conv1_kernel(
    const float* __restrict__ x, const float* __restrict__ alpha_p,
    uint8_t* __restrict__ out) {
    constexpr int H = 224, W = 224, PH = 112, PW = 112, OC = 32, OCB = 8;
    __shared__ float sx[3][34][36];
    __shared__ unsigned long long swp[OCB][3][9];   // (w,w) duplicated pairs

    const int tid = threadIdx.x;
    const int tx = tid & 15, ty = tid >> 4;          // 16x16 pooled tile
    const int tile_x = blockIdx.x;                   // 0..6
    const int tile_y = blockIdx.y % 7;
    const int b      = blockIdx.y / 7;
    const int oc0    = blockIdx.z * OCB;

    const int px0 = tile_x * 16, py0 = tile_y * 16;
    const int ix0 = 2 * px0 - 1, iy0 = 2 * py0 - 1;

    const float* xb = x + (long)b * 3 * H * W;
    for (int i = tid; i < 3 * 34 * 34; i += 256) {
        const int ic = i / 1156, rr = (i % 1156) / 34, cc = i % 34;
        const int gy = iy0 + rr, gx = ix0 + cc;
        float v = 0.f;
        if (gy >= 0 && gy < H && gx >= 0 && gx < W)
            v = xb[(long)ic * H * W + gy * W + gx];
        sx[ic][rr][cc] = v;
    }
    if (tid < OCB * 27) {
        const int j = tid / 27, r27 = tid % 27;
        const float w = g_qw1[((oc0 + j) * 3 + r27 / 9) * 9 + r27 % 9];
        unsigned long long pw;
        PACK_F32X2(pw, __float_as_uint(w), __float_as_uint(w));
        swp[j][r27 / 9][r27 % 9] = pw;
    }
    __syncthreads();

    unsigned long long accA[OCB], accB[OCB];
    #pragma unroll
    for (int j = 0; j < OCB; j++) { accA[j] = 0ull; accB[j] = 0ull; }

    #pragma unroll
    for (int ic = 0; ic < 3; ic++) {
        unsigned long long pk[4][3];
        #pragma unroll
        for (int r = 0; r < 4; r++) {
            const float2* row = (const float2*)&sx[ic][2 * ty + r][2 * tx];
            const float2 A = row[0], B = row[1];     // LDS.64 x2, no conflicts
            pk[r][0] = *(const unsigned long long*)&A;
            pk[r][2] = *(const unsigned long long*)&B;
            PACK_F32X2(pk[r][1], __float_as_uint(A.y), __float_as_uint(B.x));
        }
        #pragma unroll
        for (int j = 0; j < OCB; j++) {
            #pragma unroll
            for (int ky = 0; ky < 3; ky++)
                #pragma unroll
                for (int kx = 0; kx < 3; kx++) {
                    FMA_F32X2(accA[j], pk[ky][kx], swp[j][ic][ky * 3 + kx]);
                    FMA_F32X2(accB[j], pk[ky + 1][kx], swp[j][ic][ky * 3 + kx]);
                }
        }
    }

    const float alpha = __ldg(alpha_p);
    const float inv_scale = 3.f / alpha;
    const int px = px0 + tx, py = py0 + ty;
    uint32_t lo = 0, hi = 0;
    #pragma unroll
    for (int j = 0; j < OCB; j++) {
        float p0, p1, p2, p3;
        UNPACK_F32X2(p0, p1, accA[j]);
        UNPACK_F32X2(p2, p3, accB[j]);
        const float m = fmaxf(fmaxf(p0, p1), fmaxf(p2, p3));
        const float y = fminf(fmaxf(m, 0.f), alpha);
        const uint32_t code = (uint32_t)(int)rintf(y * inv_scale);
        if (j < 4) lo |= code << (8 * j);
        else       hi |= code << (8 * (j - 4));
    }
    *(uint2*)&out[(((long)b * PH + py) * PW + px) * OC + oc0] = make_uint2(lo, hi);
}

// ---- blocks 2/3: fused hybrid, 32 channels/CTA (16 mma + 16 dp4a) -----------
// launch_bounds(256,4): 64 regs -> 4 CTAs/SM.  (frozen from R11)
template <int H, int IC, int OC, int NOC, int MMAOC, int TW, int TH, int PSTRIDE>
__global__ __launch_bounds__(256, 4) void conv_hyb(
    const uint8_t* __restrict__ xin, const int* __restrict__ wf,
    const uint4* __restrict__ dw,
    const float* __restrict__ aprev_p, const float* __restrict__ acur_p,
    int wtensor, uint8_t* __restrict__ out) {
    constexpr int DPOC = NOC - MMAOC;          // 16
    constexpr int DQ   = DPOC / 4;             // 4
    constexpr int CH   = IC / 32;
    constexpr int IC4  = IC / 4;
    constexpr int IC16 = IC / 16;
    constexpr int TIW  = TW + 2, TIH = TH + 2;
    constexpr int OCG  = MMAOC / 8;            // 2
    constexpr int VPP  = IC / 16;
    constexpr int WTX  = TW / 8, WTY = TH / 2, NWT = WTX * WTY;
    constexpr int PHW  = H / 2;
    constexpr int DLANES = TW * (TH / 2);
    static_assert(DLANES <= 128, "dp lane budget");

    extern __shared__ __align__(16) uint8_t dsm[];
    uint8_t* stile = dsm;                                   // TIH*TIW*PSTRIDE
    uint4*   sdw   = (uint4*)(dsm + TIH * TIW * PSTRIDE);   // IC4*9*DQ uint4
    int*     swf   = (int*)(dsm + TIH * TIW * PSTRIDE + IC4 * 9 * DQ * 16);

    const int tid = threadIdx.x;
    const int tilesY = H / TH;
    const int by = blockIdx.y % tilesY;
    const int b  = blockIdx.y / tilesY;
    const int cx0 = blockIdx.x * TW, cy0 = by * TH;
    const int oc0 = blockIdx.z * NOC;

    for (int i = tid; i < 9 * CH * MMAOC * 8; i += 256) {
        const int p = i & 7, j = (i >> 3) % MMAOC, tc = (i >> 3) / MMAOC;
        swf[i] = wf[((tc * OC) + oc0 + j) * 8 + p];
    }
    {
        const uint4* dwz = dw + (long)blockIdx.z * (IC4 * 9 * DQ);
        for (int i = tid; i < IC4 * 9 * DQ; i += 256) sdw[i] = dwz[i];
    }
    for (int i = tid; i < TIH * TIW * VPP; i += 256) {
        const int v = i % VPP, pix = i / VPP;
        const int gx = cx0 - 1 + pix % TIW;
        const int gy = cy0 - 1 + pix / TIW;
        uint4 val = make_uint4(0, 0, 0, 0);
        if (gx >= 0 && gx < H && gy >= 0 && gy < H)
            val = *(const uint4*)(xin + (((long)b * H + gy) * H + gx) * IC + v * 16);
        *(uint4*)(stile + pix * PSTRIDE + v * 16) = val;
    }
    __syncthreads();

    const int warp = tid >> 5, lane = tid & 31;
    const float combined = (__ldg(aprev_p) * (1.f / 3.f)) * get_scale(wtensor);
    const float alpha = __ldg(acur_p);
    const float inv_scale = 3.f / alpha;

    if (warp < 4) {
        // ---------------- mma path (tensor pipe) ----------------
        const uint32_t sbase = smem_u32(stile);
        const int r = lane >> 2;
        for (int wt = warp; wt < NWT; wt += 4) {
            const int tx = wt % WTX, ty = wt / WTX;
            const int piy = ty * 2 + ((lane >> 3) & 1);
            const int pix = tx * 8 + (lane & 7);
            const uint32_t abase = sbase + (piy * TIW + pix) * PSTRIDE
                                 + ((lane >> 4) << 4);
            int acc[OCG][4];
            #pragma unroll
            for (int g = 0; g < OCG; g++)
                #pragma unroll
                for (int q = 0; q < 4; q++) acc[g][q] = 0;

            #pragma unroll
            for (int t = 0; t < 9; t++) {
                const int dy = t / 3, dx = t % 3;
                #pragma unroll
                for (int c = 0; c < CH; c++) {
                    int a0, a1, a2, a3;
                    ldsm4(abase + (dy * TIW + dx) * PSTRIDE + c * 32,
                          a0, a1, a2, a3);
                    #pragma unroll
                    for (int g = 0; g < OCG; g++) {
                        const uint2 bb = *(const uint2*)
                            &swf[(((t * CH + c) * MMAOC) + g * 8 + (lane >> 2)) * 8
                                 + 2 * (lane & 3)];
                        mma_s8(acc[g], a0, a1, a2, a3, (int)bb.x, (int)bb.y);
                    }
                }
            }
            #pragma unroll
            for (int g = 0; g < OCG; g++) {
                const int v0 = max(acc[g][0], acc[g][2]);
                const int v1 = max(acc[g][1], acc[g][3]);
                const int o0 = max(v0, __shfl_xor_sync(0xffffffffu, v0, 4));
                const int o1 = max(v1, __shfl_xor_sync(0xffffffffu, v1, 4));
                if (!(r & 1)) {
                    const int ppx = (cx0 >> 1) + tx * 4 + (r >> 1);
                    const int ppy = (cy0 >> 1) + ty;
                    const float f0 = fminf(fmaxf((float)o0 * combined, 0.f), alpha);
                    const float f1 = fminf(fmaxf((float)o1 * combined, 0.f), alpha);
                    const uint32_t c0 = (uint32_t)(int)rintf(f0 * inv_scale);
                    const uint32_t c1 = (uint32_t)(int)rintf(f1 * inv_scale);
                    const int oc = oc0 + g * 8 + (lane & 3) * 2;
                    *(uint16_t*)(out + (((long)b * PHW + ppy) * PHW + ppx) * OC + oc)
                        = (uint16_t)(c0 | (c1 << 8));
                }
            }
        }
    } else {
        // ---- dp4a path (fma pipe), rolling 2-row window, LDS.128 ----
        const int dt = tid - 128;              // 0..127
        const int cx = dt % TW, cyp = dt / TW;
        const bool active = dt < DLANES;
        const int dcyp = min(cyp, TH / 2 - 1);

        int acc[DPOC][2];
        #pragma unroll
        for (int j = 0; j < DPOC; j++) { acc[j][0] = 0; acc[j][1] = 0; }

        #pragma unroll 1
        for (int g4 = 0; g4 < IC16; g4++) {
            const uint8_t* tb = stile + ((2 * dcyp) * TIW + cx) * PSTRIDE
                              + g4 * 16;
            #pragma unroll
            for (int cc = 0; cc < 3; cc++) {
                const uint8_t* cp = tb + cc * PSTRIDE;
                uint4 r0 = *(const uint4*)(cp);
                uint4 r1 = *(const uint4*)(cp + TIW * PSTRIDE);
                #pragma unroll
                for (int dy = 0; dy < 3; dy++) {
                    const int t = dy * 3 + cc;
                    #pragma unroll
                    for (int kk = 0; kk < 4; kk++) {
                        const uint32_t a0 = ((const uint32_t*)&r0)[kk];
                        const uint32_t a1 = ((const uint32_t*)&r1)[kk];
                        const int k = g4 * 4 + kk;
                        #pragma unroll
                        for (int q = 0; q < DQ; q++) {
                            const uint4 w = sdw[(k * 9 + t) * DQ + q];
                            acc[q*4+0][0] = __dp4a((int)a0, (int)w.x, acc[q*4+0][0]);
                            acc[q*4+0][1] = __dp4a((int)a1, (int)w.x, acc[q*4+0][1]);
                            acc[q*4+1][0] = __dp4a((int)a0, (int)w.y, acc[q*4+1][0]);
                            acc[q*4+1][1] = __dp4a((int)a1, (int)w.y, acc[q*4+1][1]);
                            acc[q*4+2][0] = __dp4a((int)a0, (int)w.z, acc[q*4+2][0]);
                            acc[q*4+2][1] = __dp4a((int)a1, (int)w.z, acc[q*4+2][1]);
                            acc[q*4+3][0] = __dp4a((int)a0, (int)w.w, acc[q*4+3][0]);
                            acc[q*4+3][1] = __dp4a((int)a1, (int)w.w, acc[q*4+3][1]);
                        }
                    }
                    if (dy < 2) {
                        r0 = r1;
                        r1 = *(const uint4*)(cp + (dy + 2) * TIW * PSTRIDE);
                    }
                }
            }
        }

        uint32_t pw[DQ];
        #pragma unroll
        for (int q = 0; q < DQ; q++) pw[q] = 0;
        #pragma unroll
        for (int j = 0; j < DPOC; j++) {
            int v = max(acc[j][0], acc[j][1]);               // vertical pool
            v = max(v, __shfl_xor_sync(0xffffffffu, v, 1));  // horizontal pool
            const float f = fminf(fmaxf((float)v * combined, 0.f), alpha);
            const uint32_t code = (uint32_t)(int)rintf(f * inv_scale);
            pw[j >> 2] |= code << (8 * (j & 3));
        }
        if (active && !(cx & 1)) {
            const int ppx = (cx0 >> 1) + (cx >> 1);
            const int ppy = (cy0 >> 1) + cyp;
            uint8_t* o = out + (((long)b * PHW + ppy) * PHW + ppx) * OC
                       + oc0 + MMAOC;
            *(uint4*)o = make_uint4(pw[0], pw[1], pw[2], pw[3]);
        }
    }
}

// ---- global max, stage 1: partial max over 196 pixels -----------------------
__global__ void gmax_stage1(const uint8_t* __restrict__ h3) {
    __shared__ uint32_t sm[4][32];
    const int b = blockIdx.x, s = blockIdx.y;
    const int tid = threadIdx.x;
    const int w = tid >> 5, c4 = tid & 31;
    const uint32_t* p = (const uint32_t*)(h3 + (long)b * 784 * 128);
    uint32_t m = 0;
    for (int pix = s * 196 + w; pix < (s + 1) * 196; pix += 4)
        m = __vmaxu4(m, p[(long)pix * 32 + c4]);
    sm[w][c4] = m;
    __syncthreads();
    if (tid < 32)
        g_gpart[(b * 4 + s) * 32 + tid] =
            __vmaxu4(__vmaxu4(sm[0][tid], sm[1][tid]),
                     __vmaxu4(sm[2][tid], sm[3][tid]));
}

// ---- global max stage 2 + 1x1 quantized conv classifier ---------------------
__global__ void gmax_fc_kernel(const float* __restrict__ a3_p,
                               float* __restrict__ out) {
    __shared__ float gm[128];
    const int b = blockIdx.x;
    const int tid = threadIdx.x;
    if (tid < 32) {
        const uint32_t* gp = &g_gpart[b * 4 * 32];
        const uint32_t v = __vmaxu4(__vmaxu4(gp[tid], gp[32 + tid]),
                                    __vmaxu4(gp[64 + tid], gp[96 + tid]));
        const float sc = __ldg(a3_p) * (1.f / 3.f);
        gm[tid * 4 + 0] = (float)(v & 0xff) * sc;
        gm[tid * 4 + 1] = (float)((v >> 8) & 0xff) * sc;
        gm[tid * 4 + 2] = (float)((v >> 16) & 0xff) * sc;
        gm[tid * 4 + 3] = (float)(v >> 24) * sc;
    }
    __syncthreads();
    if (tid < 10) {
        float s = 0.f;
        #pragma unroll 8
        for (int k = 0; k < 128; k++)
            s = fmaf(gm[k], g_qwc[tid * 128 + k], s);
        out[b * 10 + tid] = s;
    }
}

// ---------------------------------------------------------------------------
extern "C" void kernel_launch(void* const* d_in, const int* in_sizes, int n_in,
                              void* d_out, int out_size) {
    const float* x  = (const float*)d_in[0];
    const float* w1 = (const float*)d_in[1];
    const float* w2 = (const float*)d_in[2];
    const float* w3 = (const float*)d_in[3];
    const float* wc = (const float*)d_in[4];
    const float* a1 = (const float*)d_in[5];
    const float* a2 = (const float*)d_in[6];
    const float* a3 = (const float*)d_in[7];

    int *wf2, *wf3;
    uint4 *dw2, *dw3;
    uint8_t *c1, *c2, *c3;
    cudaGetSymbolAddress((void**)&wf2, g_wf2);
    cudaGetSymbolAddress((void**)&wf3, g_wf3);
    cudaGetSymbolAddress((void**)&dw2, g_dw2);
    cudaGetSymbolAddress((void**)&dw3, g_dw3);
    cudaGetSymbolAddress((void**)&c1, g_c1);
    cudaGetSymbolAddress((void**)&c2, g_c2);
    cudaGetSymbolAddress((void**)&c3, g_c3);

    // conv2: 32 channels/CTA (16 mma + 16 dp), tile 16x16, z=2
    auto k2 = conv_hyb<112, 32, 64, 32, 16, 16, 16, 48>;
    constexpr int SM2 = 18 * 18 * 48 + 8 * 9 * 4 * 16 + 9 * 1 * 16 * 8 * 4;
    // conv3: 32 channels/CTA, tile 8x28, z=4
    auto k3 = conv_hyb<56, 64, 128, 32, 16, 8, 28, 80>;
    constexpr int SM3 = 30 * 10 * 80 + 16 * 9 * 4 * 16 + 9 * 2 * 16 * 8 * 4;
    cudaFuncSetAttribute(k2, cudaFuncAttributeMaxDynamicSharedMemorySize, SM2);
    cudaFuncSetAttribute(k3, cudaFuncAttributeMaxDynamicSharedMemorySize, SM3);

    // prologue: parallel maxabs (22 blocks), then pack (6 blocks)
    maxabs_kernel<<<22, 256>>>(w1, wc, w2, w3);
    pack_kernel<<<6, 256>>>(w1, wc, w2, w3);

    // block 1: [32,3,224,224] -> codes [32,112,112,32]
    conv1_kernel<<<dim3(7, 7 * 32, 4), 256>>>(x, a1, c1);
    // block 2: -> codes [32,56,56,64]
    k2<<<dim3(7, 7 * 32, 2), 256, SM2>>>(c1, wf2, dw2, a1, a2, 2, c2);
    // block 3: -> codes [32,28,28,128]
    k3<<<dim3(7, 2 * 32, 4), 256, SM3>>>(c2, wf3, dw3, a2, a3, 3, c3);

    // global max + classifier (two-stage)
    gmax_stage1<<<dim3(32, 4), 128>>>(c3);
    gmax_fc_kernel<<<32, 128>>>(a3, (float*)d_out);
}

// round 15
// speedup vs baseline: 1.3396x; 1.0186x over previous
#include <cuda_runtime.h>
#include <cuda_bf16.h>
#include <stdint.h>
#include <math.h>

// ---------------------------------------------------------------------------
// 2-bit quantized CNN forward.
//  conv1: fp32 conv via packed fma.rn.f32x2, float2 smem loads (conflict-free)
//  conv2/conv3: fused hybrid int8 conv, 32 channels per CTA:
//    warps 0-3: mma.sync.m16n8k32.s8 (tensor pipe), 16 channels
//    warps 4-7: dp4a (fma pipe), 16 channels, rolling 2-row window
//  Prologue for conv2/3 weights overlapped with conv1 on a side stream.
//  Exact integer math: conv = (sum code*wint) * (alpha_prev/3 * s_w).
// ---------------------------------------------------------------------------

__device__ unsigned g_smax[4];                 // maxabs bits: w1, wc, w2, w3
__device__ float    g_qw1[32 * 3 * 9];
__device__ float    g_qwc[10 * 128];
__device__ int      g_wf2[9 * 64 * 8];         // mma B-frags [tap][oc][p]
__device__ int      g_wf3[9 * 2 * 128 * 8];    // [tap][chunk][oc][p]
__device__ uint4    g_dw2[2 * 8 * 9 * 4];      // dp4a w [z][k][tap][q]
__device__ uint4    g_dw3[4 * 16 * 9 * 4];     // [z][k][tap][q]
__device__ uint32_t g_gpart[32 * 4 * 32];      // gmax stage1 partials
__device__ uint8_t  g_c1[32L * 112 * 112 * 32];
__device__ uint8_t  g_c2[32L * 56 * 56 * 64];
__device__ uint8_t  g_c3[32L * 28 * 28 * 128];

// ---- helpers ---------------------------------------------------------------
__device__ __forceinline__ uint32_t smem_u32(const void* p) {
    uint32_t a;
    asm("{ .reg .u64 t; cvta.to.shared.u64 t, %1; cvt.u32.u64 %0, t; }"
        : "=r"(a) : "l"(p));
    return a;
}
__device__ __forceinline__ void ldsm4(uint32_t addr, int& a0, int& a1,
                                      int& a2, int& a3) {
    asm volatile("ldmatrix.sync.aligned.m8n8.x4.shared.b16 {%0,%1,%2,%3},[%4];"
                 : "=r"(a0), "=r"(a1), "=r"(a2), "=r"(a3) : "r"(addr));
}
__device__ __forceinline__ void mma_s8(int* d, int a0, int a1, int a2, int a3,
                                       int b0, int b1) {
    asm("mma.sync.aligned.m16n8k32.row.col.s32.s8.s8.s32 "
        "{%0,%1,%2,%3},{%4,%5,%6,%7},{%8,%9},{%0,%1,%2,%3};"
        : "+r"(d[0]), "+r"(d[1]), "+r"(d[2]), "+r"(d[3])
        : "r"(a0), "r"(a1), "r"(a2), "r"(a3), "r"(b0), "r"(b1));
}
#define PACK_F32X2(out, lo, hi) \
    asm("mov.b64 %0, {%1, %2};" : "=l"(out) : "r"(lo), "r"(hi))
#define UNPACK_F32X2(lo, hi, in) \
    asm("mov.b64 {%0, %1}, %2;" : "=f"(lo), "=f"(hi) : "l"(in))
#define FMA_F32X2(acc, a, b) \
    asm("fma.rn.f32x2 %0, %1, %2, %0;" : "+l"(acc) : "l"(a), "l"(b))

__device__ __forceinline__ float get_scale(int t) {
    return fmaxf(__uint_as_float(g_smax[t]), 1e-8f);
}

// block-wide (256 thr) max|w| reduction
__device__ __forceinline__ float blk_maxabs(const float* __restrict__ w, int n) {
    __shared__ float red[8];
    float m = 0.f;
    for (int i = threadIdx.x; i < n; i += 256)
        m = fmaxf(m, fabsf(w[i]));
    #pragma unroll
    for (int o = 16; o; o >>= 1)
        m = fmaxf(m, __shfl_xor_sync(0xffffffffu, m, o));
    if ((threadIdx.x & 31) == 0) red[threadIdx.x >> 5] = m;
    __syncthreads();
    float v = red[0];
    #pragma unroll
    for (int i = 1; i < 8; i++) v = fmaxf(v, red[i]);
    return fmaxf(v, 1e-8f);
}

// ---- pack1: conv1 weights only (runs before conv1 on main stream) -----------
__global__ void pack1_kernel(const float* __restrict__ w1) {
    const float s = blk_maxabs(w1, 864);
    for (int i = threadIdx.x; i < 864; i += 256)
        g_qw1[i] = rintf(w1[i] / s) * s;
}

// ---- maxabs for wc/w2/w3 (21 blocks, side stream) ---------------------------
__global__ void maxabs_rest_kernel(const float* __restrict__ wc,
                                   const float* __restrict__ w2,
                                   const float* __restrict__ w3) {
    __shared__ float red[8];
    const int blk = blockIdx.x;
    int t, base, cnt;
    const float* p;
    if (blk == 0)      { t = 1; p = wc; base = 0; cnt = 1280; }
    else if (blk < 5)  { t = 2; p = w2; base = (blk - 1) * 4608; cnt = 4608; }
    else               { t = 3; p = w3; base = (blk - 5) * 4608; cnt = 4608; }
    float m = 0.f;
    for (int i = threadIdx.x; i < cnt; i += 256)
        m = fmaxf(m, fabsf(p[base + i]));
    #pragma unroll
    for (int o = 16; o; o >>= 1)
        m = fmaxf(m, __shfl_xor_sync(0xffffffffu, m, o));
    if ((threadIdx.x & 31) == 0) red[threadIdx.x >> 5] = m;
    __syncthreads();
    if (threadIdx.x == 0) {
        float v = red[0];
        #pragma unroll
        for (int i = 1; i < 8; i++) v = fmaxf(v, red[i]);
        atomicMax(&g_smax[t], __float_as_uint(v));  // |w|>=0, bit-monotone
    }
}

// ---- pack_rest: quantize + pack wc/w2/w3 (5 blocks, side stream) ------------
// dp4a tables: z = 32-channel group; dp covers oc z*32+16 .. z*32+31.
__global__ void pack_rest_kernel(const float* __restrict__ wc,
                                 const float* __restrict__ w2,
                                 const float* __restrict__ w3) {
    const int blk = blockIdx.x;
    if (blk == 0) {
        const float s = get_scale(1);
        for (int i = threadIdx.x; i < 1280; i += 256)
            g_qwc[i] = rintf(wc[i] / s) * s;
    } else if (blk == 1) {
        // mma frags conv2: word p: icw = (p>>1) + (p&1)*4
        const float inv_s = 1.f / get_scale(2);
        for (int i = threadIdx.x; i < 9 * 64 * 8; i += 256) {
            const int tap = i / 512, r = i % 512, oc = r >> 3, p = r & 7;
            const int icw = (p >> 1) + ((p & 1) << 2);
            uint32_t word = 0;
            #pragma unroll
            for (int l = 0; l < 4; l++) {
                const int ic = icw * 4 + l;
                const int c = (int)rintf(w2[(oc * 32 + ic) * 9 + tap] * inv_s);
                word |= ((uint32_t)(uint8_t)(int8_t)c) << (8 * l);
            }
            g_wf2[i] = (int)word;
        }
    } else if (blk == 2) {
        const float inv_s = 1.f / get_scale(3);
        for (int i = threadIdx.x; i < 9 * 2 * 128 * 8; i += 256) {
            const int tap = i / 2048, r = i % 2048;
            const int chunk = r >> 10, r2 = r & 1023, oc = r2 >> 3, p = r2 & 7;
            const int icw = (p >> 1) + ((p & 1) << 2);
            uint32_t word = 0;
            #pragma unroll
            for (int l = 0; l < 4; l++) {
                const int ic = chunk * 32 + (icw * 4) + l;
                const int c = (int)rintf(w3[(oc * 64 + ic) * 9 + tap] * inv_s);
                word |= ((uint32_t)(uint8_t)(int8_t)c) << (8 * l);
            }
            g_wf3[i] = (int)word;
        }
    } else if (blk == 3) {
        // dp4a conv2: [z][k][tap][q] uint4; oc = z*32+16+q*4+chl, ic = k*4+l
        const float inv_s = 1.f / get_scale(2);
        uint32_t* dst = (uint32_t*)g_dw2;
        for (int i = threadIdx.x; i < 2 * 8 * 9 * 16; i += 256) {
            const int z = i / 1152, r = i % 1152;
            const int k = r / 144, r2 = r % 144;
            const int t = r2 / 16, q = (r2 % 16) >> 2, chl = i & 3;
            const int oc = z * 32 + 16 + q * 4 + chl;
            uint32_t word = 0;
            #pragma unroll
            for (int l = 0; l < 4; l++) {
                const int ic = k * 4 + l;
                const int c = (int)rintf(w2[(oc * 32 + ic) * 9 + t] * inv_s);
                word |= ((uint32_t)(uint8_t)(int8_t)c) << (8 * l);
            }
            dst[i] = word;
        }
    } else {
        // dp4a conv3: z in {0..3}
        const float inv_s = 1.f / get_scale(3);
        uint32_t* dst = (uint32_t*)g_dw3;
        for (int i = threadIdx.x; i < 4 * 16 * 9 * 16; i += 256) {
            const int z = i / 2304, r = i % 2304;
            const int k = r / 144, r2 = r % 144;
            const int t = r2 / 16, q = (r2 % 16) >> 2, chl = i & 3;
            const int oc = z * 32 + 16 + q * 4 + chl;
            uint32_t word = 0;
            #pragma unroll
            for (int l = 0; l < 4; l++) {
                const int ic = k * 4 + l;
                const int c = (int)rintf(w3[(oc * 64 + ic) * 9 + t] * inv_s);
                word |= ((uint32_t)(uint8_t)(int8_t)c) << (8 * l);
            }
            dst[i] = word;
        }
    }
}

// ---- block 1: fp32 conv3x3(pad1) via fma.f32x2 + quant_act + maxpool2 -------
// 256 threads, 16x16 pooled tile, OCB=8, conflict-free float2 smem loads.
__global__ __launch_bounds__(256, 3) void conv1_kernel(
    const float* __restrict__ x, const float* __restrict__ alpha_p,
    uint8_t* __restrict__ out) {
    constexpr int H = 224, W = 224, PH = 112, PW = 112, OC = 32, OCB = 8;
    __shared__ float sx[3][34][36];
    __shared__ unsigned long long swp[OCB][3][9];   // (w,w) duplicated pairs

    const int tid = threadIdx.x;
    const int tx = tid & 15, ty = tid >> 4;          // 16x16 pooled tile
    const int tile_x = blockIdx.x;                   // 0..6
    const int tile_y = blockIdx.y % 7;
    const int b      = blockIdx.y / 7;
    const int oc0    = blockIdx.z * OCB;

    const int px0 = tile_x * 16, py0 = tile_y * 16;
    const int ix0 = 2 * px0 - 1, iy0 = 2 * py0 - 1;

    const float* xb = x + (long)b * 3 * H * W;
    for (int i = tid; i < 3 * 34 * 34; i += 256) {
        const int ic = i / 1156, rr = (i % 1156) / 34, cc = i % 34;
        const int gy = iy0 + rr, gx = ix0 + cc;
        float v = 0.f;
        if (gy >= 0 && gy < H && gx >= 0 && gx < W)
            v = xb[(long)ic * H * W + gy * W + gx];
        sx[ic][rr][cc] = v;
    }
    if (tid < OCB * 27) {
        const int j = tid / 27, r27 = tid % 27;
        const float w = g_qw1[((oc0 + j) * 3 + r27 / 9) * 9 + r27 % 9];
        unsigned long long pw;
        PACK_F32X2(pw, __float_as_uint(w), __float_as_uint(w));
        swp[j][r27 / 9][r27 % 9] = pw;
    }
    __syncthreads();

    unsigned long long accA[OCB], accB[OCB];
    #pragma unroll
    for (int j = 0; j < OCB; j++) { accA[j] = 0ull; accB[j] = 0ull; }

    #pragma unroll
    for (int ic = 0; ic < 3; ic++) {
        unsigned long long pk[4][3];
        #pragma unroll
        for (int r = 0; r < 4; r++) {
            const float2* row = (const float2*)&sx[ic][2 * ty + r][2 * tx];
            const float2 A = row[0], B = row[1];     // LDS.64 x2, no conflicts
            pk[r][0] = *(const unsigned long long*)&A;
            pk[r][2] = *(const unsigned long long*)&B;
            PACK_F32X2(pk[r][1], __float_as_uint(A.y), __float_as_uint(B.x));
        }
        #pragma unroll
        for (int j = 0; j < OCB; j++) {
            #pragma unroll
            for (int ky = 0; ky < 3; ky++)
                #pragma unroll
                for (int kx = 0; kx < 3; kx++) {
                    FMA_F32X2(accA[j], pk[ky][kx], swp[j][ic][ky * 3 + kx]);
                    FMA_F32X2(accB[j], pk[ky + 1][kx], swp[j][ic][ky * 3 + kx]);
                }
        }
    }

    const float alpha = __ldg(alpha_p);
    const float inv_scale = 3.f / alpha;
    const int px = px0 + tx, py = py0 + ty;
    uint32_t lo = 0, hi = 0;
    #pragma unroll
    for (int j = 0; j < OCB; j++) {
        float p0, p1, p2, p3;
        UNPACK_F32X2(p0, p1, accA[j]);
        UNPACK_F32X2(p2, p3, accB[j]);
        const float m = fmaxf(fmaxf(p0, p1), fmaxf(p2, p3));
        const float y = fminf(fmaxf(m, 0.f), alpha);
        const uint32_t code = (uint32_t)(int)rintf(y * inv_scale);
        if (j < 4) lo |= code << (8 * j);
        else       hi |= code << (8 * (j - 4));
    }
    *(uint2*)&out[(((long)b * PH + py) * PW + px) * OC + oc0] = make_uint2(lo, hi);
}

// ---- blocks 2/3: fused hybrid, 32 channels/CTA (16 mma + 16 dp4a) -----------
// launch_bounds(256,4): 64 regs -> 4 CTAs/SM.  (frozen from R11)
template <int H, int IC, int OC, int NOC, int MMAOC, int TW, int TH, int PSTRIDE>
__global__ __launch_bounds__(256, 4) void conv_hyb(
    const uint8_t* __restrict__ xin, const int* __restrict__ wf,
    const uint4* __restrict__ dw,
    const float* __restrict__ aprev_p, const float* __restrict__ acur_p,
    int wtensor, uint8_t* __restrict__ out) {
    constexpr int DPOC = NOC - MMAOC;          // 16
    constexpr int DQ   = DPOC / 4;             // 4
    constexpr int CH   = IC / 32;
    constexpr int IC4  = IC / 4;
    constexpr int IC16 = IC / 16;
    constexpr int TIW  = TW + 2, TIH = TH + 2;
    constexpr int OCG  = MMAOC / 8;            // 2
    constexpr int VPP  = IC / 16;
    constexpr int WTX  = TW / 8, WTY = TH / 2, NWT = WTX * WTY;
    constexpr int PHW  = H / 2;
    constexpr int DLANES = TW * (TH / 2);
    static_assert(DLANES <= 128, "dp lane budget");

    extern __shared__ __align__(16) uint8_t dsm[];
    uint8_t* stile = dsm;                                   // TIH*TIW*PSTRIDE
    uint4*   sdw   = (uint4*)(dsm + TIH * TIW * PSTRIDE);   // IC4*9*DQ uint4
    int*     swf   = (int*)(dsm + TIH * TIW * PSTRIDE + IC4 * 9 * DQ * 16);

    const int tid = threadIdx.x;
    const int tilesY = H / TH;
    const int by = blockIdx.y % tilesY;
    const int b  = blockIdx.y / tilesY;
    const int cx0 = blockIdx.x * TW, cy0 = by * TH;
    const int oc0 = blockIdx.z * NOC;

    for (int i = tid; i < 9 * CH * MMAOC * 8; i += 256) {
        const int p = i & 7, j = (i >> 3) % MMAOC, tc = (i >> 3) / MMAOC;
        swf[i] = wf[((tc * OC) + oc0 + j) * 8 + p];
    }
    {
        const uint4* dwz = dw + (long)blockIdx.z * (IC4 * 9 * DQ);
        for (int i = tid; i < IC4 * 9 * DQ; i += 256) sdw[i] = dwz[i];
    }
    for (int i = tid; i < TIH * TIW * VPP; i += 256) {
        const int v = i % VPP, pix = i / VPP;
        const int gx = cx0 - 1 + pix % TIW;
        const int gy = cy0 - 1 + pix / TIW;
        uint4 val = make_uint4(0, 0, 0, 0);
        if (gx >= 0 && gx < H && gy >= 0 && gy < H)
            val = *(const uint4*)(xin + (((long)b * H + gy) * H + gx) * IC + v * 16);
        *(uint4*)(stile + pix * PSTRIDE + v * 16) = val;
    }
    __syncthreads();

    const int warp = tid >> 5, lane = tid & 31;
    const float combined = (__ldg(aprev_p) * (1.f / 3.f)) * get_scale(wtensor);
    const float alpha = __ldg(acur_p);
    const float inv_scale = 3.f / alpha;

    if (warp < 4) {
        // ---------------- mma path (tensor pipe) ----------------
        const uint32_t sbase = smem_u32(stile);
        const int r = lane >> 2;
        for (int wt = warp; wt < NWT; wt += 4) {
            const int tx = wt % WTX, ty = wt / WTX;
            const int piy = ty * 2 + ((lane >> 3) & 1);
            const int pix = tx * 8 + (lane & 7);
            const uint32_t abase = sbase + (piy * TIW + pix) * PSTRIDE
                                 + ((lane >> 4) << 4);
            int acc[OCG][4];
            #pragma unroll
            for (int g = 0; g < OCG; g++)
                #pragma unroll
                for (int q = 0; q < 4; q++) acc[g][q] = 0;

            #pragma unroll
            for (int t = 0; t < 9; t++) {
                const int dy = t / 3, dx = t % 3;
                #pragma unroll
                for (int c = 0; c < CH; c++) {
                    int a0, a1, a2, a3;
                    ldsm4(abase + (dy * TIW + dx) * PSTRIDE + c * 32,
                          a0, a1, a2, a3);
                    #pragma unroll
                    for (int g = 0; g < OCG; g++) {
                        const uint2 bb = *(const uint2*)
                            &swf[(((t * CH + c) * MMAOC) + g * 8 + (lane >> 2)) * 8
                                 + 2 * (lane & 3)];
                        mma_s8(acc[g], a0, a1, a2, a3, (int)bb.x, (int)bb.y);
                    }
                }
            }
            #pragma unroll
            for (int g = 0; g < OCG; g++) {
                const int v0 = max(acc[g][0], acc[g][2]);
                const int v1 = max(acc[g][1], acc[g][3]);
                const int o0 = max(v0, __shfl_xor_sync(0xffffffffu, v0, 4));
                const int o1 = max(v1, __shfl_xor_sync(0xffffffffu, v1, 4));
                if (!(r & 1)) {
                    const int ppx = (cx0 >> 1) + tx * 4 + (r >> 1);
                    const int ppy = (cy0 >> 1) + ty;
                    const float f0 = fminf(fmaxf((float)o0 * combined, 0.f), alpha);
                    const float f1 = fminf(fmaxf((float)o1 * combined, 0.f), alpha);
                    const uint32_t c0 = (uint32_t)(int)rintf(f0 * inv_scale);
                    const uint32_t c1 = (uint32_t)(int)rintf(f1 * inv_scale);
                    const int oc = oc0 + g * 8 + (lane & 3) * 2;
                    *(uint16_t*)(out + (((long)b * PHW + ppy) * PHW + ppx) * OC + oc)
                        = (uint16_t)(c0 | (c1 << 8));
                }
            }
        }
    } else {
        // ---- dp4a path (fma pipe), rolling 2-row window, LDS.128 ----
        const int dt = tid - 128;              // 0..127
        const int cx = dt % TW, cyp = dt / TW;
        const bool active = dt < DLANES;
        const int dcyp = min(cyp, TH / 2 - 1);

        int acc[DPOC][2];
        #pragma unroll
        for (int j = 0; j < DPOC; j++) { acc[j][0] = 0; acc[j][1] = 0; }

        #pragma unroll 1
        for (int g4 = 0; g4 < IC16; g4++) {
            const uint8_t* tb = stile + ((2 * dcyp) * TIW + cx) * PSTRIDE
                              + g4 * 16;
            #pragma unroll
            for (int cc = 0; cc < 3; cc++) {
                const uint8_t* cp = tb + cc * PSTRIDE;
                uint4 r0 = *(const uint4*)(cp);
                uint4 r1 = *(const uint4*)(cp + TIW * PSTRIDE);
                #pragma unroll
                for (int dy = 0; dy < 3; dy++) {
                    const int t = dy * 3 + cc;
                    #pragma unroll
                    for (int kk = 0; kk < 4; kk++) {
                        const uint32_t a0 = ((const uint32_t*)&r0)[kk];
                        const uint32_t a1 = ((const uint32_t*)&r1)[kk];
                        const int k = g4 * 4 + kk;
                        #pragma unroll
                        for (int q = 0; q < DQ; q++) {
                            const uint4 w = sdw[(k * 9 + t) * DQ + q];
                            acc[q*4+0][0] = __dp4a((int)a0, (int)w.x, acc[q*4+0][0]);
                            acc[q*4+0][1] = __dp4a((int)a1, (int)w.x, acc[q*4+0][1]);
                            acc[q*4+1][0] = __dp4a((int)a0, (int)w.y, acc[q*4+1][0]);
                            acc[q*4+1][1] = __dp4a((int)a1, (int)w.y, acc[q*4+1][1]);
                            acc[q*4+2][0] = __dp4a((int)a0, (int)w.z, acc[q*4+2][0]);
                            acc[q*4+2][1] = __dp4a((int)a1, (int)w.z, acc[q*4+2][1]);
                            acc[q*4+3][0] = __dp4a((int)a0, (int)w.w, acc[q*4+3][0]);
                            acc[q*4+3][1] = __dp4a((int)a1, (int)w.w, acc[q*4+3][1]);
                        }
                    }
                    if (dy < 2) {
                        r0 = r1;
                        r1 = *(const uint4*)(cp + (dy + 2) * TIW * PSTRIDE);
                    }
                }
            }
        }

        uint32_t pw[DQ];
        #pragma unroll
        for (int q = 0; q < DQ; q++) pw[q] = 0;
        #pragma unroll
        for (int j = 0; j < DPOC; j++) {
            int v = max(acc[j][0], acc[j][1]);               // vertical pool
            v = max(v, __shfl_xor_sync(0xffffffffu, v, 1));  // horizontal pool
            const float f = fminf(fmaxf((float)v * combined, 0.f), alpha);
            const uint32_t code = (uint32_t)(int)rintf(f * inv_scale);
            pw[j >> 2] |= code << (8 * (j & 3));
        }
        if (active && !(cx & 1)) {
            const int ppx = (cx0 >> 1) + (cx >> 1);
            const int ppy = (cy0 >> 1) + cyp;
            uint8_t* o = out + (((long)b * PHW + ppy) * PHW + ppx) * OC
                       + oc0 + MMAOC;
            *(uint4*)o = make_uint4(pw[0], pw[1], pw[2], pw[3]);
        }
    }
}

// ---- global max, stage 1: partial max over 196 pixels -----------------------
__global__ void gmax_stage1(const uint8_t* __restrict__ h3) {
    __shared__ uint32_t sm[4][32];
    const int b = blockIdx.x, s = blockIdx.y;
    const int tid = threadIdx.x;
    const int w = tid >> 5, c4 = tid & 31;
    const uint32_t* p = (const uint32_t*)(h3 + (long)b * 784 * 128);
    uint32_t m = 0;
    for (int pix = s * 196 + w; pix < (s + 1) * 196; pix += 4)
        m = __vmaxu4(m, p[(long)pix * 32 + c4]);
    sm[w][c4] = m;
    __syncthreads();
    if (tid < 32)
        g_gpart[(b * 4 + s) * 32 + tid] =
            __vmaxu4(__vmaxu4(sm[0][tid], sm[1][tid]),
                     __vmaxu4(sm[2][tid], sm[3][tid]));
}

// ---- global max stage 2 + 1x1 quantized conv classifier ---------------------
__global__ void gmax_fc_kernel(const float* __restrict__ a3_p,
                               float* __restrict__ out) {
    __shared__ float gm[128];
    const int b = blockIdx.x;
    const int tid = threadIdx.x;
    if (tid < 32) {
        const uint32_t* gp = &g_gpart[b * 4 * 32];
        const uint32_t v = __vmaxu4(__vmaxu4(gp[tid], gp[32 + tid]),
                                    __vmaxu4(gp[64 + tid], gp[96 + tid]));
        const float sc = __ldg(a3_p) * (1.f / 3.f);
        gm[tid * 4 + 0] = (float)(v & 0xff) * sc;
        gm[tid * 4 + 1] = (float)((v >> 8) & 0xff) * sc;
        gm[tid * 4 + 2] = (float)((v >> 16) & 0xff) * sc;
        gm[tid * 4 + 3] = (float)(v >> 24) * sc;
    }
    __syncthreads();
    if (tid < 10) {
        float s = 0.f;
        #pragma unroll 8
        for (int k = 0; k < 128; k++)
            s = fmaf(gm[k], g_qwc[tid * 128 + k], s);
        out[b * 10 + tid] = s;
    }
}

// ---------------------------------------------------------------------------
extern "C" void kernel_launch(void* const* d_in, const int* in_sizes, int n_in,
                              void* d_out, int out_size) {
    const float* x  = (const float*)d_in[0];
    const float* w1 = (const float*)d_in[1];
    const float* w2 = (const float*)d_in[2];
    const float* w3 = (const float*)d_in[3];
    const float* wc = (const float*)d_in[4];
    const float* a1 = (const float*)d_in[5];
    const float* a2 = (const float*)d_in[6];
    const float* a3 = (const float*)d_in[7];

    int *wf2, *wf3;
    uint4 *dw2, *dw3;
    uint8_t *c1, *c2, *c3;
    cudaGetSymbolAddress((void**)&wf2, g_wf2);
    cudaGetSymbolAddress((void**)&wf3, g_wf3);
    cudaGetSymbolAddress((void**)&dw2, g_dw2);
    cudaGetSymbolAddress((void**)&dw3, g_dw3);
    cudaGetSymbolAddress((void**)&c1, g_c1);
    cudaGetSymbolAddress((void**)&c2, g_c2);
    cudaGetSymbolAddress((void**)&c3, g_c3);

    // conv2: 32 channels/CTA (16 mma + 16 dp), tile 16x16, z=2
    auto k2 = conv_hyb<112, 32, 64, 32, 16, 16, 16, 48>;
    constexpr int SM2 = 18 * 18 * 48 + 8 * 9 * 4 * 16 + 9 * 1 * 16 * 8 * 4;
    // conv3: 32 channels/CTA, tile 8x28, z=4
    auto k3 = conv_hyb<56, 64, 128, 32, 16, 8, 28, 80>;
    constexpr int SM3 = 30 * 10 * 80 + 16 * 9 * 4 * 16 + 9 * 2 * 16 * 8 * 4;
    cudaFuncSetAttribute(k2, cudaFuncAttributeMaxDynamicSharedMemorySize, SM2);
    cudaFuncSetAttribute(k3, cudaFuncAttributeMaxDynamicSharedMemorySize, SM3);

    // side stream + fork/join events (created on first, uncaptured call)
    static cudaStream_t s1 = nullptr;
    static cudaEvent_t evF = nullptr, evJ = nullptr;
    if (s1 == nullptr) {
        cudaStreamCreateWithFlags(&s1, cudaStreamNonBlocking);
        cudaEventCreateWithFlags(&evF, cudaEventDisableTiming);
        cudaEventCreateWithFlags(&evJ, cudaEventDisableTiming);
    }

    // conv1 weights (needed immediately by conv1)
    pack1_kernel<<<1, 256>>>(w1);

    // fork: conv2/3 weight prep overlaps conv1 on side stream
    cudaEventRecord(evF, 0);
    cudaStreamWaitEvent(s1, evF, 0);
    maxabs_rest_kernel<<<21, 256, 0, s1>>>(wc, w2, w3);
    pack_rest_kernel<<<5, 256, 0, s1>>>(wc, w2, w3);
    cudaEventRecord(evJ, s1);

    // block 1: [32,3,224,224] -> codes [32,112,112,32]
    conv1_kernel<<<dim3(7, 7 * 32, 4), 256>>>(x, a1, c1);

    // join before conv2 (needs wf2/dw2/g_smax)
    cudaStreamWaitEvent(0, evJ, 0);

    // block 2: -> codes [32,56,56,64]
    k2<<<dim3(7, 7 * 32, 2), 256, SM2>>>(c1, wf2, dw2, a1, a2, 2, c2);
    // block 3: -> codes [32,28,28,128]
    k3<<<dim3(7, 2 * 32, 4), 256, SM3>>>(c2, wf3, dw3, a2, a3, 3, c3);

    // global max + classifier (two-stage)
    gmax_stage1<<<dim3(32, 4), 128>>>(c3);
    gmax_fc_kernel<<<32, 128>>>(a3, (float*)d_out);
}

// round 16
// speedup vs baseline: 1.5989x; 1.1936x over previous
#include <cuda_runtime.h>
#include <cuda_bf16.h>
#include <stdint.h>
#include <math.h>

// ---------------------------------------------------------------------------
// 2-bit quantized CNN forward.
//  conv1: SPARSE fp32 conv — per-oc nonzero-tap lists (~89% of quantized
//    conv1 weights are exactly 0); uniform warp loops, conflict-free LDS.
//  conv2/conv3: fused hybrid int8 conv, 32 channels per CTA:
//    warps 0-3: mma.sync.m16n8k32.s8 (tensor pipe), 16 channels
//    warps 4-7: dp4a (fma pipe), 16 channels, rolling 2-row window
//  Prologue for conv2/3 weights overlapped with conv1 on a side stream.
//  Exact integer math: conv = (sum code*wint) * (alpha_prev/3 * s_w).
// ---------------------------------------------------------------------------

__device__ unsigned g_smax[4];                 // maxabs bits: w1, wc, w2, w3
__device__ float    g_qwc[10 * 128];
__device__ uint2    g_lst1[32][88];            // conv1 sparse taps {off, w}
__device__ int      g_cnt1[32];                // nonzero count per oc
__device__ int      g_wf2[9 * 64 * 8];         // mma B-frags [tap][oc][p]
__device__ int      g_wf3[9 * 2 * 128 * 8];    // [tap][chunk][oc][p]
__device__ uint4    g_dw2[2 * 8 * 9 * 4];      // dp4a w [z][k][tap][q]
__device__ uint4    g_dw3[4 * 16 * 9 * 4];     // [z][k][tap][q]
__device__ uint32_t g_gpart[32 * 4 * 32];      // gmax stage1 partials
__device__ uint8_t  g_c1[32L * 112 * 112 * 32];
__device__ uint8_t  g_c2[32L * 56 * 56 * 64];
__device__ uint8_t  g_c3[32L * 28 * 28 * 128];

// ---- helpers ---------------------------------------------------------------
__device__ __forceinline__ uint32_t smem_u32(const void* p) {
    uint32_t a;
    asm("{ .reg .u64 t; cvta.to.shared.u64 t, %1; cvt.u32.u64 %0, t; }"
        : "=r"(a) : "l"(p));
    return a;
}
__device__ __forceinline__ void ldsm4(uint32_t addr, int& a0, int& a1,
                                      int& a2, int& a3) {
    asm volatile("ldmatrix.sync.aligned.m8n8.x4.shared.b16 {%0,%1,%2,%3},[%4];"
                 : "=r"(a0), "=r"(a1), "=r"(a2), "=r"(a3) : "r"(addr));
}
__device__ __forceinline__ void mma_s8(int* d, int a0, int a1, int a2, int a3,
                                       int b0, int b1) {
    asm("mma.sync.aligned.m16n8k32.row.col.s32.s8.s8.s32 "
        "{%0,%1,%2,%3},{%4,%5,%6,%7},{%8,%9},{%0,%1,%2,%3};"
        : "+r"(d[0]), "+r"(d[1]), "+r"(d[2]), "+r"(d[3])
        : "r"(a0), "r"(a1), "r"(a2), "r"(a3), "r"(b0), "r"(b1));
}

__device__ __forceinline__ float get_scale(int t) {
    return fmaxf(__uint_as_float(g_smax[t]), 1e-8f);
}

// block-wide (256 thr) max|w| reduction
__device__ __forceinline__ float blk_maxabs(const float* __restrict__ w, int n) {
    __shared__ float red[8];
    float m = 0.f;
    for (int i = threadIdx.x; i < n; i += 256)
        m = fmaxf(m, fabsf(w[i]));
    #pragma unroll
    for (int o = 16; o; o >>= 1)
        m = fmaxf(m, __shfl_xor_sync(0xffffffffu, m, o));
    if ((threadIdx.x & 31) == 0) red[threadIdx.x >> 5] = m;
    __syncthreads();
    float v = red[0];
    #pragma unroll
    for (int i = 1; i < 8; i++) v = fmaxf(v, red[i]);
    return fmaxf(v, 1e-8f);
}

// ---- pack1: conv1 sparse tap lists (runs before conv1 on main stream) -------
// off = ic*648 + ky*36 + kx (float index into the conv1 smem tile).
__global__ void pack1_kernel(const float* __restrict__ w1) {
    const float s = blk_maxabs(w1, 864);
    if (threadIdx.x == 0) g_smax[0] = __float_as_uint(s);
    if (threadIdx.x < 32) {
        const int oc = threadIdx.x;
        const float inv_s = 1.f / s;
        int n = 0;
        for (int ic = 0; ic < 3; ic++)
            for (int t = 0; t < 9; t++) {
                const int c = (int)rintf(w1[(oc * 3 + ic) * 9 + t] * inv_s);
                if (c != 0) {
                    const uint32_t off = ic * 648 + (t / 3) * 36 + (t % 3);
                    g_lst1[oc][n++] = make_uint2(
                        off, __float_as_uint(c > 0 ? s : -s));
                }
            }
        g_cnt1[oc] = n;
    }
}

// ---- maxabs for wc/w2/w3 (21 blocks, side stream) ---------------------------
__global__ void maxabs_rest_kernel(const float* __restrict__ wc,
                                   const float* __restrict__ w2,
                                   const float* __restrict__ w3) {
    __shared__ float red[8];
    const int blk = blockIdx.x;
    int t, base, cnt;
    const float* p;
    if (blk == 0)      { t = 1; p = wc; base = 0; cnt = 1280; }
    else if (blk < 5)  { t = 2; p = w2; base = (blk - 1) * 4608; cnt = 4608; }
    else               { t = 3; p = w3; base = (blk - 5) * 4608; cnt = 4608; }
    float m = 0.f;
    for (int i = threadIdx.x; i < cnt; i += 256)
        m = fmaxf(m, fabsf(p[base + i]));
    #pragma unroll
    for (int o = 16; o; o >>= 1)
        m = fmaxf(m, __shfl_xor_sync(0xffffffffu, m, o));
    if ((threadIdx.x & 31) == 0) red[threadIdx.x >> 5] = m;
    __syncthreads();
    if (threadIdx.x == 0) {
        float v = red[0];
        #pragma unroll
        for (int i = 1; i < 8; i++) v = fmaxf(v, red[i]);
        atomicMax(&g_smax[t], __float_as_uint(v));  // |w|>=0, bit-monotone
    }
}

// ---- pack_rest: quantize + pack wc/w2/w3 (5 blocks, side stream) ------------
__global__ void pack_rest_kernel(const float* __restrict__ wc,
                                 const float* __restrict__ w2,
                                 const float* __restrict__ w3) {
    const int blk = blockIdx.x;
    if (blk == 0) {
        const float s = get_scale(1);
        for (int i = threadIdx.x; i < 1280; i += 256)
            g_qwc[i] = rintf(wc[i] / s) * s;
    } else if (blk == 1) {
        const float inv_s = 1.f / get_scale(2);
        for (int i = threadIdx.x; i < 9 * 64 * 8; i += 256) {
            const int tap = i / 512, r = i % 512, oc = r >> 3, p = r & 7;
            const int icw = (p >> 1) + ((p & 1) << 2);
            uint32_t word = 0;
            #pragma unroll
            for (int l = 0; l < 4; l++) {
                const int ic = icw * 4 + l;
                const int c = (int)rintf(w2[(oc * 32 + ic) * 9 + tap] * inv_s);
                word |= ((uint32_t)(uint8_t)(int8_t)c) << (8 * l);
            }
            g_wf2[i] = (int)word;
        }
    } else if (blk == 2) {
        const float inv_s = 1.f / get_scale(3);
        for (int i = threadIdx.x; i < 9 * 2 * 128 * 8; i += 256) {
            const int tap = i / 2048, r = i % 2048;
            const int chunk = r >> 10, r2 = r & 1023, oc = r2 >> 3, p = r2 & 7;
            const int icw = (p >> 1) + ((p & 1) << 2);
            uint32_t word = 0;
            #pragma unroll
            for (int l = 0; l < 4; l++) {
                const int ic = chunk * 32 + (icw * 4) + l;
                const int c = (int)rintf(w3[(oc * 64 + ic) * 9 + tap] * inv_s);
                word |= ((uint32_t)(uint8_t)(int8_t)c) << (8 * l);
            }
            g_wf3[i] = (int)word;
        }
    } else if (blk == 3) {
        const float inv_s = 1.f / get_scale(2);
        uint32_t* dst = (uint32_t*)g_dw2;
        for (int i = threadIdx.x; i < 2 * 8 * 9 * 16; i += 256) {
            const int z = i / 1152, r = i % 1152;
            const int k = r / 144, r2 = r % 144;
            const int t = r2 / 16, q = (r2 % 16) >> 2, chl = i & 3;
            const int oc = z * 32 + 16 + q * 4 + chl;
            uint32_t word = 0;
            #pragma unroll
            for (int l = 0; l < 4; l++) {
                const int ic = k * 4 + l;
                const int c = (int)rintf(w2[(oc * 32 + ic) * 9 + t] * inv_s);
                word |= ((uint32_t)(uint8_t)(int8_t)c) << (8 * l);
            }
            dst[i] = word;
        }
    } else {
        const float inv_s = 1.f / get_scale(3);
        uint32_t* dst = (uint32_t*)g_dw3;
        for (int i = threadIdx.x; i < 4 * 16 * 9 * 16; i += 256) {
            const int z = i / 2304, r = i % 2304;
            const int k = r / 144, r2 = r % 144;
            const int t = r2 / 16, q = (r2 % 16) >> 2, chl = i & 3;
            const int oc = z * 32 + 16 + q * 4 + chl;
            uint32_t word = 0;
            #pragma unroll
            for (int l = 0; l < 4; l++) {
                const int ic = k * 4 + l;
                const int c = (int)rintf(w3[(oc * 64 + ic) * 9 + t] * inv_s);
                word |= ((uint32_t)(uint8_t)(int8_t)c) << (8 * l);
            }
            dst[i] = word;
        }
    }
}

// ---- block 1: SPARSE fp32 conv3x3(pad1) + quant_act + maxpool2 --------------
// 256 threads = 32 conv cols x 8 pooled rows; thread owns 2 conv rows of one
// column; 16 oc per CTA (z=2).  Inner loop over the oc's nonzero taps:
// 1 broadcast LDS.64 (entry) + 2 conflict-free LDS + 2 FFMA.
__global__ __launch_bounds__(256, 4) void conv1_kernel(
    const float* __restrict__ x, const float* __restrict__ alpha_p,
    uint8_t* __restrict__ out) {
    constexpr int H = 224, W = 224, PH = 112, PW = 112, OC = 32, OCB = 16;
    __shared__ float sx[3 * 18 * 36];            // [ic][row 18][pitch 36]
    __shared__ uint2 slst[16 * 88];
    __shared__ int   scnt[16];

    const int tid = threadIdx.x;
    const int tx = tid & 31, ty = tid >> 5;      // conv col, pooled row
    const int tile_x = blockIdx.x;               // 0..6
    const int tile_y = blockIdx.y % 14;
    const int b      = blockIdx.y / 14;
    const int oc0    = blockIdx.z * OCB;

    const int cx0 = tile_x * 32, cy0 = tile_y * 16;   // conv-space origin
    const int px0 = tile_x * 16, py0 = tile_y * 8;    // pooled origin

    const float* xb = x + (long)b * 3 * H * W;
    for (int i = tid; i < 3 * 18 * 34; i += 256) {
        const int ic = i / 612, r = (i % 612) / 34, c = i % 34;
        const int gy = cy0 - 1 + r, gx = cx0 - 1 + c;
        float v = 0.f;
        if (gy >= 0 && gy < H && gx >= 0 && gx < W)
            v = xb[(long)ic * H * W + gy * W + gx];
        sx[ic * 648 + r * 36 + c] = v;
    }
    for (int i = tid; i < 16 * 88; i += 256)
        slst[i] = g_lst1[oc0 + i / 88][i % 88];
    if (tid < 16) scnt[tid] = g_cnt1[oc0 + tid];
    __syncthreads();

    const float alpha = __ldg(alpha_p);
    const float inv_scale = 3.f / alpha;
    const int base = 2 * ty * 36 + tx;

    uint32_t pw[4] = {0, 0, 0, 0};
    #pragma unroll 1
    for (int j = 0; j < OCB; j++) {
        const int n = scnt[j];
        const uint2* lst = &slst[j * 88];
        float p0 = 0.f, p1 = 0.f;
        #pragma unroll 1
        for (int i = 0; i < n; i++) {
            const uint2 e = lst[i];                  // broadcast LDS.64
            const float w = __uint_as_float(e.y);
            p0 = fmaf(w, sx[base + e.x], p0);        // conv row 2ty
            p1 = fmaf(w, sx[base + e.x + 36], p1);   // conv row 2ty+1
        }
        float m = fmaxf(p0, p1);                     // vertical pool
        m = fmaxf(m, __shfl_xor_sync(0xffffffffu, m, 1));  // horizontal pool
        const float y = fminf(fmaxf(m, 0.f), alpha);
        const uint32_t code = (uint32_t)(int)rintf(y * inv_scale);
        pw[j >> 2] |= code << (8 * (j & 3));
    }

    if (!(tx & 1)) {
        const int ppx = px0 + (tx >> 1), ppy = py0 + ty;
        *(uint4*)&out[(((long)b * PH + ppy) * PW + ppx) * OC + oc0]
            = make_uint4(pw[0], pw[1], pw[2], pw[3]);
    }
}

// ---- blocks 2/3: fused hybrid, 32 channels/CTA (16 mma + 16 dp4a) -----------
// launch_bounds(256,4): 64 regs -> 4 CTAs/SM.  (frozen from R11)
template <int H, int IC, int OC, int NOC, int MMAOC, int TW, int TH, int PSTRIDE>
__global__ __launch_bounds__(256, 4) void conv_hyb(
    const uint8_t* __restrict__ xin, const int* __restrict__ wf,
    const uint4* __restrict__ dw,
    const float* __restrict__ aprev_p, const float* __restrict__ acur_p,
    int wtensor, uint8_t* __restrict__ out) {
    constexpr int DPOC = NOC - MMAOC;          // 16
    constexpr int DQ   = DPOC / 4;             // 4
    constexpr int CH   = IC / 32;
    constexpr int IC4  = IC / 4;
    constexpr int IC16 = IC / 16;
    constexpr int TIW  = TW + 2, TIH = TH + 2;
    constexpr int OCG  = MMAOC / 8;            // 2
    constexpr int VPP  = IC / 16;
    constexpr int WTX  = TW / 8, WTY = TH / 2, NWT = WTX * WTY;
    constexpr int PHW  = H / 2;
    constexpr int DLANES = TW * (TH / 2);
    static_assert(DLANES <= 128, "dp lane budget");

    extern __shared__ __align__(16) uint8_t dsm[];
    uint8_t* stile = dsm;                                   // TIH*TIW*PSTRIDE
    uint4*   sdw   = (uint4*)(dsm + TIH * TIW * PSTRIDE);   // IC4*9*DQ uint4
    int*     swf   = (int*)(dsm + TIH * TIW * PSTRIDE + IC4 * 9 * DQ * 16);

    const int tid = threadIdx.x;
    const int tilesY = H / TH;
    const int by = blockIdx.y % tilesY;
    const int b  = blockIdx.y / tilesY;
    const int cx0 = blockIdx.x * TW, cy0 = by * TH;
    const int oc0 = blockIdx.z * NOC;

    for (int i = tid; i < 9 * CH * MMAOC * 8; i += 256) {
        const int p = i & 7, j = (i >> 3) % MMAOC, tc = (i >> 3) / MMAOC;
        swf[i] = wf[((tc * OC) + oc0 + j) * 8 + p];
    }
    {
        const uint4* dwz = dw + (long)blockIdx.z * (IC4 * 9 * DQ);
        for (int i = tid; i < IC4 * 9 * DQ; i += 256) sdw[i] = dwz[i];
    }
    for (int i = tid; i < TIH * TIW * VPP; i += 256) {
        const int v = i % VPP, pix = i / VPP;
        const int gx = cx0 - 1 + pix % TIW;
        const int gy = cy0 - 1 + pix / TIW;
        uint4 val = make_uint4(0, 0, 0, 0);
        if (gx >= 0 && gx < H && gy >= 0 && gy < H)
            val = *(const uint4*)(xin + (((long)b * H + gy) * H + gx) * IC + v * 16);
        *(uint4*)(stile + pix * PSTRIDE + v * 16) = val;
    }
    __syncthreads();

    const int warp = tid >> 5, lane = tid & 31;
    const float combined = (__ldg(aprev_p) * (1.f / 3.f)) * get_scale(wtensor);
    const float alpha = __ldg(acur_p);
    const float inv_scale = 3.f / alpha;

    if (warp < 4) {
        // ---------------- mma path (tensor pipe) ----------------
        const uint32_t sbase = smem_u32(stile);
        const int r = lane >> 2;
        for (int wt = warp; wt < NWT; wt += 4) {
            const int tx = wt % WTX, ty = wt / WTX;
            const int piy = ty * 2 + ((lane >> 3) & 1);
            const int pix = tx * 8 + (lane & 7);
            const uint32_t abase = sbase + (piy * TIW + pix) * PSTRIDE
                                 + ((lane >> 4) << 4);
            int acc[OCG][4];
            #pragma unroll
            for (int g = 0; g < OCG; g++)
                #pragma unroll
                for (int q = 0; q < 4; q++) acc[g][q] = 0;

            #pragma unroll
            for (int t = 0; t < 9; t++) {
                const int dy = t / 3, dx = t % 3;
                #pragma unroll
                for (int c = 0; c < CH; c++) {
                    int a0, a1, a2, a3;
                    ldsm4(abase + (dy * TIW + dx) * PSTRIDE + c * 32,
                          a0, a1, a2, a3);
                    #pragma unroll
                    for (int g = 0; g < OCG; g++) {
                        const uint2 bb = *(const uint2*)
                            &swf[(((t * CH + c) * MMAOC) + g * 8 + (lane >> 2)) * 8
                                 + 2 * (lane & 3)];
                        mma_s8(acc[g], a0, a1, a2, a3, (int)bb.x, (int)bb.y);
                    }
                }
            }
            #pragma unroll
            for (int g = 0; g < OCG; g++) {
                const int v0 = max(acc[g][0], acc[g][2]);
                const int v1 = max(acc[g][1], acc[g][3]);
                const int o0 = max(v0, __shfl_xor_sync(0xffffffffu, v0, 4));
                const int o1 = max(v1, __shfl_xor_sync(0xffffffffu, v1, 4));
                if (!(r & 1)) {
                    const int ppx = (cx0 >> 1) + tx * 4 + (r >> 1);
                    const int ppy = (cy0 >> 1) + ty;
                    const float f0 = fminf(fmaxf((float)o0 * combined, 0.f), alpha);
                    const float f1 = fminf(fmaxf((float)o1 * combined, 0.f), alpha);
                    const uint32_t c0 = (uint32_t)(int)rintf(f0 * inv_scale);
                    const uint32_t c1 = (uint32_t)(int)rintf(f1 * inv_scale);
                    const int oc = oc0 + g * 8 + (lane & 3) * 2;
                    *(uint16_t*)(out + (((long)b * PHW + ppy) * PHW + ppx) * OC + oc)
                        = (uint16_t)(c0 | (c1 << 8));
                }
            }
        }
    } else {
        // ---- dp4a path (fma pipe), rolling 2-row window, LDS.128 ----
        const int dt = tid - 128;              // 0..127
        const int cx = dt % TW, cyp = dt / TW;
        const bool active = dt < DLANES;
        const int dcyp = min(cyp, TH / 2 - 1);

        int acc[DPOC][2];
        #pragma unroll
        for (int j = 0; j < DPOC; j++) { acc[j][0] = 0; acc[j][1] = 0; }

        #pragma unroll 1
        for (int g4 = 0; g4 < IC16; g4++) {
            const uint8_t* tb = stile + ((2 * dcyp) * TIW + cx) * PSTRIDE
                              + g4 * 16;
            #pragma unroll
            for (int cc = 0; cc < 3; cc++) {
                const uint8_t* cp = tb + cc * PSTRIDE;
                uint4 r0 = *(const uint4*)(cp);
                uint4 r1 = *(const uint4*)(cp + TIW * PSTRIDE);
                #pragma unroll
                for (int dy = 0; dy < 3; dy++) {
                    const int t = dy * 3 + cc;
                    #pragma unroll
                    for (int kk = 0; kk < 4; kk++) {
                        const uint32_t a0 = ((const uint32_t*)&r0)[kk];
                        const uint32_t a1 = ((const uint32_t*)&r1)[kk];
                        const int k = g4 * 4 + kk;
                        #pragma unroll
                        for (int q = 0; q < DQ; q++) {
                            const uint4 w = sdw[(k * 9 + t) * DQ + q];
                            acc[q*4+0][0] = __dp4a((int)a0, (int)w.x, acc[q*4+0][0]);
                            acc[q*4+0][1] = __dp4a((int)a1, (int)w.x, acc[q*4+0][1]);
                            acc[q*4+1][0] = __dp4a((int)a0, (int)w.y, acc[q*4+1][0]);
                            acc[q*4+1][1] = __dp4a((int)a1, (int)w.y, acc[q*4+1][1]);
                            acc[q*4+2][0] = __dp4a((int)a0, (int)w.z, acc[q*4+2][0]);
                            acc[q*4+2][1] = __dp4a((int)a1, (int)w.z, acc[q*4+2][1]);
                            acc[q*4+3][0] = __dp4a((int)a0, (int)w.w, acc[q*4+3][0]);
                            acc[q*4+3][1] = __dp4a((int)a1, (int)w.w, acc[q*4+3][1]);
                        }
                    }
                    if (dy < 2) {
                        r0 = r1;
                        r1 = *(const uint4*)(cp + (dy + 2) * TIW * PSTRIDE);
                    }
                }
            }
        }

        uint32_t pw[DQ];
        #pragma unroll
        for (int q = 0; q < DQ; q++) pw[q] = 0;
        #pragma unroll
        for (int j = 0; j < DPOC; j++) {
            int v = max(acc[j][0], acc[j][1]);               // vertical pool
            v = max(v, __shfl_xor_sync(0xffffffffu, v, 1));  // horizontal pool
            const float f = fminf(fmaxf((float)v * combined, 0.f), alpha);
            const uint32_t code = (uint32_t)(int)rintf(f * inv_scale);
            pw[j >> 2] |= code << (8 * (j & 3));
        }
        if (active && !(cx & 1)) {
            const int ppx = (cx0 >> 1) + (cx >> 1);
            const int ppy = (cy0 >> 1) + cyp;
            uint8_t* o = out + (((long)b * PHW + ppy) * PHW + ppx) * OC
                       + oc0 + MMAOC;
            *(uint4*)o = make_uint4(pw[0], pw[1], pw[2], pw[3]);
        }
    }
}

// ---- global max, stage 1: partial max over 196 pixels -----------------------
__global__ void gmax_stage1(const uint8_t* __restrict__ h3) {
    __shared__ uint32_t sm[4][32];
    const int b = blockIdx.x, s = blockIdx.y;
    const int tid = threadIdx.x;
    const int w = tid >> 5, c4 = tid & 31;
    const uint32_t* p = (const uint32_t*)(h3 + (long)b * 784 * 128);
    uint32_t m = 0;
    for (int pix = s * 196 + w; pix < (s + 1) * 196; pix += 4)
        m = __vmaxu4(m, p[(long)pix * 32 + c4]);
    sm[w][c4] = m;
    __syncthreads();
    if (tid < 32)
        g_gpart[(b * 4 + s) * 32 + tid] =
            __vmaxu4(__vmaxu4(sm[0][tid], sm[1][tid]),
                     __vmaxu4(sm[2][tid], sm[3][tid]));
}

// ---- global max stage 2 + 1x1 quantized conv classifier ---------------------
__global__ void gmax_fc_kernel(const float* __restrict__ a3_p,
                               float* __restrict__ out) {
    __shared__ float gm[128];
    const int b = blockIdx.x;
    const int tid = threadIdx.x;
    if (tid < 32) {
        const uint32_t* gp = &g_gpart[b * 4 * 32];
        const uint32_t v = __vmaxu4(__vmaxu4(gp[tid], gp[32 + tid]),
                                    __vmaxu4(gp[64 + tid], gp[96 + tid]));
        const float sc = __ldg(a3_p) * (1.f / 3.f);
        gm[tid * 4 + 0] = (float)(v & 0xff) * sc;
        gm[tid * 4 + 1] = (float)((v >> 8) & 0xff) * sc;
        gm[tid * 4 + 2] = (float)((v >> 16) & 0xff) * sc;
        gm[tid * 4 + 3] = (float)(v >> 24) * sc;
    }
    __syncthreads();
    if (tid < 10) {
        float s = 0.f;
        #pragma unroll 8
        for (int k = 0; k < 128; k++)
            s = fmaf(gm[k], g_qwc[tid * 128 + k], s);
        out[b * 10 + tid] = s;
    }
}

// ---------------------------------------------------------------------------
extern "C" void kernel_launch(void* const* d_in, const int* in_sizes, int n_in,
                              void* d_out, int out_size) {
    const float* x  = (const float*)d_in[0];
    const float* w1 = (const float*)d_in[1];
    const float* w2 = (const float*)d_in[2];
    const float* w3 = (const float*)d_in[3];
    const float* wc = (const float*)d_in[4];
    const float* a1 = (const float*)d_in[5];
    const float* a2 = (const float*)d_in[6];
    const float* a3 = (const float*)d_in[7];

    int *wf2, *wf3;
    uint4 *dw2, *dw3;
    uint8_t *c1, *c2, *c3;
    cudaGetSymbolAddress((void**)&wf2, g_wf2);
    cudaGetSymbolAddress((void**)&wf3, g_wf3);
    cudaGetSymbolAddress((void**)&dw2, g_dw2);
    cudaGetSymbolAddress((void**)&dw3, g_dw3);
    cudaGetSymbolAddress((void**)&c1, g_c1);
    cudaGetSymbolAddress((void**)&c2, g_c2);
    cudaGetSymbolAddress((void**)&c3, g_c3);

    // conv2: 32 channels/CTA (16 mma + 16 dp), tile 16x16, z=2
    auto k2 = conv_hyb<112, 32, 64, 32, 16, 16, 16, 48>;
    constexpr int SM2 = 18 * 18 * 48 + 8 * 9 * 4 * 16 + 9 * 1 * 16 * 8 * 4;
    // conv3: 32 channels/CTA, tile 8x28, z=4
    auto k3 = conv_hyb<56, 64, 128, 32, 16, 8, 28, 80>;
    constexpr int SM3 = 30 * 10 * 80 + 16 * 9 * 4 * 16 + 9 * 2 * 16 * 8 * 4;
    cudaFuncSetAttribute(k2, cudaFuncAttributeMaxDynamicSharedMemorySize, SM2);
    cudaFuncSetAttribute(k3, cudaFuncAttributeMaxDynamicSharedMemorySize, SM3);

    // side stream + fork/join events (created on first, uncaptured call)
    static cudaStream_t s1 = nullptr;
    static cudaEvent_t evF = nullptr, evJ = nullptr;
    if (s1 == nullptr) {
        cudaStreamCreateWithFlags(&s1, cudaStreamNonBlocking);
        cudaEventCreateWithFlags(&evF, cudaEventDisableTiming);
        cudaEventCreateWithFlags(&evJ, cudaEventDisableTiming);
    }

    // conv1 weights (needed immediately by conv1)
    pack1_kernel<<<1, 256>>>(w1);

    // fork: conv2/3 weight prep overlaps conv1 on side stream
    cudaEventRecord(evF, 0);
    cudaStreamWaitEvent(s1, evF, 0);
    maxabs_rest_kernel<<<21, 256, 0, s1>>>(wc, w2, w3);
    pack_rest_kernel<<<5, 256, 0, s1>>>(wc, w2, w3);
    cudaEventRecord(evJ, s1);

    // block 1: [32,3,224,224] -> codes [32,112,112,32]
    conv1_kernel<<<dim3(7, 14 * 32, 2), 256>>>(x, a1, c1);

    // join before conv2 (needs wf2/dw2/g_smax)
    cudaStreamWaitEvent(0, evJ, 0);

    // block 2: -> codes [32,56,56,64]
    k2<<<dim3(7, 7 * 32, 2), 256, SM2>>>(c1, wf2, dw2, a1, a2, 2, c2);
    // block 3: -> codes [32,28,28,128]
    k3<<<dim3(7, 2 * 32, 4), 256, SM3>>>(c2, wf3, dw3, a2, a3, 3, c3);

    // global max + classifier (two-stage)
    gmax_stage1<<<dim3(32, 4), 128>>>(c3);
    gmax_fc_kernel<<<32, 128>>>(a3, (float*)d_out);
}

// round 17
// speedup vs baseline: 1.6795x; 1.0504x over previous
#include <cuda_runtime.h>
#include <cuda_bf16.h>
#include <stdint.h>
#include <math.h>

// ---------------------------------------------------------------------------
// 2-bit quantized CNN forward.
//  conv1: SPARSE fp32 conv — per-oc nonzero-tap lists (~89% of quantized
//    conv1 weights are exactly 0); 4 conv rows per thread (2 pooled rows).
//  conv2/conv3: fused hybrid int8 conv, 32 channels per CTA:
//    warps 0-3: mma.sync.m16n8k32.s8 (tensor pipe), 16 channels
//    warps 4-7: dp4a (fma pipe), 16 channels, rolling 2-row window
//  Prologue for conv2/3 weights overlapped with conv1 on a side stream.
//  Exact integer math: conv = (sum code*wint) * (alpha_prev/3 * s_w).
// ---------------------------------------------------------------------------

__device__ unsigned g_smax[4];                 // maxabs bits: w1, wc, w2, w3
__device__ float    g_qwc[10 * 128];
__device__ uint2    g_lst1[32][88];            // conv1 sparse taps {off, w}
__device__ int      g_cnt1[32];                // nonzero count per oc
__device__ int      g_wf2[9 * 64 * 8];         // mma B-frags [tap][oc][p]
__device__ int      g_wf3[9 * 2 * 128 * 8];    // [tap][chunk][oc][p]
__device__ uint4    g_dw2[2 * 8 * 9 * 4];      // dp4a w [z][k][tap][q]
__device__ uint4    g_dw3[4 * 16 * 9 * 4];     // [z][k][tap][q]
__device__ uint32_t g_gpart[32 * 4 * 32];      // gmax stage1 partials
__device__ uint8_t  g_c1[32L * 112 * 112 * 32];
__device__ uint8_t  g_c2[32L * 56 * 56 * 64];
__device__ uint8_t  g_c3[32L * 28 * 28 * 128];

// ---- helpers ---------------------------------------------------------------
__device__ __forceinline__ uint32_t smem_u32(const void* p) {
    uint32_t a;
    asm("{ .reg .u64 t; cvta.to.shared.u64 t, %1; cvt.u32.u64 %0, t; }"
        : "=r"(a) : "l"(p));
    return a;
}
__device__ __forceinline__ void ldsm4(uint32_t addr, int& a0, int& a1,
                                      int& a2, int& a3) {
    asm volatile("ldmatrix.sync.aligned.m8n8.x4.shared.b16 {%0,%1,%2,%3},[%4];"
                 : "=r"(a0), "=r"(a1), "=r"(a2), "=r"(a3) : "r"(addr));
}
__device__ __forceinline__ void mma_s8(int* d, int a0, int a1, int a2, int a3,
                                       int b0, int b1) {
    asm("mma.sync.aligned.m16n8k32.row.col.s32.s8.s8.s32 "
        "{%0,%1,%2,%3},{%4,%5,%6,%7},{%8,%9},{%0,%1,%2,%3};"
        : "+r"(d[0]), "+r"(d[1]), "+r"(d[2]), "+r"(d[3])
        : "r"(a0), "r"(a1), "r"(a2), "r"(a3), "r"(b0), "r"(b1));
}

__device__ __forceinline__ float get_scale(int t) {
    return fmaxf(__uint_as_float(g_smax[t]), 1e-8f);
}

// block-wide (256 thr) max|w| reduction
__device__ __forceinline__ float blk_maxabs(const float* __restrict__ w, int n) {
    __shared__ float red[8];
    float m = 0.f;
    for (int i = threadIdx.x; i < n; i += 256)
        m = fmaxf(m, fabsf(w[i]));
    #pragma unroll
    for (int o = 16; o; o >>= 1)
        m = fmaxf(m, __shfl_xor_sync(0xffffffffu, m, o));
    if ((threadIdx.x & 31) == 0) red[threadIdx.x >> 5] = m;
    __syncthreads();
    float v = red[0];
    #pragma unroll
    for (int i = 1; i < 8; i++) v = fmaxf(v, red[i]);
    return fmaxf(v, 1e-8f);
}

// ---- pack1: conv1 sparse tap lists (runs before conv1 on main stream) -------
// off = ic*1224 + ky*36 + kx (float index into the conv1 smem tile, 34 rows).
__global__ void pack1_kernel(const float* __restrict__ w1) {
    const float s = blk_maxabs(w1, 864);
    if (threadIdx.x == 0) g_smax[0] = __float_as_uint(s);
    if (threadIdx.x < 32) {
        const int oc = threadIdx.x;
        const float inv_s = 1.f / s;
        int n = 0;
        for (int ic = 0; ic < 3; ic++)
            for (int t = 0; t < 9; t++) {
                const int c = (int)rintf(w1[(oc * 3 + ic) * 9 + t] * inv_s);
                if (c != 0) {
                    const uint32_t off = ic * 1224 + (t / 3) * 36 + (t % 3);
                    g_lst1[oc][n++] = make_uint2(
                        off, __float_as_uint(c > 0 ? s : -s));
                }
            }
        g_cnt1[oc] = n;
    }
}

// ---- maxabs for wc/w2/w3 (21 blocks, side stream) ---------------------------
__global__ void maxabs_rest_kernel(const float* __restrict__ wc,
                                   const float* __restrict__ w2,
                                   const float* __restrict__ w3) {
    __shared__ float red[8];
    const int blk = blockIdx.x;
    int t, base, cnt;
    const float* p;
    if (blk == 0)      { t = 1; p = wc; base = 0; cnt = 1280; }
    else if (blk < 5)  { t = 2; p = w2; base = (blk - 1) * 4608; cnt = 4608; }
    else               { t = 3; p = w3; base = (blk - 5) * 4608; cnt = 4608; }
    float m = 0.f;
    for (int i = threadIdx.x; i < cnt; i += 256)
        m = fmaxf(m, fabsf(p[base + i]));
    #pragma unroll
    for (int o = 16; o; o >>= 1)
        m = fmaxf(m, __shfl_xor_sync(0xffffffffu, m, o));
    if ((threadIdx.x & 31) == 0) red[threadIdx.x >> 5] = m;
    __syncthreads();
    if (threadIdx.x == 0) {
        float v = red[0];
        #pragma unroll
        for (int i = 1; i < 8; i++) v = fmaxf(v, red[i]);
        atomicMax(&g_smax[t], __float_as_uint(v));  // |w|>=0, bit-monotone
    }
}

// ---- pack_rest: quantize + pack wc/w2/w3 (5 blocks, side stream) ------------
__global__ void pack_rest_kernel(const float* __restrict__ wc,
                                 const float* __restrict__ w2,
                                 const float* __restrict__ w3) {
    const int blk = blockIdx.x;
    if (blk == 0) {
        const float s = get_scale(1);
        for (int i = threadIdx.x; i < 1280; i += 256)
            g_qwc[i] = rintf(wc[i] / s) * s;
    } else if (blk == 1) {
        const float inv_s = 1.f / get_scale(2);
        for (int i = threadIdx.x; i < 9 * 64 * 8; i += 256) {
            const int tap = i / 512, r = i % 512, oc = r >> 3, p = r & 7;
            const int icw = (p >> 1) + ((p & 1) << 2);
            uint32_t word = 0;
            #pragma unroll
            for (int l = 0; l < 4; l++) {
                const int ic = icw * 4 + l;
                const int c = (int)rintf(w2[(oc * 32 + ic) * 9 + tap] * inv_s);
                word |= ((uint32_t)(uint8_t)(int8_t)c) << (8 * l);
            }
            g_wf2[i] = (int)word;
        }
    } else if (blk == 2) {
        const float inv_s = 1.f / get_scale(3);
        for (int i = threadIdx.x; i < 9 * 2 * 128 * 8; i += 256) {
            const int tap = i / 2048, r = i % 2048;
            const int chunk = r >> 10, r2 = r & 1023, oc = r2 >> 3, p = r2 & 7;
            const int icw = (p >> 1) + ((p & 1) << 2);
            uint32_t word = 0;
            #pragma unroll
            for (int l = 0; l < 4; l++) {
                const int ic = chunk * 32 + (icw * 4) + l;
                const int c = (int)rintf(w3[(oc * 64 + ic) * 9 + tap] * inv_s);
                word |= ((uint32_t)(uint8_t)(int8_t)c) << (8 * l);
            }
            g_wf3[i] = (int)word;
        }
    } else if (blk == 3) {
        const float inv_s = 1.f / get_scale(2);
        uint32_t* dst = (uint32_t*)g_dw2;
        for (int i = threadIdx.x; i < 2 * 8 * 9 * 16; i += 256) {
            const int z = i / 1152, r = i % 1152;
            const int k = r / 144, r2 = r % 144;
            const int t = r2 / 16, q = (r2 % 16) >> 2, chl = i & 3;
            const int oc = z * 32 + 16 + q * 4 + chl;
            uint32_t word = 0;
            #pragma unroll
            for (int l = 0; l < 4; l++) {
                const int ic = k * 4 + l;
                const int c = (int)rintf(w2[(oc * 32 + ic) * 9 + t] * inv_s);
                word |= ((uint32_t)(uint8_t)(int8_t)c) << (8 * l);
            }
            dst[i] = word;
        }
    } else {
        const float inv_s = 1.f / get_scale(3);
        uint32_t* dst = (uint32_t*)g_dw3;
        for (int i = threadIdx.x; i < 4 * 16 * 9 * 16; i += 256) {
            const int z = i / 2304, r = i % 2304;
            const int k = r / 144, r2 = r % 144;
            const int t = r2 / 16, q = (r2 % 16) >> 2, chl = i & 3;
            const int oc = z * 32 + 16 + q * 4 + chl;
            uint32_t word = 0;
            #pragma unroll
            for (int l = 0; l < 4; l++) {
                const int ic = k * 4 + l;
                const int c = (int)rintf(w3[(oc * 64 + ic) * 9 + t] * inv_s);
                word |= ((uint32_t)(uint8_t)(int8_t)c) << (8 * l);
            }
            dst[i] = word;
        }
    }
}

// ---- block 1: SPARSE fp32 conv3x3(pad1) + quant_act + maxpool2 --------------
// 256 threads = 32 conv cols x 8 row-groups; thread owns 4 conv rows
// (2 pooled rows) of one column; 16 oc per CTA (z=2).  Per tap:
// 1 broadcast LDS.64 (entry) + 4 LDS (immediate offsets) + 4 FFMA.
__global__ __launch_bounds__(256, 4) void conv1_kernel(
    const float* __restrict__ x, const float* __restrict__ alpha_p,
    uint8_t* __restrict__ out) {
    constexpr int H = 224, W = 224, PH = 112, PW = 112, OC = 32, OCB = 16;
    __shared__ float sx[3 * 34 * 36];            // [ic][row 34][pitch 36]
    __shared__ uint2 slst[16 * 88];
    __shared__ int   scnt[16];

    const int tid = threadIdx.x;
    const int tx = tid & 31, g = tid >> 5;       // conv col, 4-row group
    const int tile_x = blockIdx.x;               // 0..6
    const int tile_y = blockIdx.y % 7;
    const int b      = blockIdx.y / 7;
    const int oc0    = blockIdx.z * OCB;

    const int cx0 = tile_x * 32, cy0 = tile_y * 32;   // conv-space origin
    const int px0 = tile_x * 16, py0 = tile_y * 16;   // pooled origin

    const float* xb = x + (long)b * 3 * H * W;
    for (int i = tid; i < 3 * 34 * 34; i += 256) {
        const int ic = i / 1156, r = (i % 1156) / 34, c = i % 34;
        const int gy = cy0 - 1 + r, gx = cx0 - 1 + c;
        float v = 0.f;
        if (gy >= 0 && gy < H && gx >= 0 && gx < W)
            v = xb[(long)ic * H * W + gy * W + gx];
        sx[ic * 1224 + r * 36 + c] = v;
    }
    for (int i = tid; i < 16 * 88; i += 256)
        slst[i] = g_lst1[oc0 + i / 88][i % 88];
    if (tid < 16) scnt[tid] = g_cnt1[oc0 + tid];
    __syncthreads();

    const float alpha = __ldg(alpha_p);
    const float inv_scale = 3.f / alpha;
    const int base = 4 * g * 36 + tx;

    uint32_t pw0[4] = {0, 0, 0, 0};              // pooled row 2g
    uint32_t pw1[4] = {0, 0, 0, 0};              // pooled row 2g+1
    #pragma unroll 1
    for (int j = 0; j < OCB; j++) {
        const int n = scnt[j];
        const uint2* lst = &slst[j * 88];
        float p0 = 0.f, p1 = 0.f, p2 = 0.f, p3 = 0.f;
        #pragma unroll 1
        for (int i = 0; i < n; i++) {
            const uint2 e = lst[i];                  // broadcast LDS.64
            const float w = __uint_as_float(e.y);
            const float* sp = &sx[base + e.x];
            p0 = fmaf(w, sp[0],   p0);               // conv row 4g
            p1 = fmaf(w, sp[36],  p1);               // conv row 4g+1
            p2 = fmaf(w, sp[72],  p2);               // conv row 4g+2
            p3 = fmaf(w, sp[108], p3);               // conv row 4g+3
        }
        float m0 = fmaxf(p0, p1);                    // vertical pools
        float m1 = fmaxf(p2, p3);
        m0 = fmaxf(m0, __shfl_xor_sync(0xffffffffu, m0, 1));  // horizontal
        m1 = fmaxf(m1, __shfl_xor_sync(0xffffffffu, m1, 1));
        const float y0 = fminf(fmaxf(m0, 0.f), alpha);
        const float y1 = fminf(fmaxf(m1, 0.f), alpha);
        const uint32_t c0 = (uint32_t)(int)rintf(y0 * inv_scale);
        const uint32_t c1 = (uint32_t)(int)rintf(y1 * inv_scale);
        pw0[j >> 2] |= c0 << (8 * (j & 3));
        pw1[j >> 2] |= c1 << (8 * (j & 3));
    }

    if (!(tx & 1)) {
        const int ppx = px0 + (tx >> 1);
        const int ppy = py0 + 2 * g;
        uint8_t* o = out + (((long)b * PH + ppy) * PW + ppx) * OC + oc0;
        *(uint4*)o = make_uint4(pw0[0], pw0[1], pw0[2], pw0[3]);
        *(uint4*)(o + (long)PW * OC)
            = make_uint4(pw1[0], pw1[1], pw1[2], pw1[3]);
    }
}

// ---- blocks 2/3: fused hybrid, 32 channels/CTA (16 mma + 16 dp4a) -----------
// launch_bounds(256,4): 64 regs -> 4 CTAs/SM.  (frozen from R11)
template <int H, int IC, int OC, int NOC, int MMAOC, int TW, int TH, int PSTRIDE>
__global__ __launch_bounds__(256, 4) void conv_hyb(
    const uint8_t* __restrict__ xin, const int* __restrict__ wf,
    const uint4* __restrict__ dw,
    const float* __restrict__ aprev_p, const float* __restrict__ acur_p,
    int wtensor, uint8_t* __restrict__ out) {
    constexpr int DPOC = NOC - MMAOC;          // 16
    constexpr int DQ   = DPOC / 4;             // 4
    constexpr int CH   = IC / 32;
    constexpr int IC4  = IC / 4;
    constexpr int IC16 = IC / 16;
    constexpr int TIW  = TW + 2, TIH = TH + 2;
    constexpr int OCG  = MMAOC / 8;            // 2
    constexpr int VPP  = IC / 16;
    constexpr int WTX  = TW / 8, WTY = TH / 2, NWT = WTX * WTY;
    constexpr int PHW  = H / 2;
    constexpr int DLANES = TW * (TH / 2);
    static_assert(DLANES <= 128, "dp lane budget");

    extern __shared__ __align__(16) uint8_t dsm[];
    uint8_t* stile = dsm;                                   // TIH*TIW*PSTRIDE
    uint4*   sdw   = (uint4*)(dsm + TIH * TIW * PSTRIDE);   // IC4*9*DQ uint4
    int*     swf   = (int*)(dsm + TIH * TIW * PSTRIDE + IC4 * 9 * DQ * 16);

    const int tid = threadIdx.x;
    const int tilesY = H / TH;
    const int by = blockIdx.y % tilesY;
    const int b  = blockIdx.y / tilesY;
    const int cx0 = blockIdx.x * TW, cy0 = by * TH;
    const int oc0 = blockIdx.z * NOC;

    for (int i = tid; i < 9 * CH * MMAOC * 8; i += 256) {
        const int p = i & 7, j = (i >> 3) % MMAOC, tc = (i >> 3) / MMAOC;
        swf[i] = wf[((tc * OC) + oc0 + j) * 8 + p];
    }
    {
        const uint4* dwz = dw + (long)blockIdx.z * (IC4 * 9 * DQ);
        for (int i = tid; i < IC4 * 9 * DQ; i += 256) sdw[i] = dwz[i];
    }
    for (int i = tid; i < TIH * TIW * VPP; i += 256) {
        const int v = i % VPP, pix = i / VPP;
        const int gx = cx0 - 1 + pix % TIW;
        const int gy = cy0 - 1 + pix / TIW;
        uint4 val = make_uint4(0, 0, 0, 0);
        if (gx >= 0 && gx < H && gy >= 0 && gy < H)
            val = *(const uint4*)(xin + (((long)b * H + gy) * H + gx) * IC + v * 16);
        *(uint4*)(stile + pix * PSTRIDE + v * 16) = val;
    }
    __syncthreads();

    const int warp = tid >> 5, lane = tid & 31;
    const float combined = (__ldg(aprev_p) * (1.f / 3.f)) * get_scale(wtensor);
    const float alpha = __ldg(acur_p);
    const float inv_scale = 3.f / alpha;

    if (warp < 4) {
        // ---------------- mma path (tensor pipe) ----------------
        const uint32_t sbase = smem_u32(stile);
        const int r = lane >> 2;
        for (int wt = warp; wt < NWT; wt += 4) {
            const int tx = wt % WTX, ty = wt / WTX;
            const int piy = ty * 2 + ((lane >> 3) & 1);
            const int pix = tx * 8 + (lane & 7);
            const uint32_t abase = sbase + (piy * TIW + pix) * PSTRIDE
                                 + ((lane >> 4) << 4);
            int acc[OCG][4];
            #pragma unroll
            for (int g = 0; g < OCG; g++)
                #pragma unroll
                for (int q = 0; q < 4; q++) acc[g][q] = 0;

            #pragma unroll
            for (int t = 0; t < 9; t++) {
                const int dy = t / 3, dx = t % 3;
                #pragma unroll
                for (int c = 0; c < CH; c++) {
                    int a0, a1, a2, a3;
                    ldsm4(abase + (dy * TIW + dx) * PSTRIDE + c * 32,
                          a0, a1, a2, a3);
                    #pragma unroll
                    for (int g = 0; g < OCG; g++) {
                        const uint2 bb = *(const uint2*)
                            &swf[(((t * CH + c) * MMAOC) + g * 8 + (lane >> 2)) * 8
                                 + 2 * (lane & 3)];
                        mma_s8(acc[g], a0, a1, a2, a3, (int)bb.x, (int)bb.y);
                    }
                }
            }
            #pragma unroll
            for (int g = 0; g < OCG; g++) {
                const int v0 = max(acc[g][0], acc[g][2]);
                const int v1 = max(acc[g][1], acc[g][3]);
                const int o0 = max(v0, __shfl_xor_sync(0xffffffffu, v0, 4));
                const int o1 = max(v1, __shfl_xor_sync(0xffffffffu, v1, 4));
                if (!(r & 1)) {
                    const int ppx = (cx0 >> 1) + tx * 4 + (r >> 1);
                    const int ppy = (cy0 >> 1) + ty;
                    const float f0 = fminf(fmaxf((float)o0 * combined, 0.f), alpha);
                    const float f1 = fminf(fmaxf((float)o1 * combined, 0.f), alpha);
                    const uint32_t c0 = (uint32_t)(int)rintf(f0 * inv_scale);
                    const uint32_t c1 = (uint32_t)(int)rintf(f1 * inv_scale);
                    const int oc = oc0 + g * 8 + (lane & 3) * 2;
                    *(uint16_t*)(out + (((long)b * PHW + ppy) * PHW + ppx) * OC + oc)
                        = (uint16_t)(c0 | (c1 << 8));
                }
            }
        }
    } else {
        // ---- dp4a path (fma pipe), rolling 2-row window, LDS.128 ----
        const int dt = tid - 128;              // 0..127
        const int cx = dt % TW, cyp = dt / TW;
        const bool active = dt < DLANES;
        const int dcyp = min(cyp, TH / 2 - 1);

        int acc[DPOC][2];
        #pragma unroll
        for (int j = 0; j < DPOC; j++) { acc[j][0] = 0; acc[j][1] = 0; }

        #pragma unroll 1
        for (int g4 = 0; g4 < IC16; g4++) {
            const uint8_t* tb = stile + ((2 * dcyp) * TIW + cx) * PSTRIDE
                              + g4 * 16;
            #pragma unroll
            for (int cc = 0; cc < 3; cc++) {
                const uint8_t* cp = tb + cc * PSTRIDE;
                uint4 r0 = *(const uint4*)(cp);
                uint4 r1 = *(const uint4*)(cp + TIW * PSTRIDE);
                #pragma unroll
                for (int dy = 0; dy < 3; dy++) {
                    const int t = dy * 3 + cc;
                    #pragma unroll
                    for (int kk = 0; kk < 4; kk++) {
                        const uint32_t a0 = ((const uint32_t*)&r0)[kk];
                        const uint32_t a1 = ((const uint32_t*)&r1)[kk];
                        const int k = g4 * 4 + kk;
                        #pragma unroll
                        for (int q = 0; q < DQ; q++) {
                            const uint4 w = sdw[(k * 9 + t) * DQ + q];
                            acc[q*4+0][0] = __dp4a((int)a0, (int)w.x, acc[q*4+0][0]);
                            acc[q*4+0][1] = __dp4a((int)a1, (int)w.x, acc[q*4+0][1]);
                            acc[q*4+1][0] = __dp4a((int)a0, (int)w.y, acc[q*4+1][0]);
                            acc[q*4+1][1] = __dp4a((int)a1, (int)w.y, acc[q*4+1][1]);
                            acc[q*4+2][0] = __dp4a((int)a0, (int)w.z, acc[q*4+2][0]);
                            acc[q*4+2][1] = __dp4a((int)a1, (int)w.z, acc[q*4+2][1]);
                            acc[q*4+3][0] = __dp4a((int)a0, (int)w.w, acc[q*4+3][0]);
                            acc[q*4+3][1] = __dp4a((int)a1, (int)w.w, acc[q*4+3][1]);
                        }
                    }
                    if (dy < 2) {
                        r0 = r1;
                        r1 = *(const uint4*)(cp + (dy + 2) * TIW * PSTRIDE);
                    }
                }
            }
        }

        uint32_t pw[DQ];
        #pragma unroll
        for (int q = 0; q < DQ; q++) pw[q] = 0;
        #pragma unroll
        for (int j = 0; j < DPOC; j++) {
            int v = max(acc[j][0], acc[j][1]);               // vertical pool
            v = max(v, __shfl_xor_sync(0xffffffffu, v, 1));  // horizontal pool
            const float f = fminf(fmaxf((float)v * combined, 0.f), alpha);
            const uint32_t code = (uint32_t)(int)rintf(f * inv_scale);
            pw[j >> 2] |= code << (8 * (j & 3));
        }
        if (active && !(cx & 1)) {
            const int ppx = (cx0 >> 1) + (cx >> 1);
            const int ppy = (cy0 >> 1) + cyp;
            uint8_t* o = out + (((long)b * PHW + ppy) * PHW + ppx) * OC
                       + oc0 + MMAOC;
            *(uint4*)o = make_uint4(pw[0], pw[1], pw[2], pw[3]);
        }
    }
}

// ---- global max, stage 1: partial max over 196 pixels -----------------------
__global__ void gmax_stage1(const uint8_t* __restrict__ h3) {
    __shared__ uint32_t sm[4][32];
    const int b = blockIdx.x, s = blockIdx.y;
    const int tid = threadIdx.x;
    const int w = tid >> 5, c4 = tid & 31;
    const uint32_t* p = (const uint32_t*)(h3 + (long)b * 784 * 128);
    uint32_t m = 0;
    for (int pix = s * 196 + w; pix < (s + 1) * 196; pix += 4)
        m = __vmaxu4(m, p[(long)pix * 32 + c4]);
    sm[w][c4] = m;
    __syncthreads();
    if (tid < 32)
        g_gpart[(b * 4 + s) * 32 + tid] =
            __vmaxu4(__vmaxu4(sm[0][tid], sm[1][tid]),
                     __vmaxu4(sm[2][tid], sm[3][tid]));
}

// ---- global max stage 2 + 1x1 quantized conv classifier ---------------------
__global__ void gmax_fc_kernel(const float* __restrict__ a3_p,
                               float* __restrict__ out) {
    __shared__ float gm[128];
    const int b = blockIdx.x;
    const int tid = threadIdx.x;
    if (tid < 32) {
        const uint32_t* gp = &g_gpart[b * 4 * 32];
        const uint32_t v = __vmaxu4(__vmaxu4(gp[tid], gp[32 + tid]),
                                    __vmaxu4(gp[64 + tid], gp[96 + tid]));
        const float sc = __ldg(a3_p) * (1.f / 3.f);
        gm[tid * 4 + 0] = (float)(v & 0xff) * sc;
        gm[tid * 4 + 1] = (float)((v >> 8) & 0xff) * sc;
        gm[tid * 4 + 2] = (float)((v >> 16) & 0xff) * sc;
        gm[tid * 4 + 3] = (float)(v >> 24) * sc;
    }
    __syncthreads();
    if (tid < 10) {
        float s = 0.f;
        #pragma unroll 8
        for (int k = 0; k < 128; k++)
            s = fmaf(gm[k], g_qwc[tid * 128 + k], s);
        out[b * 10 + tid] = s;
    }
}

// ---------------------------------------------------------------------------
extern "C" void kernel_launch(void* const* d_in, const int* in_sizes, int n_in,
                              void* d_out, int out_size) {
    const float* x  = (const float*)d_in[0];
    const float* w1 = (const float*)d_in[1];
    const float* w2 = (const float*)d_in[2];
    const float* w3 = (const float*)d_in[3];
    const float* wc = (const float*)d_in[4];
    const float* a1 = (const float*)d_in[5];
    const float* a2 = (const float*)d_in[6];
    const float* a3 = (const float*)d_in[7];

    int *wf2, *wf3;
    uint4 *dw2, *dw3;
    uint8_t *c1, *c2, *c3;
    cudaGetSymbolAddress((void**)&wf2, g_wf2);
    cudaGetSymbolAddress((void**)&wf3, g_wf3);
    cudaGetSymbolAddress((void**)&dw2, g_dw2);
    cudaGetSymbolAddress((void**)&dw3, g_dw3);
    cudaGetSymbolAddress((void**)&c1, g_c1);
    cudaGetSymbolAddress((void**)&c2, g_c2);
    cudaGetSymbolAddress((void**)&c3, g_c3);

    // conv2: 32 channels/CTA (16 mma + 16 dp), tile 16x16, z=2
    auto k2 = conv_hyb<112, 32, 64, 32, 16, 16, 16, 48>;
    constexpr int SM2 = 18 * 18 * 48 + 8 * 9 * 4 * 16 + 9 * 1 * 16 * 8 * 4;
    // conv3: 32 channels/CTA, tile 8x28, z=4
    auto k3 = conv_hyb<56, 64, 128, 32, 16, 8, 28, 80>;
    constexpr int SM3 = 30 * 10 * 80 + 16 * 9 * 4 * 16 + 9 * 2 * 16 * 8 * 4;
    cudaFuncSetAttribute(k2, cudaFuncAttributeMaxDynamicSharedMemorySize, SM2);
    cudaFuncSetAttribute(k3, cudaFuncAttributeMaxDynamicSharedMemorySize, SM3);

    // side stream + fork/join events (created on first, uncaptured call)
    static cudaStream_t s1 = nullptr;
    static cudaEvent_t evF = nullptr, evJ = nullptr;
    if (s1 == nullptr) {
        cudaStreamCreateWithFlags(&s1, cudaStreamNonBlocking);
        cudaEventCreateWithFlags(&evF, cudaEventDisableTiming);
        cudaEventCreateWithFlags(&evJ, cudaEventDisableTiming);
    }

    // conv1 weights (needed immediately by conv1)
    pack1_kernel<<<1, 256>>>(w1);

    // fork: conv2/3 weight prep overlaps conv1 on side stream
    cudaEventRecord(evF, 0);
    cudaStreamWaitEvent(s1, evF, 0);
    maxabs_rest_kernel<<<21, 256, 0, s1>>>(wc, w2, w3);
    pack_rest_kernel<<<5, 256, 0, s1>>>(wc, w2, w3);
    cudaEventRecord(evJ, s1);

    // block 1: [32,3,224,224] -> codes [32,112,112,32]
    conv1_kernel<<<dim3(7, 7 * 32, 2), 256>>>(x, a1, c1);

    // join before conv2 (needs wf2/dw2/g_smax)
    cudaStreamWaitEvent(0, evJ, 0);

    // block 2: -> codes [32,56,56,64]
    k2<<<dim3(7, 7 * 32, 2), 256, SM2>>>(c1, wf2, dw2, a1, a2, 2, c2);
    // block 3: -> codes [32,28,28,128]
    k3<<<dim3(7, 2 * 32, 4), 256, SM3>>>(c2, wf3, dw3, a2, a3, 3, c3);

    // global max + classifier (two-stage)
    gmax_stage1<<<dim3(32, 4), 128>>>(c3);
    gmax_fc_kernel<<<32, 128>>>(a3, (float*)d_out);
}